// round 8
// baseline (speedup 1.0000x reference)
#include <cuda_runtime.h>
#include <cuda_fp16.h>
#include <math.h>

#define BB 4
#define NND 4096
#define EED 131072

// ---------------- scratch ----------------
__device__ float  d_stats[3 * 512];
__device__ float  d_xn  [BB * NND * 32];
__device__ float2 d_T   [BB * 64 * 16 * 32];
__device__ float2 d_Xft [BB * 32 * 16 * 32];
__device__ float2 d_oft [BB * 32 * 16 * 32];
__device__ float2 d_V   [BB * 64 * 16 * 32];
__device__ float  d_x1  [BB * NND * 32];
__device__ float  d_x1b [BB * NND * 32];
__device__ float  d_x2  [BB * NND * 32];
__device__ __half d_hh  [(long long)EED * 64];
__device__ __half d_gh  [(long long)BB * NND * 64 * 32];   // B-fragment layout per (row=b*NND+n)
__device__ float  d_msg [(long long)EED * BB * 32];        // indexed by dst-CSR position
__device__ int    d_esrc[EED];
__device__ int    d_edst[EED];
__device__ int    d_is64;
__device__ int    d_cnt [2 * NND];
__device__ int    d_offA[2 * (NND + 1)];
__device__ int    d_cur [2 * NND];
__device__ int    d_eid [2 * EED];   // [0:E) src-CSR edge ids; [E:2E) dstpos per edge

__device__ __forceinline__ float gelu_f(float x) {
    return 0.5f * x * (1.0f + erff(x * 0.70710678118654752f));
}
__device__ __forceinline__ unsigned smem_u32(const void* p) {
    return (unsigned)__cvta_generic_to_shared(p);
}

// ---------------- init: zero cnt/cur + probe edge dtype ----------------
__global__ void initcsr_kernel(const void* ei) {
    int i = blockIdx.x * 1024 + threadIdx.x;   // 8x1024
    d_cnt[i] = 0; d_cur[i] = 0;
    if (blockIdx.x == 0 && threadIdx.x < 256) {
        const int* w = (const int*)ei;
        int t = threadIdx.x;
        int nz = 0;
        for (int k = t; k < 1024; k += 256) nz |= w[2 * k + 1];
        __shared__ int s;
        if (t == 0) s = 0;
        __syncthreads();
        if (nz) atomicOr(&s, 1);
        __syncthreads();
        if (t == 0) d_is64 = (s == 0);   // all-zero odd words => int64
    }
}

// ---------------- convert + histogram ----------------
__global__ void convhist_kernel(const void* ei) {
    int e = blockIdx.x * 256 + threadIdx.x;  // 512x256
    int s, d;
    if (d_is64) {
        const long long* p = (const long long*)ei;
        s = (int)p[e]; d = (int)p[EED + e];
    } else {
        const int* p = (const int*)ei;
        s = p[e]; d = p[EED + e];
    }
    d_esrc[e] = s; d_edst[e] = d;
    atomicAdd(&d_cnt[s], 1);
    atomicAdd(&d_cnt[NND + d], 1);
}

__global__ void scan_kernel() {
    int a = blockIdx.x;   // 0=src, 1=dst
    int t = threadIdx.x;  // 1024
    const int* cnt = d_cnt + a * NND;
    int* off = d_offA + a * (NND + 1);
    int v0 = cnt[t * 4], v1 = cnt[t * 4 + 1], v2 = cnt[t * 4 + 2], v3 = cnt[t * 4 + 3];
    int s = v0 + v1 + v2 + v3;
    __shared__ int sh[1024];
    sh[t] = s; __syncthreads();
    for (int o1 = 1; o1 < 1024; o1 <<= 1) {
        int v = (t >= o1) ? sh[t - o1] : 0;
        __syncthreads();
        sh[t] += v;
        __syncthreads();
    }
    int excl = sh[t] - s;
    off[t * 4] = excl; off[t * 4 + 1] = excl + v0;
    off[t * 4 + 2] = excl + v0 + v1; off[t * 4 + 3] = excl + v0 + v1 + v2;
    if (t == 1023) off[NND] = sh[1023];
}

__global__ void fill_kernel() {
    int e = blockIdx.x * 256 + threadIdx.x;    // 512x256
    int s = d_esrc[e], d2 = d_edst[e];
    int p = atomicAdd(&d_cur[s], 1);
    d_eid[d_offA[s] + p] = e;
    int q = atomicAdd(&d_cur[NND + d2], 1);
    d_eid[EED + e] = d_offA[(NND + 1) + d2] + q;   // dstpos of edge e
}

// ---------------- instance-norm stats over (W,C) ----------------
__global__ void stats_kernel(const float* in, int slot) {
    int row = blockIdx.x;            // 256
    const float* p = in + row * 2048;
    int t = threadIdx.x;             // 256
    float s = 0.f, s2 = 0.f;
#pragma unroll
    for (int i = 0; i < 8; i++) { float v = p[t + i * 256]; s += v; s2 += v * v; }
    __shared__ float sh1[256], sh2[256];
    sh1[t] = s; sh2[t] = s2; __syncthreads();
    for (int o = 128; o > 0; o >>= 1) {
        if (t < o) { sh1[t] += sh1[t + o]; sh2[t] += sh2[t + o]; }
        __syncthreads();
    }
    if (t == 0) {
        float m = sh1[0] * (1.0f / 2048.0f);
        float var = sh2[0] * (1.0f / 2048.0f) - m * m;
        d_stats[slot * 512 + row] = m;
        d_stats[slot * 512 + 256 + row] = rsqrtf(var + 1e-5f);
    }
}

__global__ void norm_kernel(const float* nodes) {
    int i = blockIdx.x * 1024 + threadIdx.x;   // 512x1024
    int row = i >> 11;
    d_xn[i] = (nodes[i] - d_stats[row]) * d_stats[256 + row];
}

// ---------------- forward DFT over W (ky 0..15) ----------------
__global__ void fwdW_kernel() {
    int bh = blockIdx.x;            // 256
    int t = threadIdx.x;            // 256
    __shared__ float  xs[2048];
    __shared__ float2 tw[1024];
    for (int i = t; i < 2048; i += 256) xs[i] = d_xn[bh * 2048 + i];
    for (int i = t; i < 1024; i += 256) {
        int ky = i >> 6, w = i & 63; float s, c;
        sincospif(-(float)(ky * w) * (1.0f / 32.0f), &s, &c);
        tw[i] = make_float2(c, s);
    }
    __syncthreads();
#pragma unroll
    for (int r = 0; r < 2; r++) {
        int oi = t + r * 256; int ky = oi >> 5, c = oi & 31;
        float re = 0.f, im = 0.f;
#pragma unroll 8
        for (int w = 0; w < 64; w++) {
            float xv = xs[w * 32 + c]; float2 tv = tw[ky * 64 + w];
            re += xv * tv.x; im += xv * tv.y;
        }
        d_T[(bh * 16 + ky) * 32 + c] = make_float2(re, im);
    }
}

// ---------------- forward DFT over H (kx 0..15, 48..63), *1/64 ----------------
__global__ void fwdH_kernel() {
    int b = blockIdx.x >> 5, kxi = blockIdx.x & 31;   // 128 blocks
    int kx = (kxi < 16) ? kxi : kxi + 32;
    int t = threadIdx.x;                               // 512
    __shared__ float2 tw[64];
    if (t < 64) { float s, c; sincospif(-(float)(kx * t) * (1.0f / 32.0f), &s, &c); tw[t] = make_float2(c, s); }
    __syncthreads();
    int ky = t >> 5, c = t & 31;
    float re = 0.f, im = 0.f;
#pragma unroll 4
    for (int h = 0; h < 64; h++) {
        float2 v = d_T[((b * 64 + h) * 16 + ky) * 32 + c];
        float2 w = tw[h];
        re += v.x * w.x - v.y * w.y;
        im += v.x * w.y + v.y * w.x;
    }
    d_Xft[((b * 32 + kxi) * 16 + ky) * 32 + c] = make_float2(re * (1.0f / 64.0f), im * (1.0f / 64.0f));
}

// ---------------- complex channel mix per (kx,ky) ----------------
__global__ void modemix_kernel(const float* w1re, const float* w1im,
                               const float* w2re, const float* w2im) {
    int kxi = blockIdx.x >> 4, ky = blockIdx.x & 15;   // 512 blocks
    int xm = (kxi < 16) ? kxi : kxi - 16;
    const float* wre = (kxi < 16) ? w1re : w2re;
    const float* wim = (kxi < 16) ? w1im : w2im;
    int t = threadIdx.x;                                // 128
    __shared__ float wr[1024], wi[1024];
    __shared__ float2 Xs[128];
    for (int i = t; i < 1024; i += 128) {
        int off = i * 256 + xm * 16 + ky;
        wr[i] = wre[off]; wi[i] = wim[off];
    }
    { int b = t >> 5, c = t & 31; Xs[t] = d_Xft[((b * 32 + kxi) * 16 + ky) * 32 + c]; }
    __syncthreads();
    int b = t >> 5, o = t & 31;
    float re = 0.f, im = 0.f;
#pragma unroll
    for (int i = 0; i < 32; i++) {
        float2 xv = Xs[b * 32 + i];
        float wrv = wr[i * 32 + o], wiv = wi[i * 32 + o];
        re += xv.x * wrv - xv.y * wiv;
        im += xv.x * wiv + xv.y * wrv;
    }
    d_oft[((b * 32 + kxi) * 16 + ky) * 32 + o] = make_float2(re, im);
}

// ---------------- inverse DFT over H, *1/8 ----------------
__global__ void invH_kernel() {
    int b = blockIdx.x >> 6, h = blockIdx.x & 63;   // 256 blocks
    int t = threadIdx.x;                             // 512
    __shared__ float2 tw[32];
    if (t < 32) {
        int kx = (t < 16) ? t : t + 32; float s, c;
        sincospif((float)(kx * h) * (1.0f / 32.0f), &s, &c);
        tw[t] = make_float2(c, s);
    }
    __syncthreads();
    int ky = t >> 5, o = t & 31;
    float re = 0.f, im = 0.f;
#pragma unroll 4
    for (int k = 0; k < 32; k++) {
        float2 v = d_oft[((b * 32 + k) * 16 + ky) * 32 + o];
        float2 w = tw[k];
        re += v.x * w.x - v.y * w.y;
        im += v.x * w.y + v.y * w.x;
    }
    d_V[((b * 64 + h) * 16 + ky) * 32 + o] = make_float2(re * 0.125f, im * 0.125f);
}

// ---------------- inverse C2R over W, *1/8, fused stats(slot1) ----------------
__global__ void invW_kernel() {
    int bh = blockIdx.x; int t = threadIdx.x;   // 256 x 256
    __shared__ float2 Vs[512];
    __shared__ float2 tw[1024];
    __shared__ float sh1[256], sh2[256];
    for (int i = t; i < 512; i += 256) Vs[i] = d_V[bh * 512 + i];
    for (int i = t; i < 1024; i += 256) {
        int ky = i >> 6, w = i & 63; float s, c;
        sincospif((float)(ky * w) * (1.0f / 32.0f), &s, &c);
        tw[i] = make_float2(c, s);
    }
    __syncthreads();
    float ss = 0.f, ss2 = 0.f;
#pragma unroll
    for (int r = 0; r < 8; r++) {
        int oi = t + r * 256; int w = oi >> 5, o = oi & 31;
        float acc = 0.f;
#pragma unroll
        for (int ky = 0; ky < 16; ky++) {
            float2 v = Vs[ky * 32 + o]; float2 tv = tw[ky * 64 + w];
            float term = v.x * tv.x - v.y * tv.y;
            acc += (ky == 0) ? term : 2.0f * term;
        }
        acc *= 0.125f;
        d_x1[bh * 2048 + oi] = acc;
        ss += acc; ss2 += acc * acc;
    }
    sh1[t] = ss; sh2[t] = ss2; __syncthreads();
    for (int o = 128; o > 0; o >>= 1) {
        if (t < o) { sh1[t] += sh1[t + o]; sh2[t] += sh2[t + o]; }
        __syncthreads();
    }
    if (t == 0) {
        float m = sh1[0] * (1.0f / 2048.0f);
        float var = sh2[0] * (1.0f / 2048.0f) - m * m;
        d_stats[512 + bh] = m;
        d_stats[512 + 256 + bh] = rsqrtf(var + 1e-5f);
    }
}

// ---------------- MLP on inorm(x1) -> d_x1b ----------------
__global__ void __launch_bounds__(128) mlp0_kernel(const float* w1, const float* b1,
                                                   const float* w2, const float* b2) {
    int t = threadIdx.x;   // 128
    __shared__ float w1s[2048], w2s[2048], b1s[64], b2s[32];
    for (int i = t; i < 2048; i += 128) { w1s[i] = w1[i]; w2s[i] = w2[i]; }
    if (t < 64) b1s[t] = b1[t];
    if (t < 32) b2s[t] = b2[t];
    __syncthreads();
    int p = blockIdx.x * 128 + t;   // grid 128
    int row = p >> 6;
    float m = d_stats[512 + row], rs = d_stats[512 + 256 + row];
    float x[32];
#pragma unroll
    for (int c = 0; c < 32; c++) x[c] = (d_x1[p * 32 + c] - m) * rs;
    float o[32];
#pragma unroll
    for (int j = 0; j < 32; j++) o[j] = b2s[j];
    for (int k = 0; k < 64; k++) {
        float a = b1s[k];
#pragma unroll
        for (int c = 0; c < 32; c++) a += x[c] * w1s[c * 64 + k];
        a = gelu_f(a);
#pragma unroll
        for (int j = 0; j < 32; j++) o[j] += a * w2s[k * 32 + j];
    }
#pragma unroll
    for (int j = 0; j < 32; j++) d_x1b[p * 32 + j] = o[j];
}

// ---------------- MLP on xn -> d_x2, fused stats(slot2) ----------------
__global__ void __launch_bounds__(128) mlp1_kernel(const float* w1, const float* b1,
                                                   const float* w2, const float* b2) {
    int t = threadIdx.x;   // 128
    __shared__ float w1s[2048], w2s[2048], b1s[64], b2s[32];
    __shared__ float sh1[128], sh2[128];
    for (int i = t; i < 2048; i += 128) { w1s[i] = w1[i]; w2s[i] = w2[i]; }
    if (t < 64) b1s[t] = b1[t];
    if (t < 32) b2s[t] = b2[t];
    __syncthreads();
    int p = blockIdx.x * 128 + t;   // grid 128; block covers rows 2*blk, 2*blk+1
    float x[32];
#pragma unroll
    for (int c = 0; c < 32; c++) x[c] = d_xn[p * 32 + c];
    float o[32];
#pragma unroll
    for (int j = 0; j < 32; j++) o[j] = b2s[j];
    for (int k = 0; k < 64; k++) {
        float a = b1s[k];
#pragma unroll
        for (int c = 0; c < 32; c++) a += x[c] * w1s[c * 64 + k];
        a = gelu_f(a);
#pragma unroll
        for (int j = 0; j < 32; j++) o[j] += a * w2s[k * 32 + j];
    }
    float ss = 0.f, ss2 = 0.f;
#pragma unroll
    for (int j = 0; j < 32; j++) {
        d_x2[p * 32 + j] = o[j];
        ss += o[j]; ss2 += o[j] * o[j];
    }
    sh1[t] = ss; sh2[t] = ss2; __syncthreads();
    int half = t & 64;
    int l = t & 63;
    for (int off = 32; off > 0; off >>= 1) {
        if (l < off) { sh1[half + l] += sh1[half + l + off]; sh2[half + l] += sh2[half + l + off]; }
        __syncthreads();
    }
    if (l == 0) {
        int row = blockIdx.x * 2 + (half >> 6);
        float m = sh1[half] * (1.0f / 2048.0f);
        float var = sh2[half] * (1.0f / 2048.0f) - m * m;
        d_stats[1024 + row] = m;
        d_stats[1024 + 256 + row] = rsqrtf(var + 1e-5f);
    }
}

// ---------------- edge hidden h = gelu(attr @ kw1 + kb1), fp16 out ----------------
__global__ void edgehid_kernel(const float* attr, const float* w1, const float* b1) {
    int e0 = blockIdx.x * 64;   // 2048 blocks
    int t = threadIdx.x;        // 256
    __shared__ float at[384], w1s[384], b1s[64];
    for (int i = t; i < 384; i += 256) { at[i] = attr[e0 * 6 + i]; w1s[i] = w1[i]; }
    if (t < 64) b1s[t] = b1[t];
    __syncthreads();
#pragma unroll
    for (int r = 0; r < 16; r++) {
        int i = t + r * 256; int el = i >> 6, k = i & 63;
        float a = b1s[k];
#pragma unroll
        for (int d = 0; d < 6; d++) a += at[el * 6 + d] * w1s[d * 64 + k];
        d_hh[(long long)(e0 + el) * 64 + k] = __float2half_rn(gelu_f(a));
    }
}

// ---------------- g GEMM: [16384,32] @ [32,2048], fp16 B-fragment layout ----------------
__global__ void gemm_g_kernel(const float* __restrict__ w2) {
    __shared__ float As[64 * 33];
    __shared__ float Bs[32 * 65];
    int row0 = blockIdx.x * 64;     // grid (256,32)
    int col0 = blockIdx.y * 64;
    int t = threadIdx.x;            // 256
    for (int i = t; i < 2048; i += 256)
        As[(i >> 5) * 33 + (i & 31)] = d_xn[(row0 + (i >> 5)) * 32 + (i & 31)];
    for (int i = t; i < 2048; i += 256) {
        int c = i >> 6, j = i & 63; int col = col0 + j;
        Bs[c * 65 + j] = w2[(col >> 5) * 1024 + c * 32 + (col & 31)];
    }
    __syncthreads();
    int tr = (t >> 4) * 4, tc = (t & 15) * 4;
    float acc[4][4] = {};
#pragma unroll
    for (int c = 0; c < 32; c++) {
        float a0 = As[tr * 33 + c], a1 = As[(tr + 1) * 33 + c],
              a2 = As[(tr + 2) * 33 + c], a3 = As[(tr + 3) * 33 + c];
        float b0 = Bs[c * 65 + tc], b1 = Bs[c * 65 + tc + 1],
              b2 = Bs[c * 65 + tc + 2], b3 = Bs[c * 65 + tc + 3];
        acc[0][0] += a0 * b0; acc[0][1] += a0 * b1; acc[0][2] += a0 * b2; acc[0][3] += a0 * b3;
        acc[1][0] += a1 * b0; acc[1][1] += a1 * b1; acc[1][2] += a1 * b2; acc[1][3] += a1 * b3;
        acc[2][0] += a2 * b0; acc[2][1] += a2 * b1; acc[2][2] += a2 * b2; acc[2][3] += a2 * b3;
        acc[3][0] += a3 * b0; acc[3][1] += a3 * b1; acc[3][2] += a3 * b2; acc[3][3] += a3 * b3;
    }
    // store into mma B-fragment layout:
    // half offset = row*2048 + ((kstep*4+ntile)*32 + lane)*4 + hpos
#pragma unroll
    for (int i = 0; i < 4; i++) {
        int row = row0 + tr + i;
#pragma unroll
        for (int j = 0; j < 4; j++) {
            int col = col0 + tc + j;
            int k = col >> 5, o = col & 31;
            int kstep = k >> 4, kin = k & 15;
            int nt = o >> 3, nin = o & 7;
            int lane = nin * 4 + ((kin >> 1) & 3);
            int hp = (kin & 1) + ((kin >> 3) << 1);
            d_gh[(long long)row * 2048 + ((kstep * 4 + nt) * 32 + lane) * 4 + hp] =
                __float2half_rn(acc[i][j]);
        }
    }
}

// ---------------- per-src msg via mma.m16n8k16 ----------------
__global__ void __launch_bounds__(128) edgemsg_kernel(const float* __restrict__ kb2) {
    int node = blockIdx.x;   // 4096
    int t = threadIdx.x;
    int wid = t >> 5, lane = t & 31;   // wid == b
    int s0 = d_offA[node], s1 = d_offA[node + 1];
    if (s0 == s1) return;
    __shared__ float  xsrc[128];
    __shared__ float  xbs[128];
    __shared__ __half hsm[16 * 72];
    __shared__ int    es[16];
    __shared__ int    dp[16];

    // B fragments for this (b=wid, node): 16 frags x uint2, coalesced
    uint2 bf[16];
    {
        const uint2* gp = (const uint2*)d_gh + (long long)(wid * NND + node) * 512;
#pragma unroll
        for (int f = 0; f < 16; f++) bf[f] = gp[f * 32 + lane];
    }
    // xb[b][o] = sum_c xn[b,node,c]*kb2[c,o]
    xsrc[t] = d_xn[(wid * NND + node) * 32 + lane];
    __syncthreads();
    float xb = 0.f;
#pragma unroll
    for (int c = 0; c < 32; c++) xb += xsrc[wid * 32 + c] * kb2[c * 32 + lane];
    xbs[t] = xb;
    __syncthreads();
    float xb0[4], xb1[4];
#pragma unroll
    for (int nt = 0; nt < 4; nt++) {
        int col = nt * 8 + (lane & 3) * 2;
        xb0[nt] = xbs[wid * 32 + col];
        xb1[nt] = xbs[wid * 32 + col + 1];
    }
    int r0 = lane >> 2, r1 = r0 + 8;
    unsigned hbase = smem_u32(hsm);

    for (int ec = s0; ec < s1; ec += 16) {
        int nch = min(16, s1 - ec);
        __syncthreads();
        if (t < nch) { int e = d_eid[ec + t]; es[t] = e; dp[t] = d_eid[EED + e]; }
        __syncthreads();
        {   // load H tile [16 x 64] halves, row pitch 72
            int r = t >> 3, c8 = t & 7;
            int4 hv = make_int4(0, 0, 0, 0);
            if (r < nch) hv = *(const int4*)(d_hh + (long long)es[r] * 64 + c8 * 8);
            *(int4*)(hsm + r * 72 + c8 * 8) = hv;
        }
        __syncthreads();
        float acc[4][4];
#pragma unroll
        for (int nt = 0; nt < 4; nt++) {
            acc[nt][0] = xb0[nt]; acc[nt][1] = xb1[nt];
            acc[nt][2] = xb0[nt]; acc[nt][3] = xb1[nt];
        }
#pragma unroll
        for (int ks = 0; ks < 4; ks++) {
            unsigned a0, a1, a2, a3;
            unsigned addr = hbase + (lane & 15) * 144 + ks * 32 + (lane >> 4) * 16;
            asm volatile("ldmatrix.sync.aligned.m8n8.x4.shared.b16 {%0,%1,%2,%3}, [%4];"
                         : "=r"(a0), "=r"(a1), "=r"(a2), "=r"(a3) : "r"(addr));
#pragma unroll
            for (int nt = 0; nt < 4; nt++) {
                int f = ks * 4 + nt;
                asm volatile(
                    "mma.sync.aligned.m16n8k16.row.col.f32.f16.f16.f32 "
                    "{%0,%1,%2,%3}, {%4,%5,%6,%7}, {%8,%9}, {%0,%1,%2,%3};"
                    : "+f"(acc[nt][0]), "+f"(acc[nt][1]), "+f"(acc[nt][2]), "+f"(acc[nt][3])
                    : "r"(a0), "r"(a1), "r"(a2), "r"(a3), "r"(bf[f].x), "r"(bf[f].y));
            }
        }
        // store rows to dst-ordered msg
#pragma unroll
        for (int nt = 0; nt < 4; nt++) {
            int col = nt * 8 + (lane & 3) * 2;
            if (r0 < nch)
                *(float2*)&d_msg[((long long)dp[r0] * 4 + wid) * 32 + col] =
                    make_float2(acc[nt][0], acc[nt][1]);
            if (r1 < nch)
                *(float2*)&d_msg[((long long)dp[r1] * 4 + wid) * 32 + col] =
                    make_float2(acc[nt][2], acc[nt][3]);
        }
    }
}

// ---------------- dst gather (contiguous) + root + bias + combine + gelu ----------------
__global__ void __launch_bounds__(128) final_kernel(const float* __restrict__ root,
                                                    const float* __restrict__ gbias,
                                                    float* __restrict__ out) {
    int n = blockIdx.x;   // 4096
    int t = threadIdx.x; int b = t >> 5, o = t & 31;
    __shared__ float roots[1024];
    __shared__ float xs[128];
    for (int i = t; i < 1024; i += 128) roots[i] = root[i];
    xs[t] = d_xn[(b * NND + n) * 32 + o];
    __syncthreads();
    float acc = gbias[o];
#pragma unroll
    for (int c = 0; c < 32; c++) acc += xs[b * 32 + c] * roots[c * 32 + o];
    int s0 = d_offA[(NND + 1) + n], s1 = d_offA[(NND + 1) + n + 1];
    int i = s0;
    float a0 = 0.f, a1 = 0.f, a2 = 0.f, a3 = 0.f;
    for (; i + 4 <= s1; i += 4) {
        a0 += d_msg[((long long)i * 4 + b) * 32 + o];
        a1 += d_msg[((long long)(i + 1) * 4 + b) * 32 + o];
        a2 += d_msg[((long long)(i + 2) * 4 + b) * 32 + o];
        a3 += d_msg[((long long)(i + 3) * 4 + b) * 32 + o];
    }
    for (; i < s1; i++) a0 += d_msg[((long long)i * 4 + b) * 32 + o];
    acc += (a0 + a1) + (a2 + a3);
    int p = b * NND + n; int row = p >> 6;
    float x2v = (d_x2[(long long)p * 32 + o] - d_stats[1024 + row]) * d_stats[1024 + 256 + row];
    float s = d_x1b[(long long)p * 32 + o] + x2v + acc;
    out[(long long)p * 32 + o] = gelu_f(s);
}

// ---------------- launch ----------------
extern "C" void kernel_launch(void* const* d_in, const int* in_sizes, int n_in,
                              void* d_out, int out_size) {
    const float* nodes  = (const float*)d_in[0];
    const void*  eidx   = d_in[1];
    const float* eattr  = (const float*)d_in[2];
    const float* w1re   = (const float*)d_in[3];
    const float* w1im   = (const float*)d_in[4];
    const float* w2re   = (const float*)d_in[5];
    const float* w2im   = (const float*)d_in[6];
    const float* mlp_w1 = (const float*)d_in[7];
    const float* mlp_b1 = (const float*)d_in[8];
    const float* mlp_w2 = (const float*)d_in[9];
    const float* mlp_b2 = (const float*)d_in[10];
    const float* wm_w1  = (const float*)d_in[11];
    const float* wm_b1  = (const float*)d_in[12];
    const float* wm_w2  = (const float*)d_in[13];
    const float* wm_b2  = (const float*)d_in[14];
    const float* kw1    = (const float*)d_in[15];
    const float* kb1    = (const float*)d_in[16];
    const float* kw2    = (const float*)d_in[17];
    const float* kb2    = (const float*)d_in[18];
    const float* root   = (const float*)d_in[19];
    const float* gbias  = (const float*)d_in[20];
    float* out = (float*)d_out;

    // CSR build
    initcsr_kernel<<<8, 1024>>>(eidx);
    convhist_kernel<<<512, 256>>>(eidx);
    scan_kernel<<<2, 1024>>>();
    fill_kernel<<<512, 256>>>();

    // normalize input
    stats_kernel<<<256, 256>>>(nodes, 0);
    norm_kernel<<<512, 1024>>>(nodes);

    // spectral branch
    fwdW_kernel<<<256, 256>>>();
    fwdH_kernel<<<128, 512>>>();
    modemix_kernel<<<512, 128>>>(w1re, w1im, w2re, w2im);
    invH_kernel<<<256, 512>>>();
    invW_kernel<<<256, 256>>>();          // + stats slot1
    mlp0_kernel<<<128, 128>>>(mlp_w1, mlp_b1, mlp_w2, mlp_b2);

    // pointwise branch
    mlp1_kernel<<<128, 128>>>(wm_w1, wm_b1, wm_w2, wm_b2);   // + stats slot2

    // GNO branch
    edgehid_kernel<<<2048, 256>>>(eattr, kw1, kb1);
    {
        dim3 g(256, 32);
        gemm_g_kernel<<<g, 256>>>(kw2);
    }
    edgemsg_kernel<<<4096, 128>>>(kb2);

    // combine
    final_kernel<<<4096, 128>>>(root, gbias, out);
}

// round 10
// speedup vs baseline: 1.4821x; 1.4821x over previous
#include <cuda_runtime.h>
#include <cuda_fp16.h>
#include <math.h>

#define BB 4
#define NND 4096
#define EED 131072

// ---------------- scratch ----------------
__device__ float  d_stats[3 * 512];
__device__ float  d_xn  [BB * NND * 32];
__device__ float2 d_T   [BB * 64 * 16 * 32];
__device__ float2 d_Xft [BB * 32 * 16 * 32];
__device__ float2 d_oft [BB * 32 * 16 * 32];
__device__ float2 d_V   [BB * 64 * 16 * 32];
__device__ float  d_x1  [BB * NND * 32];
__device__ float  d_x1b [BB * NND * 32];
__device__ float  d_x2  [BB * NND * 32];
__device__ __half d_hh  [(long long)EED * 64];
__device__ __half d_gh  [(long long)BB * NND * 64 * 32];   // linear [row][k*32+o]
__device__ float  d_msg [(long long)EED * BB * 32];        // indexed by dst-CSR position
__device__ int    d_esrc[EED];
__device__ int    d_edst[EED];
__device__ int    d_is64;
__device__ int    d_cnt [2 * NND];
__device__ int    d_offA[2 * (NND + 1)];
__device__ int    d_cur [2 * NND];
__device__ int    d_eid [2 * EED];   // [0:E) src-CSR edge ids; [E:2E) dstpos per edge

__device__ __forceinline__ float gelu_f(float x) {
    return 0.5f * x * (1.0f + erff(x * 0.70710678118654752f));
}
__device__ __forceinline__ unsigned smem_u32(const void* p) {
    return (unsigned)__cvta_generic_to_shared(p);
}

// ---------------- init: zero cnt/cur + probe edge dtype ----------------
__global__ void initcsr_kernel(const void* ei) {
    int i = blockIdx.x * 1024 + threadIdx.x;   // 8x1024
    d_cnt[i] = 0; d_cur[i] = 0;
    if (blockIdx.x == 0 && threadIdx.x < 256) {
        const int* w = (const int*)ei;
        int t = threadIdx.x;
        int nz = 0;
        for (int k = t; k < 1024; k += 256) nz |= w[2 * k + 1];
        __shared__ int s;
        if (t == 0) s = 0;
        __syncthreads();
        if (nz) atomicOr(&s, 1);
        __syncthreads();
        if (t == 0) d_is64 = (s == 0);   // all-zero odd words => int64
    }
}

// ---------------- convert + histogram ----------------
__global__ void convhist_kernel(const void* ei) {
    int e = blockIdx.x * 256 + threadIdx.x;  // 512x256
    int s, d;
    if (d_is64) {
        const long long* p = (const long long*)ei;
        s = (int)p[e]; d = (int)p[EED + e];
    } else {
        const int* p = (const int*)ei;
        s = p[e]; d = p[EED + e];
    }
    d_esrc[e] = s; d_edst[e] = d;
    atomicAdd(&d_cnt[s], 1);
    atomicAdd(&d_cnt[NND + d], 1);
}

__global__ void scan_kernel() {
    int a = blockIdx.x;   // 0=src, 1=dst
    int t = threadIdx.x;  // 1024
    const int* cnt = d_cnt + a * NND;
    int* off = d_offA + a * (NND + 1);
    int v0 = cnt[t * 4], v1 = cnt[t * 4 + 1], v2 = cnt[t * 4 + 2], v3 = cnt[t * 4 + 3];
    int s = v0 + v1 + v2 + v3;
    __shared__ int sh[1024];
    sh[t] = s; __syncthreads();
    for (int o1 = 1; o1 < 1024; o1 <<= 1) {
        int v = (t >= o1) ? sh[t - o1] : 0;
        __syncthreads();
        sh[t] += v;
        __syncthreads();
    }
    int excl = sh[t] - s;
    off[t * 4] = excl; off[t * 4 + 1] = excl + v0;
    off[t * 4 + 2] = excl + v0 + v1; off[t * 4 + 3] = excl + v0 + v1 + v2;
    if (t == 1023) off[NND] = sh[1023];
}

__global__ void fill_kernel() {
    int e = blockIdx.x * 256 + threadIdx.x;    // 512x256
    int s = d_esrc[e], d2 = d_edst[e];
    int p = atomicAdd(&d_cur[s], 1);
    d_eid[d_offA[s] + p] = e;
    int q = atomicAdd(&d_cur[NND + d2], 1);
    d_eid[EED + e] = d_offA[(NND + 1) + d2] + q;   // dstpos of edge e
}

// ---------------- instance-norm stats over (W,C) ----------------
__global__ void stats_kernel(const float* in, int slot) {
    int row = blockIdx.x;            // 256
    const float* p = in + row * 2048;
    int t = threadIdx.x;             // 256
    float s = 0.f, s2 = 0.f;
#pragma unroll
    for (int i = 0; i < 8; i++) { float v = p[t + i * 256]; s += v; s2 += v * v; }
    __shared__ float sh1[256], sh2[256];
    sh1[t] = s; sh2[t] = s2; __syncthreads();
    for (int o = 128; o > 0; o >>= 1) {
        if (t < o) { sh1[t] += sh1[t + o]; sh2[t] += sh2[t + o]; }
        __syncthreads();
    }
    if (t == 0) {
        float m = sh1[0] * (1.0f / 2048.0f);
        float var = sh2[0] * (1.0f / 2048.0f) - m * m;
        d_stats[slot * 512 + row] = m;
        d_stats[slot * 512 + 256 + row] = rsqrtf(var + 1e-5f);
    }
}

__global__ void norm_kernel(const float* nodes) {
    int i = blockIdx.x * 1024 + threadIdx.x;   // 512x1024
    int row = i >> 11;
    d_xn[i] = (nodes[i] - d_stats[row]) * d_stats[256 + row];
}

// ---------------- forward DFT over W (ky 0..15) ----------------
__global__ void fwdW_kernel() {
    int bh = blockIdx.x;            // 256
    int t = threadIdx.x;            // 256
    __shared__ float  xs[2048];
    __shared__ float2 tw[1024];
    for (int i = t; i < 2048; i += 256) xs[i] = d_xn[bh * 2048 + i];
    for (int i = t; i < 1024; i += 256) {
        int ky = i >> 6, w = i & 63; float s, c;
        sincospif(-(float)(ky * w) * (1.0f / 32.0f), &s, &c);
        tw[i] = make_float2(c, s);
    }
    __syncthreads();
#pragma unroll
    for (int r = 0; r < 2; r++) {
        int oi = t + r * 256; int ky = oi >> 5, c = oi & 31;
        float re = 0.f, im = 0.f;
#pragma unroll 8
        for (int w = 0; w < 64; w++) {
            float xv = xs[w * 32 + c]; float2 tv = tw[ky * 64 + w];
            re += xv * tv.x; im += xv * tv.y;
        }
        d_T[(bh * 16 + ky) * 32 + c] = make_float2(re, im);
    }
}

// ---------------- forward DFT over H (kx 0..15, 48..63), *1/64 ----------------
__global__ void fwdH_kernel() {
    int b = blockIdx.x >> 5, kxi = blockIdx.x & 31;   // 128 blocks
    int kx = (kxi < 16) ? kxi : kxi + 32;
    int t = threadIdx.x;                               // 512
    __shared__ float2 tw[64];
    if (t < 64) { float s, c; sincospif(-(float)(kx * t) * (1.0f / 32.0f), &s, &c); tw[t] = make_float2(c, s); }
    __syncthreads();
    int ky = t >> 5, c = t & 31;
    float re = 0.f, im = 0.f;
#pragma unroll 4
    for (int h = 0; h < 64; h++) {
        float2 v = d_T[((b * 64 + h) * 16 + ky) * 32 + c];
        float2 w = tw[h];
        re += v.x * w.x - v.y * w.y;
        im += v.x * w.y + v.y * w.x;
    }
    d_Xft[((b * 32 + kxi) * 16 + ky) * 32 + c] = make_float2(re * (1.0f / 64.0f), im * (1.0f / 64.0f));
}

// ---------------- complex channel mix per (kx,ky) ----------------
__global__ void modemix_kernel(const float* w1re, const float* w1im,
                               const float* w2re, const float* w2im) {
    int kxi = blockIdx.x >> 4, ky = blockIdx.x & 15;   // 512 blocks
    int xm = (kxi < 16) ? kxi : kxi - 16;
    const float* wre = (kxi < 16) ? w1re : w2re;
    const float* wim = (kxi < 16) ? w1im : w2im;
    int t = threadIdx.x;                                // 128
    __shared__ float wr[1024], wi[1024];
    __shared__ float2 Xs[128];
    for (int i = t; i < 1024; i += 128) {
        int off = i * 256 + xm * 16 + ky;
        wr[i] = wre[off]; wi[i] = wim[off];
    }
    { int b = t >> 5, c = t & 31; Xs[t] = d_Xft[((b * 32 + kxi) * 16 + ky) * 32 + c]; }
    __syncthreads();
    int b = t >> 5, o = t & 31;
    float re = 0.f, im = 0.f;
#pragma unroll
    for (int i = 0; i < 32; i++) {
        float2 xv = Xs[b * 32 + i];
        float wrv = wr[i * 32 + o], wiv = wi[i * 32 + o];
        re += xv.x * wrv - xv.y * wiv;
        im += xv.x * wiv + xv.y * wrv;
    }
    d_oft[((b * 32 + kxi) * 16 + ky) * 32 + o] = make_float2(re, im);
}

// ---------------- inverse DFT over H, *1/8 ----------------
__global__ void invH_kernel() {
    int b = blockIdx.x >> 6, h = blockIdx.x & 63;   // 256 blocks
    int t = threadIdx.x;                             // 512
    __shared__ float2 tw[32];
    if (t < 32) {
        int kx = (t < 16) ? t : t + 32; float s, c;
        sincospif((float)(kx * h) * (1.0f / 32.0f), &s, &c);
        tw[t] = make_float2(c, s);
    }
    __syncthreads();
    int ky = t >> 5, o = t & 31;
    float re = 0.f, im = 0.f;
#pragma unroll 4
    for (int k = 0; k < 32; k++) {
        float2 v = d_oft[((b * 32 + k) * 16 + ky) * 32 + o];
        float2 w = tw[k];
        re += v.x * w.x - v.y * w.y;
        im += v.x * w.y + v.y * w.x;
    }
    d_V[((b * 64 + h) * 16 + ky) * 32 + o] = make_float2(re * 0.125f, im * 0.125f);
}

// ---------------- inverse C2R over W, *1/8, fused stats(slot1) ----------------
__global__ void invW_kernel() {
    int bh = blockIdx.x; int t = threadIdx.x;   // 256 x 256
    __shared__ float2 Vs[512];
    __shared__ float2 tw[1024];
    __shared__ float sh1[256], sh2[256];
    for (int i = t; i < 512; i += 256) Vs[i] = d_V[bh * 512 + i];
    for (int i = t; i < 1024; i += 256) {
        int ky = i >> 6, w = i & 63; float s, c;
        sincospif((float)(ky * w) * (1.0f / 32.0f), &s, &c);
        tw[i] = make_float2(c, s);
    }
    __syncthreads();
    float ss = 0.f, ss2 = 0.f;
#pragma unroll
    for (int r = 0; r < 8; r++) {
        int oi = t + r * 256; int w = oi >> 5, o = oi & 31;
        float acc = 0.f;
#pragma unroll
        for (int ky = 0; ky < 16; ky++) {
            float2 v = Vs[ky * 32 + o]; float2 tv = tw[ky * 64 + w];
            float term = v.x * tv.x - v.y * tv.y;
            acc += (ky == 0) ? term : 2.0f * term;
        }
        acc *= 0.125f;
        d_x1[bh * 2048 + oi] = acc;
        ss += acc; ss2 += acc * acc;
    }
    sh1[t] = ss; sh2[t] = ss2; __syncthreads();
    for (int o = 128; o > 0; o >>= 1) {
        if (t < o) { sh1[t] += sh1[t + o]; sh2[t] += sh2[t + o]; }
        __syncthreads();
    }
    if (t == 0) {
        float m = sh1[0] * (1.0f / 2048.0f);
        float var = sh2[0] * (1.0f / 2048.0f) - m * m;
        d_stats[512 + bh] = m;
        d_stats[512 + 256 + bh] = rsqrtf(var + 1e-5f);
    }
}

// ---------------- MLP on inorm(x1) -> d_x1b ----------------
__global__ void __launch_bounds__(128) mlp0_kernel(const float* w1, const float* b1,
                                                   const float* w2, const float* b2) {
    int t = threadIdx.x;   // 128
    __shared__ float w1s[2048], w2s[2048], b1s[64], b2s[32];
    for (int i = t; i < 2048; i += 128) { w1s[i] = w1[i]; w2s[i] = w2[i]; }
    if (t < 64) b1s[t] = b1[t];
    if (t < 32) b2s[t] = b2[t];
    __syncthreads();
    int p = blockIdx.x * 128 + t;   // grid 128
    int row = p >> 6;
    float m = d_stats[512 + row], rs = d_stats[512 + 256 + row];
    float x[32];
#pragma unroll
    for (int c = 0; c < 32; c++) x[c] = (d_x1[p * 32 + c] - m) * rs;
    float o[32];
#pragma unroll
    for (int j = 0; j < 32; j++) o[j] = b2s[j];
    for (int k = 0; k < 64; k++) {
        float a = b1s[k];
#pragma unroll
        for (int c = 0; c < 32; c++) a += x[c] * w1s[c * 64 + k];
        a = gelu_f(a);
#pragma unroll
        for (int j = 0; j < 32; j++) o[j] += a * w2s[k * 32 + j];
    }
#pragma unroll
    for (int j = 0; j < 32; j++) d_x1b[p * 32 + j] = o[j];
}

// ---------------- MLP on xn -> d_x2, fused stats(slot2) ----------------
__global__ void __launch_bounds__(128) mlp1_kernel(const float* w1, const float* b1,
                                                   const float* w2, const float* b2) {
    int t = threadIdx.x;   // 128
    __shared__ float w1s[2048], w2s[2048], b1s[64], b2s[32];
    __shared__ float sh1[128], sh2[128];
    for (int i = t; i < 2048; i += 128) { w1s[i] = w1[i]; w2s[i] = w2[i]; }
    if (t < 64) b1s[t] = b1[t];
    if (t < 32) b2s[t] = b2[t];
    __syncthreads();
    int p = blockIdx.x * 128 + t;   // grid 128
    float x[32];
#pragma unroll
    for (int c = 0; c < 32; c++) x[c] = d_xn[p * 32 + c];
    float o[32];
#pragma unroll
    for (int j = 0; j < 32; j++) o[j] = b2s[j];
    for (int k = 0; k < 64; k++) {
        float a = b1s[k];
#pragma unroll
        for (int c = 0; c < 32; c++) a += x[c] * w1s[c * 64 + k];
        a = gelu_f(a);
#pragma unroll
        for (int j = 0; j < 32; j++) o[j] += a * w2s[k * 32 + j];
    }
    float ss = 0.f, ss2 = 0.f;
#pragma unroll
    for (int j = 0; j < 32; j++) {
        d_x2[p * 32 + j] = o[j];
        ss += o[j]; ss2 += o[j] * o[j];
    }
    sh1[t] = ss; sh2[t] = ss2; __syncthreads();
    int half = t & 64;
    int l = t & 63;
    for (int off = 32; off > 0; off >>= 1) {
        if (l < off) { sh1[half + l] += sh1[half + l + off]; sh2[half + l] += sh2[half + l + off]; }
        __syncthreads();
    }
    if (l == 0) {
        int row = blockIdx.x * 2 + (half >> 6);
        float m = sh1[half] * (1.0f / 2048.0f);
        float var = sh2[half] * (1.0f / 2048.0f) - m * m;
        d_stats[1024 + row] = m;
        d_stats[1024 + 256 + row] = rsqrtf(var + 1e-5f);
    }
}

// ---------------- edge hidden h = gelu(attr @ kw1 + kb1), fp16 out ----------------
__global__ void edgehid_kernel(const float* attr, const float* w1, const float* b1) {
    int e0 = blockIdx.x * 64;   // 2048 blocks
    int t = threadIdx.x;        // 256
    __shared__ float at[384], w1s[384], b1s[64];
    for (int i = t; i < 384; i += 256) { at[i] = attr[e0 * 6 + i]; w1s[i] = w1[i]; }
    if (t < 64) b1s[t] = b1[t];
    __syncthreads();
#pragma unroll
    for (int r = 0; r < 16; r++) {
        int i = t + r * 256; int el = i >> 6, k = i & 63;
        float a = b1s[k];
#pragma unroll
        for (int d = 0; d < 6; d++) a += at[el * 6 + d] * w1s[d * 64 + k];
        d_hh[(long long)(e0 + el) * 64 + k] = __float2half_rn(gelu_f(a));
    }
}

// ---------------- g GEMM: [16384,32] @ [32,2048], fp16 linear out ----------------
__global__ void gemm_g_kernel(const float* __restrict__ w2) {
    __shared__ float As[64 * 33];
    __shared__ float Bs[32 * 65];
    int row0 = blockIdx.x * 64;     // grid (256,32)
    int col0 = blockIdx.y * 64;
    int t = threadIdx.x;            // 256
    for (int i = t; i < 2048; i += 256)
        As[(i >> 5) * 33 + (i & 31)] = d_xn[(row0 + (i >> 5)) * 32 + (i & 31)];
    for (int i = t; i < 2048; i += 256) {
        int c = i >> 6, j = i & 63; int col = col0 + j;
        Bs[c * 65 + j] = w2[(col >> 5) * 1024 + c * 32 + (col & 31)];
    }
    __syncthreads();
    int tr = (t >> 4) * 4, tc = (t & 15) * 4;
    float acc[4][4] = {};
#pragma unroll
    for (int c = 0; c < 32; c++) {
        float a0 = As[tr * 33 + c], a1 = As[(tr + 1) * 33 + c],
              a2 = As[(tr + 2) * 33 + c], a3 = As[(tr + 3) * 33 + c];
        float b0 = Bs[c * 65 + tc], b1 = Bs[c * 65 + tc + 1],
              b2 = Bs[c * 65 + tc + 2], b3 = Bs[c * 65 + tc + 3];
        acc[0][0] += a0 * b0; acc[0][1] += a0 * b1; acc[0][2] += a0 * b2; acc[0][3] += a0 * b3;
        acc[1][0] += a1 * b0; acc[1][1] += a1 * b1; acc[1][2] += a1 * b2; acc[1][3] += a1 * b3;
        acc[2][0] += a2 * b0; acc[2][1] += a2 * b1; acc[2][2] += a2 * b2; acc[2][3] += a2 * b3;
        acc[3][0] += a3 * b0; acc[3][1] += a3 * b1; acc[3][2] += a3 * b2; acc[3][3] += a3 * b3;
    }
    __half2* gh2 = (__half2*)d_gh;
#pragma unroll
    for (int i = 0; i < 4; i++) {
        long long base = (long long)(row0 + tr + i) * 2048 + col0 + tc;
        gh2[base >> 1]       = __floats2half2_rn(acc[i][0], acc[i][1]);
        gh2[(base >> 1) + 1] = __floats2half2_rn(acc[i][2], acc[i][3]);
    }
}

// ---------------- per-src msg via mma.m16n8k16; B-frags via ldmatrix.trans ----------------
__global__ void __launch_bounds__(128) edgemsg_kernel(const float* __restrict__ kb2) {
    int node = blockIdx.x;   // 4096
    int t = threadIdx.x;
    int wid = t >> 5, lane = t & 31;   // wid == b
    int s0 = d_offA[node], s1 = d_offA[node + 1];
    if (s0 == s1) return;
    __shared__ __align__(16) __half gsm[4][64 * 40];   // [b][k row][o], pitch 40 halves = 80B
    __shared__ __align__(16) __half hsm[16 * 72];      // [edge][k], pitch 72 halves = 144B
    __shared__ float xsrc[128];
    __shared__ float xbs[128];
    __shared__ int   es[16];
    __shared__ int   dp[16];

    // coalesced load of G (linear) into pitched smem
    {
        const int4* gp = (const int4*)(d_gh + (long long)(wid * NND + node) * 2048);
#pragma unroll
        for (int i = 0; i < 8; i++) {
            int idx = i * 32 + lane;          // 256 int4 per warp
            int4 v = gp[idx];
            int r = idx >> 2, c4 = idx & 3;
            *(int4*)&gsm[wid][r * 40 + c4 * 8] = v;
        }
    }
    xsrc[t] = d_xn[(wid * NND + node) * 32 + lane];
    __syncwarp();

    // build 16 B-fragments with ldmatrix.x4.trans
    uint2 bf[16];
    {
        unsigned gb = smem_u32(&gsm[wid][0]);
        int grp = lane >> 3, rowi = lane & 7;
#pragma unroll
        for (int ks = 0; ks < 4; ks++) {
#pragma unroll
            for (int np = 0; np < 2; np++) {
                unsigned addr = gb + (unsigned)((ks * 16 + (grp & 1) * 8 + rowi) * 80
                                                + (np * 2 + (grp >> 1)) * 16);
                unsigned r0, r1, r2, r3;
                asm volatile("ldmatrix.sync.aligned.m8n8.x4.trans.shared.b16 {%0,%1,%2,%3}, [%4];"
                             : "=r"(r0), "=r"(r1), "=r"(r2), "=r"(r3) : "r"(addr));
                bf[ks * 4 + np * 2 + 0] = make_uint2(r0, r1);
                bf[ks * 4 + np * 2 + 1] = make_uint2(r2, r3);
            }
        }
    }
    // xb[b][o] = sum_c xn[b,node,c]*kb2[c,o]   (warp-local)
    float xb = 0.f;
#pragma unroll
    for (int c = 0; c < 32; c++) xb += xsrc[wid * 32 + c] * kb2[c * 32 + lane];
    xbs[t] = xb;
    __syncwarp();
    float xb0[4], xb1[4];
#pragma unroll
    for (int nt = 0; nt < 4; nt++) {
        int col = nt * 8 + (lane & 3) * 2;
        xb0[nt] = xbs[wid * 32 + col];
        xb1[nt] = xbs[wid * 32 + col + 1];
    }
    int r0 = lane >> 2, r1 = r0 + 8;
    unsigned hbase = smem_u32(hsm);

    for (int ec = s0; ec < s1; ec += 16) {
        int nch = min(16, s1 - ec);
        __syncthreads();
        if (t < nch) { int e = d_eid[ec + t]; es[t] = e; dp[t] = d_eid[EED + e]; }
        __syncthreads();
        {   // load H tile [16 x 64] halves
            int r = t >> 3, c8 = t & 7;
            int4 hv = make_int4(0, 0, 0, 0);
            if (r < nch) hv = *(const int4*)(d_hh + (long long)es[r] * 64 + c8 * 8);
            *(int4*)(hsm + r * 72 + c8 * 8) = hv;
        }
        __syncthreads();
        float acc[4][4];
#pragma unroll
        for (int nt = 0; nt < 4; nt++) {
            acc[nt][0] = xb0[nt]; acc[nt][1] = xb1[nt];
            acc[nt][2] = xb0[nt]; acc[nt][3] = xb1[nt];
        }
#pragma unroll
        for (int ks = 0; ks < 4; ks++) {
            unsigned a0, a1, a2, a3;
            unsigned addr = hbase + (lane & 15) * 144 + ks * 32 + (lane >> 4) * 16;
            asm volatile("ldmatrix.sync.aligned.m8n8.x4.shared.b16 {%0,%1,%2,%3}, [%4];"
                         : "=r"(a0), "=r"(a1), "=r"(a2), "=r"(a3) : "r"(addr));
#pragma unroll
            for (int nt = 0; nt < 4; nt++) {
                int f = ks * 4 + nt;
                asm volatile(
                    "mma.sync.aligned.m16n8k16.row.col.f32.f16.f16.f32 "
                    "{%0,%1,%2,%3}, {%4,%5,%6,%7}, {%8,%9}, {%0,%1,%2,%3};"
                    : "+f"(acc[nt][0]), "+f"(acc[nt][1]), "+f"(acc[nt][2]), "+f"(acc[nt][3])
                    : "r"(a0), "r"(a1), "r"(a2), "r"(a3), "r"(bf[f].x), "r"(bf[f].y));
            }
        }
#pragma unroll
        for (int nt = 0; nt < 4; nt++) {
            int col = nt * 8 + (lane & 3) * 2;
            if (r0 < nch)
                *(float2*)&d_msg[((long long)dp[r0] * 4 + wid) * 32 + col] =
                    make_float2(acc[nt][0], acc[nt][1]);
            if (r1 < nch)
                *(float2*)&d_msg[((long long)dp[r1] * 4 + wid) * 32 + col] =
                    make_float2(acc[nt][2], acc[nt][3]);
        }
    }
}

// ---------------- dst gather (contiguous) + root + bias + combine + gelu ----------------
__global__ void __launch_bounds__(128) final_kernel(const float* __restrict__ root,
                                                    const float* __restrict__ gbias,
                                                    float* __restrict__ out) {
    int n = blockIdx.x;   // 4096
    int t = threadIdx.x; int b = t >> 5, o = t & 31;
    __shared__ float roots[1024];
    __shared__ float xs[128];
    for (int i = t; i < 1024; i += 128) roots[i] = root[i];
    xs[t] = d_xn[(b * NND + n) * 32 + o];
    __syncthreads();
    float acc = gbias[o];
#pragma unroll
    for (int c = 0; c < 32; c++) acc += xs[b * 32 + c] * roots[c * 32 + o];
    int s0 = d_offA[(NND + 1) + n], s1 = d_offA[(NND + 1) + n + 1];
    int i = s0;
    float a0 = 0.f, a1 = 0.f, a2 = 0.f, a3 = 0.f;
    for (; i + 4 <= s1; i += 4) {
        a0 += d_msg[((long long)i * 4 + b) * 32 + o];
        a1 += d_msg[((long long)(i + 1) * 4 + b) * 32 + o];
        a2 += d_msg[((long long)(i + 2) * 4 + b) * 32 + o];
        a3 += d_msg[((long long)(i + 3) * 4 + b) * 32 + o];
    }
    for (; i < s1; i++) a0 += d_msg[((long long)i * 4 + b) * 32 + o];
    acc += (a0 + a1) + (a2 + a3);
    int p = b * NND + n; int row = p >> 6;
    float x2v = (d_x2[(long long)p * 32 + o] - d_stats[1024 + row]) * d_stats[1024 + 256 + row];
    float s = d_x1b[(long long)p * 32 + o] + x2v + acc;
    out[(long long)p * 32 + o] = gelu_f(s);
}

// ---------------- launch (fork/join stream-parallel graph) ----------------
extern "C" void kernel_launch(void* const* d_in, const int* in_sizes, int n_in,
                              void* d_out, int out_size) {
    const float* nodes  = (const float*)d_in[0];
    const void*  eidx   = d_in[1];
    const float* eattr  = (const float*)d_in[2];
    const float* w1re   = (const float*)d_in[3];
    const float* w1im   = (const float*)d_in[4];
    const float* w2re   = (const float*)d_in[5];
    const float* w2im   = (const float*)d_in[6];
    const float* mlp_w1 = (const float*)d_in[7];
    const float* mlp_b1 = (const float*)d_in[8];
    const float* mlp_w2 = (const float*)d_in[9];
    const float* mlp_b2 = (const float*)d_in[10];
    const float* wm_w1  = (const float*)d_in[11];
    const float* wm_b1  = (const float*)d_in[12];
    const float* wm_w2  = (const float*)d_in[13];
    const float* wm_b2  = (const float*)d_in[14];
    const float* kw1    = (const float*)d_in[15];
    const float* kb1    = (const float*)d_in[16];
    const float* kw2    = (const float*)d_in[17];
    const float* kb2    = (const float*)d_in[18];
    const float* root   = (const float*)d_in[19];
    const float* gbias  = (const float*)d_in[20];
    float* out = (float*)d_out;

    static cudaStream_t sA = nullptr, sB = nullptr;
    static cudaEvent_t evRoot, evN, evA, evB;
    if (sA == nullptr) {
        cudaStreamCreateWithFlags(&sA, cudaStreamNonBlocking);
        cudaStreamCreateWithFlags(&sB, cudaStreamNonBlocking);
        cudaEventCreateWithFlags(&evRoot, cudaEventDisableTiming);
        cudaEventCreateWithFlags(&evN, cudaEventDisableTiming);
        cudaEventCreateWithFlags(&evA, cudaEventDisableTiming);
        cudaEventCreateWithFlags(&evB, cudaEventDisableTiming);
    }

    // fork point
    cudaEventRecord(evRoot, 0);
    cudaStreamWaitEvent(sA, evRoot, 0);
    cudaStreamWaitEvent(sB, evRoot, 0);

    // stream A: CSR build
    initcsr_kernel<<<8, 1024, 0, sA>>>(eidx);
    convhist_kernel<<<512, 256, 0, sA>>>(eidx);
    scan_kernel<<<2, 1024, 0, sA>>>();
    fill_kernel<<<512, 256, 0, sA>>>();
    cudaEventRecord(evA, sA);

    // stream B: edge hidden (independent of x)
    edgehid_kernel<<<2048, 256, 0, sB>>>(eattr, kw1, kb1);

    // stream 0: normalize input
    stats_kernel<<<256, 256>>>(nodes, 0);
    norm_kernel<<<512, 1024>>>(nodes);
    cudaEventRecord(evN, 0);

    // stream B: g GEMM (needs norm), then edge msg (needs CSR + h + g)
    cudaStreamWaitEvent(sB, evN, 0);
    {
        dim3 g(256, 32);
        gemm_g_kernel<<<g, 256, 0, sB>>>(kw2);
    }
    cudaStreamWaitEvent(sB, evA, 0);
    edgemsg_kernel<<<4096, 128, 0, sB>>>(kb2);
    cudaEventRecord(evB, sB);

    // stream 0: spectral branch + MLPs
    fwdW_kernel<<<256, 256>>>();
    fwdH_kernel<<<128, 512>>>();
    modemix_kernel<<<512, 128>>>(w1re, w1im, w2re, w2im);
    invH_kernel<<<256, 512>>>();
    invW_kernel<<<256, 256>>>();          // + stats slot1
    mlp0_kernel<<<128, 128>>>(mlp_w1, mlp_b1, mlp_w2, mlp_b2);
    mlp1_kernel<<<128, 128>>>(wm_w1, wm_b1, wm_w2, wm_b2);   // + stats slot2

    // join: final combine
    cudaStreamWaitEvent(0, evB, 0);
    final_kernel<<<4096, 128>>>(root, gbias, out);
}

// round 12
// speedup vs baseline: 1.5574x; 1.0508x over previous
#include <cuda_runtime.h>
#include <cuda_fp16.h>
#include <math.h>

#define BB 4
#define NND 4096
#define EED 131072

// ---------------- scratch ----------------
__device__ float  d_stats[3 * 512];          // slot1: x1 stats @512, slot2: x2 stats @1024
__device__ float  d_xn  [BB * NND * 32];
__device__ float2 d_T   [BB * 64 * 16 * 32];
__device__ float2 d_Xft [BB * 32 * 16 * 32];
__device__ float2 d_oft [BB * 32 * 16 * 32];
__device__ float2 d_V   [BB * 64 * 16 * 32];
__device__ float  d_x1  [BB * NND * 32];
__device__ float  d_x1b [BB * NND * 32];
__device__ float  d_x2  [BB * NND * 32];
__device__ __half d_hh  [(long long)EED * 64];
__device__ __half d_gh  [(long long)BB * NND * 64 * 32];   // linear [row][k*32+o]
__device__ __half d_msg [(long long)EED * BB * 32];        // fp16, indexed by dst-CSR position
__device__ int    d_esrc[EED];
__device__ int    d_edst[EED];
__device__ int    d_is64;
__device__ int    d_cnt [2 * NND];
__device__ int    d_offA[2 * (NND + 1)];
__device__ int    d_cur [2 * NND];
__device__ int    d_eid [2 * EED];   // [0:E) src-CSR edge ids; [E:2E) dstpos per edge

__device__ __forceinline__ float gelu_f(float x) {
    return 0.5f * x * (1.0f + erff(x * 0.70710678118654752f));
}
__device__ __forceinline__ unsigned smem_u32(const void* p) {
    return (unsigned)__cvta_generic_to_shared(p);
}

// ---------------- init: zero cnt/cur + probe edge dtype ----------------
__global__ void initcsr_kernel(const void* ei) {
    int i = blockIdx.x * 1024 + threadIdx.x;   // 8x1024
    d_cnt[i] = 0; d_cur[i] = 0;
    if (blockIdx.x == 0 && threadIdx.x < 256) {
        const int* w = (const int*)ei;
        int t = threadIdx.x;
        int nz = 0;
        for (int k = t; k < 1024; k += 256) nz |= w[2 * k + 1];
        __shared__ int s;
        if (t == 0) s = 0;
        __syncthreads();
        if (nz) atomicOr(&s, 1);
        __syncthreads();
        if (t == 0) d_is64 = (s == 0);   // all-zero odd words => int64
    }
}

// ---------------- convert + histogram ----------------
__global__ void convhist_kernel(const void* ei) {
    int e = blockIdx.x * 256 + threadIdx.x;  // 512x256
    int s, d;
    if (d_is64) {
        const long long* p = (const long long*)ei;
        s = (int)p[e]; d = (int)p[EED + e];
    } else {
        const int* p = (const int*)ei;
        s = p[e]; d = p[EED + e];
    }
    d_esrc[e] = s; d_edst[e] = d;
    atomicAdd(&d_cnt[s], 1);
    atomicAdd(&d_cnt[NND + d], 1);
}

__global__ void scan_kernel() {
    int a = blockIdx.x;   // 0=src, 1=dst
    int t = threadIdx.x;  // 1024
    const int* cnt = d_cnt + a * NND;
    int* off = d_offA + a * (NND + 1);
    int v0 = cnt[t * 4], v1 = cnt[t * 4 + 1], v2 = cnt[t * 4 + 2], v3 = cnt[t * 4 + 3];
    int s = v0 + v1 + v2 + v3;
    __shared__ int sh[1024];
    sh[t] = s; __syncthreads();
    for (int o1 = 1; o1 < 1024; o1 <<= 1) {
        int v = (t >= o1) ? sh[t - o1] : 0;
        __syncthreads();
        sh[t] += v;
        __syncthreads();
    }
    int excl = sh[t] - s;
    off[t * 4] = excl; off[t * 4 + 1] = excl + v0;
    off[t * 4 + 2] = excl + v0 + v1; off[t * 4 + 3] = excl + v0 + v1 + v2;
    if (t == 1023) off[NND] = sh[1023];
}

__global__ void fill_kernel() {
    int e = blockIdx.x * 256 + threadIdx.x;    // 512x256
    int s = d_esrc[e], d2 = d_edst[e];
    int p = atomicAdd(&d_cur[s], 1);
    d_eid[d_offA[s] + p] = e;
    int q = atomicAdd(&d_cur[NND + d2], 1);
    d_eid[EED + e] = d_offA[(NND + 1) + d2] + q;   // dstpos of edge e
}

// ---------------- fused instance-norm: stats + normalize in one pass ----------------
__global__ void statsnorm_kernel(const float* __restrict__ nodes) {
    int row = blockIdx.x;            // 256
    int t = threadIdx.x;             // 256
    __shared__ float xs[2048];
    __shared__ float sh1[256], sh2[256];
    __shared__ float mr[2];
    const float* p = nodes + row * 2048;
    float s = 0.f, s2 = 0.f;
#pragma unroll
    for (int i = 0; i < 8; i++) {
        float v = p[t + i * 256];
        xs[t + i * 256] = v;
        s += v; s2 += v * v;
    }
    sh1[t] = s; sh2[t] = s2; __syncthreads();
    for (int o = 128; o > 0; o >>= 1) {
        if (t < o) { sh1[t] += sh1[t + o]; sh2[t] += sh2[t + o]; }
        __syncthreads();
    }
    if (t == 0) {
        float m = sh1[0] * (1.0f / 2048.0f);
        float var = sh2[0] * (1.0f / 2048.0f) - m * m;
        mr[0] = m; mr[1] = rsqrtf(var + 1e-5f);
    }
    __syncthreads();
    float m = mr[0], rs = mr[1];
#pragma unroll
    for (int i = 0; i < 8; i++)
        d_xn[row * 2048 + t + i * 256] = (xs[t + i * 256] - m) * rs;
}

// ---------------- forward DFT over W (ky 0..15) ----------------
__global__ void fwdW_kernel() {
    int bh = blockIdx.x;            // 256
    int t = threadIdx.x;            // 256
    __shared__ float  xs[2048];
    __shared__ float2 tw[1024];
    for (int i = t; i < 2048; i += 256) xs[i] = d_xn[bh * 2048 + i];
    for (int i = t; i < 1024; i += 256) {
        int ky = i >> 6, w = i & 63; float s, c;
        sincospif(-(float)(ky * w) * (1.0f / 32.0f), &s, &c);
        tw[i] = make_float2(c, s);
    }
    __syncthreads();
#pragma unroll
    for (int r = 0; r < 2; r++) {
        int oi = t + r * 256; int ky = oi >> 5, c = oi & 31;
        float re = 0.f, im = 0.f;
#pragma unroll 8
        for (int w = 0; w < 64; w++) {
            float xv = xs[w * 32 + c]; float2 tv = tw[ky * 64 + w];
            re += xv * tv.x; im += xv * tv.y;
        }
        d_T[(bh * 16 + ky) * 32 + c] = make_float2(re, im);
    }
}

// ---------------- forward DFT over H (kx 0..15, 48..63), *1/64 ----------------
__global__ void fwdH_kernel() {
    int b = blockIdx.x >> 5, kxi = blockIdx.x & 31;   // 128 blocks
    int kx = (kxi < 16) ? kxi : kxi + 32;
    int t = threadIdx.x;                               // 512
    __shared__ float2 tw[64];
    if (t < 64) { float s, c; sincospif(-(float)(kx * t) * (1.0f / 32.0f), &s, &c); tw[t] = make_float2(c, s); }
    __syncthreads();
    int ky = t >> 5, c = t & 31;
    float re = 0.f, im = 0.f;
#pragma unroll 4
    for (int h = 0; h < 64; h++) {
        float2 v = d_T[((b * 64 + h) * 16 + ky) * 32 + c];
        float2 w = tw[h];
        re += v.x * w.x - v.y * w.y;
        im += v.x * w.y + v.y * w.x;
    }
    d_Xft[((b * 32 + kxi) * 16 + ky) * 32 + c] = make_float2(re * (1.0f / 64.0f), im * (1.0f / 64.0f));
}

// ---------------- complex channel mix per (kx,ky) ----------------
__global__ void modemix_kernel(const float* w1re, const float* w1im,
                               const float* w2re, const float* w2im) {
    int kxi = blockIdx.x >> 4, ky = blockIdx.x & 15;   // 512 blocks
    int xm = (kxi < 16) ? kxi : kxi - 16;
    const float* wre = (kxi < 16) ? w1re : w2re;
    const float* wim = (kxi < 16) ? w1im : w2im;
    int t = threadIdx.x;                                // 128
    __shared__ float wr[1024], wi[1024];
    __shared__ float2 Xs[128];
    for (int i = t; i < 1024; i += 128) {
        int off = i * 256 + xm * 16 + ky;
        wr[i] = wre[off]; wi[i] = wim[off];
    }
    { int b = t >> 5, c = t & 31; Xs[t] = d_Xft[((b * 32 + kxi) * 16 + ky) * 32 + c]; }
    __syncthreads();
    int b = t >> 5, o = t & 31;
    float re = 0.f, im = 0.f;
#pragma unroll
    for (int i = 0; i < 32; i++) {
        float2 xv = Xs[b * 32 + i];
        float wrv = wr[i * 32 + o], wiv = wi[i * 32 + o];
        re += xv.x * wrv - xv.y * wiv;
        im += xv.x * wiv + xv.y * wrv;
    }
    d_oft[((b * 32 + kxi) * 16 + ky) * 32 + o] = make_float2(re, im);
}

// ---------------- inverse DFT over H, *1/8 ----------------
__global__ void invH_kernel() {
    int b = blockIdx.x >> 6, h = blockIdx.x & 63;   // 256 blocks
    int t = threadIdx.x;                             // 512
    __shared__ float2 tw[32];
    if (t < 32) {
        int kx = (t < 16) ? t : t + 32; float s, c;
        sincospif((float)(kx * h) * (1.0f / 32.0f), &s, &c);
        tw[t] = make_float2(c, s);
    }
    __syncthreads();
    int ky = t >> 5, o = t & 31;
    float re = 0.f, im = 0.f;
#pragma unroll 4
    for (int k = 0; k < 32; k++) {
        float2 v = d_oft[((b * 32 + k) * 16 + ky) * 32 + o];
        float2 w = tw[k];
        re += v.x * w.x - v.y * w.y;
        im += v.x * w.y + v.y * w.x;
    }
    d_V[((b * 64 + h) * 16 + ky) * 32 + o] = make_float2(re * 0.125f, im * 0.125f);
}

// ---------------- inverse C2R over W, *1/8, fused stats(slot1) ----------------
__global__ void invW_kernel() {
    int bh = blockIdx.x; int t = threadIdx.x;   // 256 x 256
    __shared__ float2 Vs[512];
    __shared__ float2 tw[1024];
    __shared__ float sh1[256], sh2[256];
    for (int i = t; i < 512; i += 256) Vs[i] = d_V[bh * 512 + i];
    for (int i = t; i < 1024; i += 256) {
        int ky = i >> 6, w = i & 63; float s, c;
        sincospif((float)(ky * w) * (1.0f / 32.0f), &s, &c);
        tw[i] = make_float2(c, s);
    }
    __syncthreads();
    float ss = 0.f, ss2 = 0.f;
#pragma unroll
    for (int r = 0; r < 8; r++) {
        int oi = t + r * 256; int w = oi >> 5, o = oi & 31;
        float acc = 0.f;
#pragma unroll
        for (int ky = 0; ky < 16; ky++) {
            float2 v = Vs[ky * 32 + o]; float2 tv = tw[ky * 64 + w];
            float term = v.x * tv.x - v.y * tv.y;
            acc += (ky == 0) ? term : 2.0f * term;
        }
        acc *= 0.125f;
        d_x1[bh * 2048 + oi] = acc;
        ss += acc; ss2 += acc * acc;
    }
    sh1[t] = ss; sh2[t] = ss2; __syncthreads();
    for (int o = 128; o > 0; o >>= 1) {
        if (t < o) { sh1[t] += sh1[t + o]; sh2[t] += sh2[t + o]; }
        __syncthreads();
    }
    if (t == 0) {
        float m = sh1[0] * (1.0f / 2048.0f);
        float var = sh2[0] * (1.0f / 2048.0f) - m * m;
        d_stats[512 + bh] = m;
        d_stats[512 + 256 + bh] = rsqrtf(var + 1e-5f);
    }
}

// ---------------- MLP on inorm(x1) -> d_x1b ----------------
__global__ void __launch_bounds__(128) mlp0_kernel(const float* w1, const float* b1,
                                                   const float* w2, const float* b2) {
    int t = threadIdx.x;   // 128
    __shared__ float w1s[2048], w2s[2048], b1s[64], b2s[32];
    for (int i = t; i < 2048; i += 128) { w1s[i] = w1[i]; w2s[i] = w2[i]; }
    if (t < 64) b1s[t] = b1[t];
    if (t < 32) b2s[t] = b2[t];
    __syncthreads();
    int p = blockIdx.x * 128 + t;   // grid 128
    int row = p >> 6;
    float m = d_stats[512 + row], rs = d_stats[512 + 256 + row];
    float x[32];
#pragma unroll
    for (int c = 0; c < 32; c++) x[c] = (d_x1[p * 32 + c] - m) * rs;
    float o[32];
#pragma unroll
    for (int j = 0; j < 32; j++) o[j] = b2s[j];
    for (int k = 0; k < 64; k++) {
        float a = b1s[k];
#pragma unroll
        for (int c = 0; c < 32; c++) a += x[c] * w1s[c * 64 + k];
        a = gelu_f(a);
#pragma unroll
        for (int j = 0; j < 32; j++) o[j] += a * w2s[k * 32 + j];
    }
#pragma unroll
    for (int j = 0; j < 32; j++) d_x1b[p * 32 + j] = o[j];
}

// ---------------- MLP on xn -> d_x2, fused stats(slot2) ----------------
__global__ void __launch_bounds__(128) mlp1_kernel(const float* w1, const float* b1,
                                                   const float* w2, const float* b2) {
    int t = threadIdx.x;   // 128
    __shared__ float w1s[2048], w2s[2048], b1s[64], b2s[32];
    __shared__ float sh1[128], sh2[128];
    for (int i = t; i < 2048; i += 128) { w1s[i] = w1[i]; w2s[i] = w2[i]; }
    if (t < 64) b1s[t] = b1[t];
    if (t < 32) b2s[t] = b2[t];
    __syncthreads();
    int p = blockIdx.x * 128 + t;   // grid 128
    float x[32];
#pragma unroll
    for (int c = 0; c < 32; c++) x[c] = d_xn[p * 32 + c];
    float o[32];
#pragma unroll
    for (int j = 0; j < 32; j++) o[j] = b2s[j];
    for (int k = 0; k < 64; k++) {
        float a = b1s[k];
#pragma unroll
        for (int c = 0; c < 32; c++) a += x[c] * w1s[c * 64 + k];
        a = gelu_f(a);
#pragma unroll
        for (int j = 0; j < 32; j++) o[j] += a * w2s[k * 32 + j];
    }
    float ss = 0.f, ss2 = 0.f;
#pragma unroll
    for (int j = 0; j < 32; j++) {
        d_x2[p * 32 + j] = o[j];
        ss += o[j]; ss2 += o[j] * o[j];
    }
    sh1[t] = ss; sh2[t] = ss2; __syncthreads();
    int half = t & 64;
    int l = t & 63;
    for (int off = 32; off > 0; off >>= 1) {
        if (l < off) { sh1[half + l] += sh1[half + l + off]; sh2[half + l] += sh2[half + l + off]; }
        __syncthreads();
    }
    if (l == 0) {
        int row = blockIdx.x * 2 + (half >> 6);
        float m = sh1[half] * (1.0f / 2048.0f);
        float var = sh2[half] * (1.0f / 2048.0f) - m * m;
        d_stats[1024 + row] = m;
        d_stats[1024 + 256 + row] = rsqrtf(var + 1e-5f);
    }
}

// ---------------- edge hidden h = gelu(attr @ kw1 + kb1), fp16 out ----------------
__global__ void edgehid_kernel(const float* attr, const float* w1, const float* b1) {
    int e0 = blockIdx.x * 64;   // 2048 blocks
    int t = threadIdx.x;        // 256
    __shared__ float at[384], w1s[384], b1s[64];
    for (int i = t; i < 384; i += 256) { at[i] = attr[e0 * 6 + i]; w1s[i] = w1[i]; }
    if (t < 64) b1s[t] = b1[t];
    __syncthreads();
#pragma unroll
    for (int r = 0; r < 16; r++) {
        int i = t + r * 256; int el = i >> 6, k = i & 63;
        float a = b1s[k];
#pragma unroll
        for (int d = 0; d < 6; d++) a += at[el * 6 + d] * w1s[d * 64 + k];
        d_hh[(long long)(e0 + el) * 64 + k] = __float2half_rn(gelu_f(a));
    }
}

// ---------------- g GEMM: [16384,32] @ [32,2048], fp16 linear out ----------------
__global__ void gemm_g_kernel(const float* __restrict__ w2) {
    __shared__ float As[64 * 33];
    __shared__ float Bs[32 * 65];
    int row0 = blockIdx.x * 64;     // grid (256,32)
    int col0 = blockIdx.y * 64;
    int t = threadIdx.x;            // 256
    for (int i = t; i < 2048; i += 256)
        As[(i >> 5) * 33 + (i & 31)] = d_xn[(row0 + (i >> 5)) * 32 + (i & 31)];
    for (int i = t; i < 2048; i += 256) {
        int c = i >> 6, j = i & 63; int col = col0 + j;
        Bs[c * 65 + j] = w2[(col >> 5) * 1024 + c * 32 + (col & 31)];
    }
    __syncthreads();
    int tr = (t >> 4) * 4, tc = (t & 15) * 4;
    float acc[4][4] = {};
#pragma unroll
    for (int c = 0; c < 32; c++) {
        float a0 = As[tr * 33 + c], a1 = As[(tr + 1) * 33 + c],
              a2 = As[(tr + 2) * 33 + c], a3 = As[(tr + 3) * 33 + c];
        float b0 = Bs[c * 65 + tc], b1 = Bs[c * 65 + tc + 1],
              b2 = Bs[c * 65 + tc + 2], b3 = Bs[c * 65 + tc + 3];
        acc[0][0] += a0 * b0; acc[0][1] += a0 * b1; acc[0][2] += a0 * b2; acc[0][3] += a0 * b3;
        acc[1][0] += a1 * b0; acc[1][1] += a1 * b1; acc[1][2] += a1 * b2; acc[1][3] += a1 * b3;
        acc[2][0] += a2 * b0; acc[2][1] += a2 * b1; acc[2][2] += a2 * b2; acc[2][3] += a2 * b3;
        acc[3][0] += a3 * b0; acc[3][1] += a3 * b1; acc[3][2] += a3 * b2; acc[3][3] += a3 * b3;
    }
    __half2* gh2 = (__half2*)d_gh;
#pragma unroll
    for (int i = 0; i < 4; i++) {
        long long base = (long long)(row0 + tr + i) * 2048 + col0 + tc;
        gh2[base >> 1]       = __floats2half2_rn(acc[i][0], acc[i][1]);
        gh2[(base >> 1) + 1] = __floats2half2_rn(acc[i][2], acc[i][3]);
    }
}

// ---------------- per-src msg via mma.m16n8k16; B-frags via ldmatrix.trans ----------------
__global__ void __launch_bounds__(128) edgemsg_kernel(const float* __restrict__ kb2) {
    int node = blockIdx.x;   // 4096
    int t = threadIdx.x;
    int wid = t >> 5, lane = t & 31;   // wid == b
    int s0 = d_offA[node], s1 = d_offA[node + 1];
    if (s0 == s1) return;
    __shared__ __align__(16) __half gsm[4][64 * 40];   // [b][k row][o], pitch 40 halves = 80B
    __shared__ __align__(16) __half hsm[16 * 72];      // [edge][k], pitch 72 halves = 144B
    __shared__ float xsrc[128];
    __shared__ float xbs[128];
    __shared__ int   es[16];
    __shared__ int   dp[16];

    // coalesced load of G (linear) into pitched smem
    {
        const int4* gp = (const int4*)(d_gh + (long long)(wid * NND + node) * 2048);
#pragma unroll
        for (int i = 0; i < 8; i++) {
            int idx = i * 32 + lane;          // 256 int4 per warp
            int4 v = gp[idx];
            int r = idx >> 2, c4 = idx & 3;
            *(int4*)&gsm[wid][r * 40 + c4 * 8] = v;
        }
    }
    xsrc[t] = d_xn[(wid * NND + node) * 32 + lane];
    __syncwarp();

    // build 16 B-fragments with ldmatrix.x4.trans
    uint2 bf[16];
    {
        unsigned gb = smem_u32(&gsm[wid][0]);
        int grp = lane >> 3, rowi = lane & 7;
#pragma unroll
        for (int ks = 0; ks < 4; ks++) {
#pragma unroll
            for (int np = 0; np < 2; np++) {
                unsigned addr = gb + (unsigned)((ks * 16 + (grp & 1) * 8 + rowi) * 80
                                                + (np * 2 + (grp >> 1)) * 16);
                unsigned r0, r1, r2, r3;
                asm volatile("ldmatrix.sync.aligned.m8n8.x4.trans.shared.b16 {%0,%1,%2,%3}, [%4];"
                             : "=r"(r0), "=r"(r1), "=r"(r2), "=r"(r3) : "r"(addr));
                bf[ks * 4 + np * 2 + 0] = make_uint2(r0, r1);
                bf[ks * 4 + np * 2 + 1] = make_uint2(r2, r3);
            }
        }
    }
    // xb[b][o] = sum_c xn[b,node,c]*kb2[c,o]   (warp-local)
    float xb = 0.f;
#pragma unroll
    for (int c = 0; c < 32; c++) xb += xsrc[wid * 32 + c] * kb2[c * 32 + lane];
    xbs[t] = xb;
    __syncwarp();
    float xb0[4], xb1[4];
#pragma unroll
    for (int nt = 0; nt < 4; nt++) {
        int col = nt * 8 + (lane & 3) * 2;
        xb0[nt] = xbs[wid * 32 + col];
        xb1[nt] = xbs[wid * 32 + col + 1];
    }
    int r0 = lane >> 2, r1 = r0 + 8;
    unsigned hbase = smem_u32(hsm);
    __half2* msg2 = (__half2*)d_msg;

    for (int ec = s0; ec < s1; ec += 16) {
        int nch = min(16, s1 - ec);
        __syncthreads();
        if (t < nch) { int e = d_eid[ec + t]; es[t] = e; dp[t] = d_eid[EED + e]; }
        __syncthreads();
        {   // load H tile [16 x 64] halves
            int r = t >> 3, c8 = t & 7;
            int4 hv = make_int4(0, 0, 0, 0);
            if (r < nch) hv = *(const int4*)(d_hh + (long long)es[r] * 64 + c8 * 8);
            *(int4*)(hsm + r * 72 + c8 * 8) = hv;
        }
        __syncthreads();
        float acc[4][4];
#pragma unroll
        for (int nt = 0; nt < 4; nt++) {
            acc[nt][0] = xb0[nt]; acc[nt][1] = xb1[nt];
            acc[nt][2] = xb0[nt]; acc[nt][3] = xb1[nt];
        }
#pragma unroll
        for (int ks = 0; ks < 4; ks++) {
            unsigned a0, a1, a2, a3;
            unsigned addr = hbase + (lane & 15) * 144 + ks * 32 + (lane >> 4) * 16;
            asm volatile("ldmatrix.sync.aligned.m8n8.x4.shared.b16 {%0,%1,%2,%3}, [%4];"
                         : "=r"(a0), "=r"(a1), "=r"(a2), "=r"(a3) : "r"(addr));
#pragma unroll
            for (int nt = 0; nt < 4; nt++) {
                int f = ks * 4 + nt;
                asm volatile(
                    "mma.sync.aligned.m16n8k16.row.col.f32.f16.f16.f32 "
                    "{%0,%1,%2,%3}, {%4,%5,%6,%7}, {%8,%9}, {%0,%1,%2,%3};"
                    : "+f"(acc[nt][0]), "+f"(acc[nt][1]), "+f"(acc[nt][2]), "+f"(acc[nt][3])
                    : "r"(a0), "r"(a1), "r"(a2), "r"(a3), "r"(bf[f].x), "r"(bf[f].y));
            }
        }
#pragma unroll
        for (int nt = 0; nt < 4; nt++) {
            int h2idx = nt * 4 + (lane & 3);   // half2 index within the 16-wide row
            if (r0 < nch)
                msg2[((long long)dp[r0] * 4 + wid) * 16 + h2idx] =
                    __floats2half2_rn(acc[nt][0], acc[nt][1]);
            if (r1 < nch)
                msg2[((long long)dp[r1] * 4 + wid) * 16 + h2idx] =
                    __floats2half2_rn(acc[nt][2], acc[nt][3]);
        }
    }
}

// ---------------- dst gather (contiguous, fp16) + root + bias + combine + gelu ----------------
__global__ void __launch_bounds__(128) final_kernel(const float* __restrict__ root,
                                                    const float* __restrict__ gbias,
                                                    float* __restrict__ out) {
    int n = blockIdx.x;   // 4096
    int t = threadIdx.x; int b = t >> 5, o = t & 31;
    __shared__ float roots[1024];
    __shared__ float xs[128];
    for (int i = t; i < 1024; i += 128) roots[i] = root[i];
    xs[t] = d_xn[(b * NND + n) * 32 + o];
    __syncthreads();
    float acc = gbias[o];
#pragma unroll
    for (int c = 0; c < 32; c++) acc += xs[b * 32 + c] * roots[c * 32 + o];
    int s0 = d_offA[(NND + 1) + n], s1 = d_offA[(NND + 1) + n + 1];
    const __half* mp = d_msg;
    int i = s0;
    float a0 = 0.f, a1 = 0.f, a2 = 0.f, a3 = 0.f;
    for (; i + 4 <= s1; i += 4) {
        a0 += __half2float(mp[((long long)i * 4 + b) * 32 + o]);
        a1 += __half2float(mp[((long long)(i + 1) * 4 + b) * 32 + o]);
        a2 += __half2float(mp[((long long)(i + 2) * 4 + b) * 32 + o]);
        a3 += __half2float(mp[((long long)(i + 3) * 4 + b) * 32 + o]);
    }
    for (; i < s1; i++) a0 += __half2float(mp[((long long)i * 4 + b) * 32 + o]);
    acc += (a0 + a1) + (a2 + a3);
    int p = b * NND + n; int row = p >> 6;
    float x2v = (d_x2[(long long)p * 32 + o] - d_stats[1024 + row]) * d_stats[1024 + 256 + row];
    float s = d_x1b[(long long)p * 32 + o] + x2v + acc;
    out[(long long)p * 32 + o] = gelu_f(s);
}

// ---------------- launch (fork/join stream-parallel graph) ----------------
extern "C" void kernel_launch(void* const* d_in, const int* in_sizes, int n_in,
                              void* d_out, int out_size) {
    const float* nodes  = (const float*)d_in[0];
    const void*  eidx   = d_in[1];
    const float* eattr  = (const float*)d_in[2];
    const float* w1re   = (const float*)d_in[3];
    const float* w1im   = (const float*)d_in[4];
    const float* w2re   = (const float*)d_in[5];
    const float* w2im   = (const float*)d_in[6];
    const float* mlp_w1 = (const float*)d_in[7];
    const float* mlp_b1 = (const float*)d_in[8];
    const float* mlp_w2 = (const float*)d_in[9];
    const float* mlp_b2 = (const float*)d_in[10];
    const float* wm_w1  = (const float*)d_in[11];
    const float* wm_b1  = (const float*)d_in[12];
    const float* wm_w2  = (const float*)d_in[13];
    const float* wm_b2  = (const float*)d_in[14];
    const float* kw1    = (const float*)d_in[15];
    const float* kb1    = (const float*)d_in[16];
    const float* kw2    = (const float*)d_in[17];
    const float* kb2    = (const float*)d_in[18];
    const float* root   = (const float*)d_in[19];
    const float* gbias  = (const float*)d_in[20];
    float* out = (float*)d_out;

    static cudaStream_t sA = nullptr, sB = nullptr;
    static cudaEvent_t evRoot, evN, evA, evB, evM;
    if (sA == nullptr) {
        cudaStreamCreateWithFlags(&sA, cudaStreamNonBlocking);
        cudaStreamCreateWithFlags(&sB, cudaStreamNonBlocking);
        cudaEventCreateWithFlags(&evRoot, cudaEventDisableTiming);
        cudaEventCreateWithFlags(&evN, cudaEventDisableTiming);
        cudaEventCreateWithFlags(&evA, cudaEventDisableTiming);
        cudaEventCreateWithFlags(&evB, cudaEventDisableTiming);
        cudaEventCreateWithFlags(&evM, cudaEventDisableTiming);
    }

    // fork point
    cudaEventRecord(evRoot, 0);
    cudaStreamWaitEvent(sA, evRoot, 0);
    cudaStreamWaitEvent(sB, evRoot, 0);

    // stream A: CSR build
    initcsr_kernel<<<8, 1024, 0, sA>>>(eidx);
    convhist_kernel<<<512, 256, 0, sA>>>(eidx);
    scan_kernel<<<2, 1024, 0, sA>>>();
    fill_kernel<<<512, 256, 0, sA>>>();
    cudaEventRecord(evA, sA);

    // stream B: edge hidden (independent of x)
    edgehid_kernel<<<2048, 256, 0, sB>>>(eattr, kw1, kb1);

    // stream 0: fused normalize of input
    statsnorm_kernel<<<256, 256>>>(nodes);
    cudaEventRecord(evN, 0);

    // stream A: pointwise MLP branch (needs only xn; sA idle after CSR)
    cudaStreamWaitEvent(sA, evN, 0);
    mlp1_kernel<<<128, 128, 0, sA>>>(wm_w1, wm_b1, wm_w2, wm_b2);   // + stats slot2
    cudaEventRecord(evM, sA);

    // stream B: g GEMM (needs norm), then edge msg (needs CSR + h + g)
    cudaStreamWaitEvent(sB, evN, 0);
    {
        dim3 g(256, 32);
        gemm_g_kernel<<<g, 256, 0, sB>>>(kw2);
    }
    cudaStreamWaitEvent(sB, evA, 0);
    edgemsg_kernel<<<4096, 128, 0, sB>>>(kb2);
    cudaEventRecord(evB, sB);

    // stream 0: spectral branch
    fwdW_kernel<<<256, 256>>>();
    fwdH_kernel<<<128, 512>>>();
    modemix_kernel<<<512, 128>>>(w1re, w1im, w2re, w2im);
    invH_kernel<<<256, 512>>>();
    invW_kernel<<<256, 256>>>();          // + stats slot1
    mlp0_kernel<<<128, 128>>>(mlp_w1, mlp_b1, mlp_w2, mlp_b2);

    // join: final combine
    cudaStreamWaitEvent(0, evB, 0);
    cudaStreamWaitEvent(0, evM, 0);
    final_kernel<<<4096, 128>>>(root, gbias, out);
}

// round 14
// speedup vs baseline: 1.9916x; 1.2788x over previous
#include <cuda_runtime.h>
#include <cuda_fp16.h>
#include <math.h>

#define BB 4
#define NND 4096
#define EED 131072

// ---------------- scratch ----------------
__device__ float  d_stats[3 * 512];
__device__ float  d_xn  [BB * NND * 32];
__device__ __half d_xnh [BB * NND * 32];
__device__ __half d_w2h [32 * 2048];               // [c][k*32+o] fp16
__device__ float2 d_T   [BB * 64 * 16 * 32];
__device__ float2 d_Xft [BB * 32 * 16 * 32];
__device__ float2 d_oft [BB * 32 * 16 * 32];
__device__ float2 d_V   [BB * 64 * 16 * 32];
__device__ float  d_x1  [BB * NND * 32];
__device__ float  d_x1b [BB * NND * 32];
__device__ float  d_x2  [BB * NND * 32];
__device__ __half d_hh  [(long long)EED * 64];
__device__ __half d_gh  [(long long)BB * NND * 64 * 32];   // linear [row][k*32+o]
__device__ __half d_msg [(long long)EED * BB * 32];        // fp16, indexed by dst-CSR position
__device__ int    d_esrc[EED];
__device__ int    d_edst[EED];
__device__ int    d_is64;
__device__ int    d_cnt [2 * NND];
__device__ int    d_offA[2 * (NND + 1)];
__device__ int    d_cur [2 * NND];
__device__ int    d_eid [2 * EED];   // [0:E) src-CSR edge ids; [E:2E) dstpos per edge

__device__ __forceinline__ float gelu_f(float x) {
    return 0.5f * x * (1.0f + erff(x * 0.70710678118654752f));
}
__device__ __forceinline__ unsigned smem_u32(const void* p) {
    return (unsigned)__cvta_generic_to_shared(p);
}

// ---------------- init: zero cnt/cur + probe edge dtype ----------------
__global__ void initcsr_kernel(const void* ei) {
    int i = blockIdx.x * 1024 + threadIdx.x;   // 8x1024
    d_cnt[i] = 0; d_cur[i] = 0;
    if (blockIdx.x == 0 && threadIdx.x < 256) {
        const int* w = (const int*)ei;
        int t = threadIdx.x;
        int nz = 0;
        for (int k = t; k < 1024; k += 256) nz |= w[2 * k + 1];
        __shared__ int s;
        if (t == 0) s = 0;
        __syncthreads();
        if (nz) atomicOr(&s, 1);
        __syncthreads();
        if (t == 0) d_is64 = (s == 0);   // all-zero odd words => int64
    }
}

// ---------------- convert + histogram ----------------
__global__ void convhist_kernel(const void* ei) {
    int e = blockIdx.x * 256 + threadIdx.x;  // 512x256
    int s, d;
    if (d_is64) {
        const long long* p = (const long long*)ei;
        s = (int)p[e]; d = (int)p[EED + e];
    } else {
        const int* p = (const int*)ei;
        s = p[e]; d = p[EED + e];
    }
    d_esrc[e] = s; d_edst[e] = d;
    atomicAdd(&d_cnt[s], 1);
    atomicAdd(&d_cnt[NND + d], 1);
}

__global__ void scan_kernel() {
    int a = blockIdx.x;   // 0=src, 1=dst
    int t = threadIdx.x;  // 1024
    const int* cnt = d_cnt + a * NND;
    int* off = d_offA + a * (NND + 1);
    int v0 = cnt[t * 4], v1 = cnt[t * 4 + 1], v2 = cnt[t * 4 + 2], v3 = cnt[t * 4 + 3];
    int s = v0 + v1 + v2 + v3;
    __shared__ int sh[1024];
    sh[t] = s; __syncthreads();
    for (int o1 = 1; o1 < 1024; o1 <<= 1) {
        int v = (t >= o1) ? sh[t - o1] : 0;
        __syncthreads();
        sh[t] += v;
        __syncthreads();
    }
    int excl = sh[t] - s;
    off[t * 4] = excl; off[t * 4 + 1] = excl + v0;
    off[t * 4 + 2] = excl + v0 + v1; off[t * 4 + 3] = excl + v0 + v1 + v2;
    if (t == 1023) off[NND] = sh[1023];
}

__global__ void fill_kernel() {
    int e = blockIdx.x * 256 + threadIdx.x;    // 512x256
    int s = d_esrc[e], d2 = d_edst[e];
    int p = atomicAdd(&d_cur[s], 1);
    d_eid[d_offA[s] + p] = e;
    int q = atomicAdd(&d_cur[NND + d2], 1);
    d_eid[EED + e] = d_offA[(NND + 1) + d2] + q;   // dstpos of edge e
}

// ---------------- fused instance-norm: stats + normalize, emits fp32 + fp16 ----------------
__global__ void statsnorm_kernel(const float* __restrict__ nodes) {
    int row = blockIdx.x;            // 256
    int t = threadIdx.x;             // 256
    __shared__ float xs[2048];
    __shared__ float sh1[256], sh2[256];
    __shared__ float mr[2];
    const float* p = nodes + row * 2048;
    float s = 0.f, s2 = 0.f;
#pragma unroll
    for (int i = 0; i < 8; i++) {
        float v = p[t + i * 256];
        xs[t + i * 256] = v;
        s += v; s2 += v * v;
    }
    sh1[t] = s; sh2[t] = s2; __syncthreads();
    for (int o = 128; o > 0; o >>= 1) {
        if (t < o) { sh1[t] += sh1[t + o]; sh2[t] += sh2[t + o]; }
        __syncthreads();
    }
    if (t == 0) {
        float m = sh1[0] * (1.0f / 2048.0f);
        float var = sh2[0] * (1.0f / 2048.0f) - m * m;
        mr[0] = m; mr[1] = rsqrtf(var + 1e-5f);
    }
    __syncthreads();
    float m = mr[0], rs = mr[1];
#pragma unroll
    for (int i = 0; i < 8; i++) {
        float v = (xs[t + i * 256] - m) * rs;
        d_xn [row * 2048 + t + i * 256] = v;
        d_xnh[row * 2048 + t + i * 256] = __float2half_rn(v);
    }
}

// ---------------- w2 transpose+convert: d_w2h[c][k*32+o] = kw2[k][c*32+o] ----------------
__global__ void w2conv_kernel(const float* __restrict__ kw2) {
    int i = blockIdx.x * 256 + threadIdx.x;   // 256x256 = 65536
    int c = i >> 11, col = i & 2047;
    d_w2h[i] = __float2half_rn(kw2[(col >> 5) * 1024 + c * 32 + (col & 31)]);
}

// ---------------- forward DFT over W (ky 0..15) ----------------
__global__ void fwdW_kernel() {
    int bh = blockIdx.x;            // 256
    int t = threadIdx.x;            // 256
    __shared__ float  xs[2048];
    __shared__ float2 tw[1024];
    for (int i = t; i < 2048; i += 256) xs[i] = d_xn[bh * 2048 + i];
    for (int i = t; i < 1024; i += 256) {
        int ky = i >> 6, w = i & 63; float s, c;
        sincospif(-(float)(ky * w) * (1.0f / 32.0f), &s, &c);
        tw[i] = make_float2(c, s);
    }
    __syncthreads();
#pragma unroll
    for (int r = 0; r < 2; r++) {
        int oi = t + r * 256; int ky = oi >> 5, c = oi & 31;
        float re = 0.f, im = 0.f;
#pragma unroll 8
        for (int w = 0; w < 64; w++) {
            float xv = xs[w * 32 + c]; float2 tv = tw[ky * 64 + w];
            re += xv * tv.x; im += xv * tv.y;
        }
        d_T[(bh * 16 + ky) * 32 + c] = make_float2(re, im);
    }
}

// ---------------- forward DFT over H (kx 0..15, 48..63), *1/64 ----------------
__global__ void fwdH_kernel() {
    int b = blockIdx.x >> 5, kxi = blockIdx.x & 31;   // 128 blocks
    int kx = (kxi < 16) ? kxi : kxi + 32;
    int t = threadIdx.x;                               // 512
    __shared__ float2 tw[64];
    if (t < 64) { float s, c; sincospif(-(float)(kx * t) * (1.0f / 32.0f), &s, &c); tw[t] = make_float2(c, s); }
    __syncthreads();
    int ky = t >> 5, c = t & 31;
    float re = 0.f, im = 0.f;
#pragma unroll 4
    for (int h = 0; h < 64; h++) {
        float2 v = d_T[((b * 64 + h) * 16 + ky) * 32 + c];
        float2 w = tw[h];
        re += v.x * w.x - v.y * w.y;
        im += v.x * w.y + v.y * w.x;
    }
    d_Xft[((b * 32 + kxi) * 16 + ky) * 32 + c] = make_float2(re * (1.0f / 64.0f), im * (1.0f / 64.0f));
}

// ---------------- complex channel mix per (kx,ky) ----------------
__global__ void modemix_kernel(const float* w1re, const float* w1im,
                               const float* w2re, const float* w2im) {
    int kxi = blockIdx.x >> 4, ky = blockIdx.x & 15;   // 512 blocks
    int xm = (kxi < 16) ? kxi : kxi - 16;
    const float* wre = (kxi < 16) ? w1re : w2re;
    const float* wim = (kxi < 16) ? w1im : w2im;
    int t = threadIdx.x;                                // 128
    __shared__ float wr[1024], wi[1024];
    __shared__ float2 Xs[128];
    for (int i = t; i < 1024; i += 128) {
        int off = i * 256 + xm * 16 + ky;
        wr[i] = wre[off]; wi[i] = wim[off];
    }
    { int b = t >> 5, c = t & 31; Xs[t] = d_Xft[((b * 32 + kxi) * 16 + ky) * 32 + c]; }
    __syncthreads();
    int b = t >> 5, o = t & 31;
    float re = 0.f, im = 0.f;
#pragma unroll
    for (int i = 0; i < 32; i++) {
        float2 xv = Xs[b * 32 + i];
        float wrv = wr[i * 32 + o], wiv = wi[i * 32 + o];
        re += xv.x * wrv - xv.y * wiv;
        im += xv.x * wiv + xv.y * wrv;
    }
    d_oft[((b * 32 + kxi) * 16 + ky) * 32 + o] = make_float2(re, im);
}

// ---------------- inverse DFT over H, *1/8 ----------------
__global__ void invH_kernel() {
    int b = blockIdx.x >> 6, h = blockIdx.x & 63;   // 256 blocks
    int t = threadIdx.x;                             // 512
    __shared__ float2 tw[32];
    if (t < 32) {
        int kx = (t < 16) ? t : t + 32; float s, c;
        sincospif((float)(kx * h) * (1.0f / 32.0f), &s, &c);
        tw[t] = make_float2(c, s);
    }
    __syncthreads();
    int ky = t >> 5, o = t & 31;
    float re = 0.f, im = 0.f;
#pragma unroll 4
    for (int k = 0; k < 32; k++) {
        float2 v = d_oft[((b * 32 + k) * 16 + ky) * 32 + o];
        float2 w = tw[k];
        re += v.x * w.x - v.y * w.y;
        im += v.x * w.y + v.y * w.x;
    }
    d_V[((b * 64 + h) * 16 + ky) * 32 + o] = make_float2(re * 0.125f, im * 0.125f);
}

// ---------------- inverse C2R over W, *1/8, fused stats(slot1) ----------------
__global__ void invW_kernel() {
    int bh = blockIdx.x; int t = threadIdx.x;   // 256 x 256
    __shared__ float2 Vs[512];
    __shared__ float2 tw[1024];
    __shared__ float sh1[256], sh2[256];
    for (int i = t; i < 512; i += 256) Vs[i] = d_V[bh * 512 + i];
    for (int i = t; i < 1024; i += 256) {
        int ky = i >> 6, w = i & 63; float s, c;
        sincospif((float)(ky * w) * (1.0f / 32.0f), &s, &c);
        tw[i] = make_float2(c, s);
    }
    __syncthreads();
    float ss = 0.f, ss2 = 0.f;
#pragma unroll
    for (int r = 0; r < 8; r++) {
        int oi = t + r * 256; int w = oi >> 5, o = oi & 31;
        float acc = 0.f;
#pragma unroll
        for (int ky = 0; ky < 16; ky++) {
            float2 v = Vs[ky * 32 + o]; float2 tv = tw[ky * 64 + w];
            float term = v.x * tv.x - v.y * tv.y;
            acc += (ky == 0) ? term : 2.0f * term;
        }
        acc *= 0.125f;
        d_x1[bh * 2048 + oi] = acc;
        ss += acc; ss2 += acc * acc;
    }
    sh1[t] = ss; sh2[t] = ss2; __syncthreads();
    for (int o = 128; o > 0; o >>= 1) {
        if (t < o) { sh1[t] += sh1[t + o]; sh2[t] += sh2[t + o]; }
        __syncthreads();
    }
    if (t == 0) {
        float m = sh1[0] * (1.0f / 2048.0f);
        float var = sh2[0] * (1.0f / 2048.0f) - m * m;
        d_stats[512 + bh] = m;
        d_stats[512 + 256 + bh] = rsqrtf(var + 1e-5f);
    }
}

// ---------------- MLP on inorm(x1) -> d_x1b ----------------
__global__ void __launch_bounds__(128) mlp0_kernel(const float* w1, const float* b1,
                                                   const float* w2, const float* b2) {
    int t = threadIdx.x;   // 128
    __shared__ float w1s[2048], w2s[2048], b1s[64], b2s[32];
    for (int i = t; i < 2048; i += 128) { w1s[i] = w1[i]; w2s[i] = w2[i]; }
    if (t < 64) b1s[t] = b1[t];
    if (t < 32) b2s[t] = b2[t];
    __syncthreads();
    int p = blockIdx.x * 128 + t;   // grid 128
    int row = p >> 6;
    float m = d_stats[512 + row], rs = d_stats[512 + 256 + row];
    float x[32];
#pragma unroll
    for (int c = 0; c < 32; c++) x[c] = (d_x1[p * 32 + c] - m) * rs;
    float o[32];
#pragma unroll
    for (int j = 0; j < 32; j++) o[j] = b2s[j];
    for (int k = 0; k < 64; k++) {
        float a = b1s[k];
#pragma unroll
        for (int c = 0; c < 32; c++) a += x[c] * w1s[c * 64 + k];
        a = gelu_f(a);
#pragma unroll
        for (int j = 0; j < 32; j++) o[j] += a * w2s[k * 32 + j];
    }
#pragma unroll
    for (int j = 0; j < 32; j++) d_x1b[p * 32 + j] = o[j];
}

// ---------------- MLP on xn -> d_x2, fused stats(slot2) ----------------
__global__ void __launch_bounds__(128) mlp1_kernel(const float* w1, const float* b1,
                                                   const float* w2, const float* b2) {
    int t = threadIdx.x;   // 128
    __shared__ float w1s[2048], w2s[2048], b1s[64], b2s[32];
    __shared__ float sh1[128], sh2[128];
    for (int i = t; i < 2048; i += 128) { w1s[i] = w1[i]; w2s[i] = w2[i]; }
    if (t < 64) b1s[t] = b1[t];
    if (t < 32) b2s[t] = b2[t];
    __syncthreads();
    int p = blockIdx.x * 128 + t;   // grid 128
    float x[32];
#pragma unroll
    for (int c = 0; c < 32; c++) x[c] = d_xn[p * 32 + c];
    float o[32];
#pragma unroll
    for (int j = 0; j < 32; j++) o[j] = b2s[j];
    for (int k = 0; k < 64; k++) {
        float a = b1s[k];
#pragma unroll
        for (int c = 0; c < 32; c++) a += x[c] * w1s[c * 64 + k];
        a = gelu_f(a);
#pragma unroll
        for (int j = 0; j < 32; j++) o[j] += a * w2s[k * 32 + j];
    }
    float ss = 0.f, ss2 = 0.f;
#pragma unroll
    for (int j = 0; j < 32; j++) {
        d_x2[p * 32 + j] = o[j];
        ss += o[j]; ss2 += o[j] * o[j];
    }
    sh1[t] = ss; sh2[t] = ss2; __syncthreads();
    int half = t & 64;
    int l = t & 63;
    for (int off = 32; off > 0; off >>= 1) {
        if (l < off) { sh1[half + l] += sh1[half + l + off]; sh2[half + l] += sh2[half + l + off]; }
        __syncthreads();
    }
    if (l == 0) {
        int row = blockIdx.x * 2 + (half >> 6);
        float m = sh1[half] * (1.0f / 2048.0f);
        float var = sh2[half] * (1.0f / 2048.0f) - m * m;
        d_stats[1024 + row] = m;
        d_stats[1024 + 256 + row] = rsqrtf(var + 1e-5f);
    }
}

// ---------------- edge hidden h = gelu(attr @ kw1 + kb1), fp16 out ----------------
__global__ void edgehid_kernel(const float* attr, const float* w1, const float* b1) {
    int e0 = blockIdx.x * 64;   // 2048 blocks
    int t = threadIdx.x;        // 256
    __shared__ float at[384], w1s[384], b1s[64];
    for (int i = t; i < 384; i += 256) { at[i] = attr[e0 * 6 + i]; w1s[i] = w1[i]; }
    if (t < 64) b1s[t] = b1[t];
    __syncthreads();
#pragma unroll
    for (int r = 0; r < 16; r++) {
        int i = t + r * 256; int el = i >> 6, k = i & 63;
        float a = b1s[k];
#pragma unroll
        for (int d = 0; d < 6; d++) a += at[el * 6 + d] * w1s[d * 64 + k];
        d_hh[(long long)(e0 + el) * 64 + k] = __float2half_rn(gelu_f(a));
    }
}

// ---------------- tensor-core g GEMM: d_gh = xnh[16384,32] @ w2h[32,2048] ----------------
__global__ void __launch_bounds__(256) gemm_gh_kernel() {
    int bm = blockIdx.x;    // 128 row blocks (128 rows each)
    int bn = blockIdx.y;    // 16 col blocks (128 cols each)
    int t = threadIdx.x;    // 256 = 8 warps
    int w = t >> 5, lane = t & 31;
    // aliased smem: phase1 A(10240B)+B(8704B); phase2 C(32768B)
    __shared__ __align__(16) char smemraw[32768];
    __half* Ah = (__half*)smemraw;              // [128][40] pitch 80B
    __half* Bh = (__half*)(smemraw + 10240);    // [32][136] pitch 272B
    __half* Cs = (__half*)smemraw;              // [128][128] (after barrier)

    // load A tile: 128 rows x 32 halves (512 int4)
    {
        const int4* ap = (const int4*)(d_xnh + (long long)bm * 128 * 32);
        for (int i = t; i < 512; i += 256) {
            int4 v = ap[i];
            int r = i >> 2, c4 = i & 3;
            *(int4*)&Ah[r * 40 + c4 * 8] = v;
        }
    }
    // load B tile: 32 rows x 128 halves
    {
        for (int i = t; i < 512; i += 256) {
            int r = i >> 4, c8 = i & 15;
            int4 v = *(const int4*)(d_w2h + r * 2048 + bn * 128 + c8 * 8);
            *(int4*)&Bh[r * 136 + c8 * 8] = v;
        }
    }
    __syncthreads();

    float acc[16][4];
#pragma unroll
    for (int nt = 0; nt < 16; nt++) {
        acc[nt][0] = 0.f; acc[nt][1] = 0.f; acc[nt][2] = 0.f; acc[nt][3] = 0.f;
    }
    unsigned abase = smem_u32(Ah) + w * 16 * 80;
    unsigned bbase = smem_u32(Bh);
    int grp = lane >> 3, rowi = lane & 7;
#pragma unroll
    for (int ks = 0; ks < 2; ks++) {
        unsigned a0, a1, a2, a3;
        unsigned aaddr = abase + (lane & 15) * 80 + ks * 32 + (lane >> 4) * 16;
        asm volatile("ldmatrix.sync.aligned.m8n8.x4.shared.b16 {%0,%1,%2,%3}, [%4];"
                     : "=r"(a0), "=r"(a1), "=r"(a2), "=r"(a3) : "r"(aaddr));
#pragma unroll
        for (int np = 0; np < 8; np++) {
            unsigned baddr = bbase + (unsigned)((ks * 16 + (grp & 1) * 8 + rowi) * 272
                                                + (np * 2 + (grp >> 1)) * 16);
            unsigned r0, r1, r2, r3;
            asm volatile("ldmatrix.sync.aligned.m8n8.x4.trans.shared.b16 {%0,%1,%2,%3}, [%4];"
                         : "=r"(r0), "=r"(r1), "=r"(r2), "=r"(r3) : "r"(baddr));
            asm volatile(
                "mma.sync.aligned.m16n8k16.row.col.f32.f16.f16.f32 "
                "{%0,%1,%2,%3}, {%4,%5,%6,%7}, {%8,%9}, {%0,%1,%2,%3};"
                : "+f"(acc[np * 2][0]), "+f"(acc[np * 2][1]),
                  "+f"(acc[np * 2][2]), "+f"(acc[np * 2][3])
                : "r"(a0), "r"(a1), "r"(a2), "r"(a3), "r"(r0), "r"(r1));
            asm volatile(
                "mma.sync.aligned.m16n8k16.row.col.f32.f16.f16.f32 "
                "{%0,%1,%2,%3}, {%4,%5,%6,%7}, {%8,%9}, {%0,%1,%2,%3};"
                : "+f"(acc[np * 2 + 1][0]), "+f"(acc[np * 2 + 1][1]),
                  "+f"(acc[np * 2 + 1][2]), "+f"(acc[np * 2 + 1][3])
                : "r"(a0), "r"(a1), "r"(a2), "r"(a3), "r"(r2), "r"(r3));
        }
    }
    __syncthreads();   // A/B no longer needed; reuse as C stage
    {
        int r0 = lane >> 2;
#pragma unroll
        for (int nt = 0; nt < 16; nt++) {
            int col = nt * 8 + (lane & 3) * 2;
            *(__half2*)&Cs[(w * 16 + r0) * 128 + col] =
                __floats2half2_rn(acc[nt][0], acc[nt][1]);
            *(__half2*)&Cs[(w * 16 + r0 + 8) * 128 + col] =
                __floats2half2_rn(acc[nt][2], acc[nt][3]);
        }
    }
    __syncthreads();
    // coalesced store: 128 rows x 16 int4 (256B) each
    {
        __half* gp = d_gh + (long long)bm * 128 * 2048 + bn * 128;
        for (int i = t; i < 2048; i += 256) {
            int r = i >> 4, c8 = i & 15;
            *(int4*)(gp + (long long)r * 2048 + c8 * 8) = *(int4*)&Cs[r * 128 + c8 * 8];
        }
    }
}

// ---------------- per-src msg via mma.m16n8k16; B-frags via ldmatrix.trans ----------------
__global__ void __launch_bounds__(128) edgemsg_kernel(const float* __restrict__ kb2) {
    int node = blockIdx.x;   // 4096
    int t = threadIdx.x;
    int wid = t >> 5, lane = t & 31;   // wid == b
    int s0 = d_offA[node], s1 = d_offA[node + 1];
    if (s0 == s1) return;
    __shared__ __align__(16) __half gsm[4][64 * 40];   // [b][k row][o], pitch 80B
    __shared__ __align__(16) __half hsm[16 * 72];      // [edge][k], pitch 144B
    __shared__ float xsrc[128];
    __shared__ float xbs[128];
    __shared__ int   es[16];
    __shared__ int   dp[16];

    {
        const int4* gp = (const int4*)(d_gh + (long long)(wid * NND + node) * 2048);
#pragma unroll
        for (int i = 0; i < 8; i++) {
            int idx = i * 32 + lane;
            int4 v = gp[idx];
            int r = idx >> 2, c4 = idx & 3;
            *(int4*)&gsm[wid][r * 40 + c4 * 8] = v;
        }
    }
    xsrc[t] = d_xn[(wid * NND + node) * 32 + lane];
    __syncwarp();

    uint2 bf[16];
    {
        unsigned gb = smem_u32(&gsm[wid][0]);
        int grp = lane >> 3, rowi = lane & 7;
#pragma unroll
        for (int ks = 0; ks < 4; ks++) {
#pragma unroll
            for (int np = 0; np < 2; np++) {
                unsigned addr = gb + (unsigned)((ks * 16 + (grp & 1) * 8 + rowi) * 80
                                                + (np * 2 + (grp >> 1)) * 16);
                unsigned r0, r1, r2, r3;
                asm volatile("ldmatrix.sync.aligned.m8n8.x4.trans.shared.b16 {%0,%1,%2,%3}, [%4];"
                             : "=r"(r0), "=r"(r1), "=r"(r2), "=r"(r3) : "r"(addr));
                bf[ks * 4 + np * 2 + 0] = make_uint2(r0, r1);
                bf[ks * 4 + np * 2 + 1] = make_uint2(r2, r3);
            }
        }
    }
    float xb = 0.f;
#pragma unroll
    for (int c = 0; c < 32; c++) xb += xsrc[wid * 32 + c] * kb2[c * 32 + lane];
    xbs[t] = xb;
    __syncwarp();
    float xb0[4], xb1[4];
#pragma unroll
    for (int nt = 0; nt < 4; nt++) {
        int col = nt * 8 + (lane & 3) * 2;
        xb0[nt] = xbs[wid * 32 + col];
        xb1[nt] = xbs[wid * 32 + col + 1];
    }
    int r0 = lane >> 2, r1 = r0 + 8;
    unsigned hbase = smem_u32(hsm);
    __half2* msg2 = (__half2*)d_msg;

    for (int ec = s0; ec < s1; ec += 16) {
        int nch = min(16, s1 - ec);
        __syncthreads();
        if (t < nch) { int e = d_eid[ec + t]; es[t] = e; dp[t] = d_eid[EED + e]; }
        __syncthreads();
        {
            int r = t >> 3, c8 = t & 7;
            int4 hv = make_int4(0, 0, 0, 0);
            if (r < nch) hv = *(const int4*)(d_hh + (long long)es[r] * 64 + c8 * 8);
            *(int4*)(hsm + r * 72 + c8 * 8) = hv;
        }
        __syncthreads();
        float acc[4][4];
#pragma unroll
        for (int nt = 0; nt < 4; nt++) {
            acc[nt][0] = xb0[nt]; acc[nt][1] = xb1[nt];
            acc[nt][2] = xb0[nt]; acc[nt][3] = xb1[nt];
        }
#pragma unroll
        for (int ks = 0; ks < 4; ks++) {
            unsigned a0, a1, a2, a3;
            unsigned addr = hbase + (lane & 15) * 144 + ks * 32 + (lane >> 4) * 16;
            asm volatile("ldmatrix.sync.aligned.m8n8.x4.shared.b16 {%0,%1,%2,%3}, [%4];"
                         : "=r"(a0), "=r"(a1), "=r"(a2), "=r"(a3) : "r"(addr));
#pragma unroll
            for (int nt = 0; nt < 4; nt++) {
                int f = ks * 4 + nt;
                asm volatile(
                    "mma.sync.aligned.m16n8k16.row.col.f32.f16.f16.f32 "
                    "{%0,%1,%2,%3}, {%4,%5,%6,%7}, {%8,%9}, {%0,%1,%2,%3};"
                    : "+f"(acc[nt][0]), "+f"(acc[nt][1]), "+f"(acc[nt][2]), "+f"(acc[nt][3])
                    : "r"(a0), "r"(a1), "r"(a2), "r"(a3), "r"(bf[f].x), "r"(bf[f].y));
            }
        }
#pragma unroll
        for (int nt = 0; nt < 4; nt++) {
            int h2idx = nt * 4 + (lane & 3);
            if (r0 < nch)
                msg2[((long long)dp[r0] * 4 + wid) * 16 + h2idx] =
                    __floats2half2_rn(acc[nt][0], acc[nt][1]);
            if (r1 < nch)
                msg2[((long long)dp[r1] * 4 + wid) * 16 + h2idx] =
                    __floats2half2_rn(acc[nt][2], acc[nt][3]);
        }
    }
}

// ---------------- dst gather (contiguous, fp16) + root + bias + combine + gelu ----------------
__global__ void __launch_bounds__(128) final_kernel(const float* __restrict__ root,
                                                    const float* __restrict__ gbias,
                                                    float* __restrict__ out) {
    int n = blockIdx.x;   // 4096
    int t = threadIdx.x; int b = t >> 5, o = t & 31;
    __shared__ float roots[1024];
    __shared__ float xs[128];
    for (int i = t; i < 1024; i += 128) roots[i] = root[i];
    xs[t] = d_xn[(b * NND + n) * 32 + o];
    __syncthreads();
    float acc = gbias[o];
#pragma unroll
    for (int c = 0; c < 32; c++) acc += xs[b * 32 + c] * roots[c * 32 + o];
    int s0 = d_offA[(NND + 1) + n], s1 = d_offA[(NND + 1) + n + 1];
    const __half* mp = d_msg;
    int i = s0;
    float a0 = 0.f, a1 = 0.f, a2 = 0.f, a3 = 0.f;
    for (; i + 4 <= s1; i += 4) {
        a0 += __half2float(mp[((long long)i * 4 + b) * 32 + o]);
        a1 += __half2float(mp[((long long)(i + 1) * 4 + b) * 32 + o]);
        a2 += __half2float(mp[((long long)(i + 2) * 4 + b) * 32 + o]);
        a3 += __half2float(mp[((long long)(i + 3) * 4 + b) * 32 + o]);
    }
    for (; i < s1; i++) a0 += __half2float(mp[((long long)i * 4 + b) * 32 + o]);
    acc += (a0 + a1) + (a2 + a3);
    int p = b * NND + n; int row = p >> 6;
    float x2v = (d_x2[(long long)p * 32 + o] - d_stats[1024 + row]) * d_stats[1024 + 256 + row];
    float s = d_x1b[(long long)p * 32 + o] + x2v + acc;
    out[(long long)p * 32 + o] = gelu_f(s);
}

// ---------------- launch (fork/join stream-parallel graph) ----------------
extern "C" void kernel_launch(void* const* d_in, const int* in_sizes, int n_in,
                              void* d_out, int out_size) {
    const float* nodes  = (const float*)d_in[0];
    const void*  eidx   = d_in[1];
    const float* eattr  = (const float*)d_in[2];
    const float* w1re   = (const float*)d_in[3];
    const float* w1im   = (const float*)d_in[4];
    const float* w2re   = (const float*)d_in[5];
    const float* w2im   = (const float*)d_in[6];
    const float* mlp_w1 = (const float*)d_in[7];
    const float* mlp_b1 = (const float*)d_in[8];
    const float* mlp_w2 = (const float*)d_in[9];
    const float* mlp_b2 = (const float*)d_in[10];
    const float* wm_w1  = (const float*)d_in[11];
    const float* wm_b1  = (const float*)d_in[12];
    const float* wm_w2  = (const float*)d_in[13];
    const float* wm_b2  = (const float*)d_in[14];
    const float* kw1    = (const float*)d_in[15];
    const float* kb1    = (const float*)d_in[16];
    const float* kw2    = (const float*)d_in[17];
    const float* kb2    = (const float*)d_in[18];
    const float* root   = (const float*)d_in[19];
    const float* gbias  = (const float*)d_in[20];
    float* out = (float*)d_out;

    static cudaStream_t sA = nullptr, sB = nullptr;
    static cudaEvent_t evRoot, evN, evA, evB, evM;
    if (sA == nullptr) {
        cudaStreamCreateWithFlags(&sA, cudaStreamNonBlocking);
        cudaStreamCreateWithFlags(&sB, cudaStreamNonBlocking);
        cudaEventCreateWithFlags(&evRoot, cudaEventDisableTiming);
        cudaEventCreateWithFlags(&evN, cudaEventDisableTiming);
        cudaEventCreateWithFlags(&evA, cudaEventDisableTiming);
        cudaEventCreateWithFlags(&evB, cudaEventDisableTiming);
        cudaEventCreateWithFlags(&evM, cudaEventDisableTiming);
    }

    // fork point
    cudaEventRecord(evRoot, 0);
    cudaStreamWaitEvent(sA, evRoot, 0);
    cudaStreamWaitEvent(sB, evRoot, 0);

    // stream A: CSR build
    initcsr_kernel<<<8, 1024, 0, sA>>>(eidx);
    convhist_kernel<<<512, 256, 0, sA>>>(eidx);
    scan_kernel<<<2, 1024, 0, sA>>>();
    fill_kernel<<<512, 256, 0, sA>>>();
    cudaEventRecord(evA, sA);

    // stream B: edge hidden + w2 convert (both independent of x)
    edgehid_kernel<<<2048, 256, 0, sB>>>(eattr, kw1, kb1);
    w2conv_kernel<<<256, 256, 0, sB>>>(kw2);

    // stream 0: fused normalize of input
    statsnorm_kernel<<<256, 256>>>(nodes);
    cudaEventRecord(evN, 0);

    // stream A: pointwise MLP branch
    cudaStreamWaitEvent(sA, evN, 0);
    mlp1_kernel<<<128, 128, 0, sA>>>(wm_w1, wm_b1, wm_w2, wm_b2);   // + stats slot2
    cudaEventRecord(evM, sA);

    // stream B: tensor-core g GEMM, then edge msg
    cudaStreamWaitEvent(sB, evN, 0);
    {
        dim3 g(128, 16);
        gemm_gh_kernel<<<g, 256, 0, sB>>>();
    }
    cudaStreamWaitEvent(sB, evA, 0);
    edgemsg_kernel<<<4096, 128, 0, sB>>>(kb2);
    cudaEventRecord(evB, sB);

    // stream 0: spectral branch
    fwdW_kernel<<<256, 256>>>();
    fwdH_kernel<<<128, 512>>>();
    modemix_kernel<<<512, 128>>>(w1re, w1im, w2re, w2im);
    invH_kernel<<<256, 512>>>();
    invW_kernel<<<256, 256>>>();          // + stats slot1
    mlp0_kernel<<<128, 128>>>(mlp_w1, mlp_b1, mlp_w2, mlp_b2);

    // join: final combine
    cudaStreamWaitEvent(0, evB, 0);
    cudaStreamWaitEvent(0, evM, 0);
    final_kernel<<<4096, 128>>>(root, gbias, out);
}

// round 15
// speedup vs baseline: 2.1330x; 1.0710x over previous
#include <cuda_runtime.h>
#include <cuda_fp16.h>
#include <math.h>

#define BB 4
#define NND 4096
#define EED 131072

// ---------------- scratch ----------------
__device__ float  d_stats[3 * 512];          // slot2 @1024 used for x2 stats
__device__ float  d_xn  [BB * NND * 32];
__device__ __half d_xnh [BB * NND * 32];
__device__ __half d_w2h [32 * 2048];               // [c][k*32+o] fp16
__device__ float2 d_T   [BB * 64 * 16 * 32];
__device__ float2 d_Xft [BB * 32 * 16 * 32];
__device__ float2 d_oft [BB * 32 * 16 * 32];
__device__ float2 d_V   [BB * 64 * 16 * 32];
__device__ float  d_x1b [BB * NND * 32];
__device__ float  d_x2  [BB * NND * 32];
__device__ __half d_hh  [(long long)EED * 64];
__device__ __half d_gh  [(long long)BB * NND * 64 * 32];   // linear [row][k*32+o]
__device__ __half d_msg [(long long)EED * BB * 32];        // fp16, indexed by dst-CSR position
__device__ int    d_esrc[EED];
__device__ int    d_edst[EED];
__device__ int    d_is64;
__device__ int    d_cnt [2 * NND];   // zero-initialized at load; re-zeroed by final_kernel
__device__ int    d_offA[2 * (NND + 1)];
__device__ int    d_cur [2 * NND];   // ditto
__device__ int    d_eid [2 * EED];   // [0:E) src-CSR edge ids; [E:2E) dstpos per edge

__device__ __forceinline__ float gelu_f(float x) {
    return 0.5f * x * (1.0f + erff(x * 0.70710678118654752f));
}
__device__ __forceinline__ unsigned smem_u32(const void* p) {
    return (unsigned)__cvta_generic_to_shared(p);
}

// ---------------- probe edge dtype (cnt/cur zeroing moved to final_kernel tail) ----------------
__global__ void probe_kernel(const void* ei) {
    const int* w = (const int*)ei;
    int t = threadIdx.x;   // 256
    int nz = 0;
    for (int k = t; k < 1024; k += 256) nz |= w[2 * k + 1];
    __shared__ int s;
    if (t == 0) s = 0;
    __syncthreads();
    if (nz) atomicOr(&s, 1);
    __syncthreads();
    if (t == 0) d_is64 = (s == 0);   // all-zero odd words => int64
}

// ---------------- convert + histogram ----------------
__global__ void convhist_kernel(const void* ei) {
    int e = blockIdx.x * 256 + threadIdx.x;  // 512x256
    int s, d;
    if (d_is64) {
        const long long* p = (const long long*)ei;
        s = (int)p[e]; d = (int)p[EED + e];
    } else {
        const int* p = (const int*)ei;
        s = p[e]; d = p[EED + e];
    }
    d_esrc[e] = s; d_edst[e] = d;
    atomicAdd(&d_cnt[s], 1);
    atomicAdd(&d_cnt[NND + d], 1);
}

__global__ void scan_kernel() {
    int a = blockIdx.x;   // 0=src, 1=dst
    int t = threadIdx.x;  // 1024
    const int* cnt = d_cnt + a * NND;
    int* off = d_offA + a * (NND + 1);
    int v0 = cnt[t * 4], v1 = cnt[t * 4 + 1], v2 = cnt[t * 4 + 2], v3 = cnt[t * 4 + 3];
    int s = v0 + v1 + v2 + v3;
    __shared__ int sh[1024];
    sh[t] = s; __syncthreads();
    for (int o1 = 1; o1 < 1024; o1 <<= 1) {
        int v = (t >= o1) ? sh[t - o1] : 0;
        __syncthreads();
        sh[t] += v;
        __syncthreads();
    }
    int excl = sh[t] - s;
    off[t * 4] = excl; off[t * 4 + 1] = excl + v0;
    off[t * 4 + 2] = excl + v0 + v1; off[t * 4 + 3] = excl + v0 + v1 + v2;
    if (t == 1023) off[NND] = sh[1023];
}

__global__ void fill_kernel() {
    int e = blockIdx.x * 256 + threadIdx.x;    // 512x256
    int s = d_esrc[e], d2 = d_edst[e];
    int p = atomicAdd(&d_cur[s], 1);
    d_eid[d_offA[s] + p] = e;
    int q = atomicAdd(&d_cur[NND + d2], 1);
    d_eid[EED + e] = d_offA[(NND + 1) + d2] + q;   // dstpos of edge e
}

// ---------------- fused instance-norm: stats + normalize, emits fp32 + fp16 ----------------
__global__ void statsnorm_kernel(const float* __restrict__ nodes) {
    int row = blockIdx.x;            // 256
    int t = threadIdx.x;             // 256
    __shared__ float xs[2048];
    __shared__ float sh1[256], sh2[256];
    __shared__ float mr[2];
    const float* p = nodes + row * 2048;
    float s = 0.f, s2 = 0.f;
#pragma unroll
    for (int i = 0; i < 8; i++) {
        float v = p[t + i * 256];
        xs[t + i * 256] = v;
        s += v; s2 += v * v;
    }
    sh1[t] = s; sh2[t] = s2; __syncthreads();
    for (int o = 128; o > 0; o >>= 1) {
        if (t < o) { sh1[t] += sh1[t + o]; sh2[t] += sh2[t + o]; }
        __syncthreads();
    }
    if (t == 0) {
        float m = sh1[0] * (1.0f / 2048.0f);
        float var = sh2[0] * (1.0f / 2048.0f) - m * m;
        mr[0] = m; mr[1] = rsqrtf(var + 1e-5f);
    }
    __syncthreads();
    float m = mr[0], rs = mr[1];
#pragma unroll
    for (int i = 0; i < 8; i++) {
        float v = (xs[t + i * 256] - m) * rs;
        d_xn [row * 2048 + t + i * 256] = v;
        d_xnh[row * 2048 + t + i * 256] = __float2half_rn(v);
    }
}

// ---------------- w2 transpose+convert ----------------
__global__ void w2conv_kernel(const float* __restrict__ kw2) {
    int i = blockIdx.x * 256 + threadIdx.x;   // 256x256 = 65536
    int c = i >> 11, col = i & 2047;
    d_w2h[i] = __float2half_rn(kw2[(col >> 5) * 1024 + c * 32 + (col & 31)]);
}

// ---------------- forward DFT over W (ky 0..15) ----------------
__global__ void fwdW_kernel() {
    int bh = blockIdx.x;            // 256
    int t = threadIdx.x;            // 256
    __shared__ float  xs[2048];
    __shared__ float2 tw[1024];
    for (int i = t; i < 2048; i += 256) xs[i] = d_xn[bh * 2048 + i];
    for (int i = t; i < 1024; i += 256) {
        int ky = i >> 6, w = i & 63; float s, c;
        sincospif(-(float)(ky * w) * (1.0f / 32.0f), &s, &c);
        tw[i] = make_float2(c, s);
    }
    __syncthreads();
#pragma unroll
    for (int r = 0; r < 2; r++) {
        int oi = t + r * 256; int ky = oi >> 5, c = oi & 31;
        float re = 0.f, im = 0.f;
#pragma unroll 8
        for (int w = 0; w < 64; w++) {
            float xv = xs[w * 32 + c]; float2 tv = tw[ky * 64 + w];
            re += xv * tv.x; im += xv * tv.y;
        }
        d_T[(bh * 16 + ky) * 32 + c] = make_float2(re, im);
    }
}

// ---------------- forward DFT over H (kx 0..15, 48..63), *1/64 ----------------
__global__ void fwdH_kernel() {
    int b = blockIdx.x >> 5, kxi = blockIdx.x & 31;   // 128 blocks
    int kx = (kxi < 16) ? kxi : kxi + 32;
    int t = threadIdx.x;                               // 512
    __shared__ float2 tw[64];
    if (t < 64) { float s, c; sincospif(-(float)(kx * t) * (1.0f / 32.0f), &s, &c); tw[t] = make_float2(c, s); }
    __syncthreads();
    int ky = t >> 5, c = t & 31;
    float re = 0.f, im = 0.f;
#pragma unroll 4
    for (int h = 0; h < 64; h++) {
        float2 v = d_T[((b * 64 + h) * 16 + ky) * 32 + c];
        float2 w = tw[h];
        re += v.x * w.x - v.y * w.y;
        im += v.x * w.y + v.y * w.x;
    }
    d_Xft[((b * 32 + kxi) * 16 + ky) * 32 + c] = make_float2(re * (1.0f / 64.0f), im * (1.0f / 64.0f));
}

// ---------------- complex channel mix per (kx,ky) ----------------
__global__ void modemix_kernel(const float* w1re, const float* w1im,
                               const float* w2re, const float* w2im) {
    int kxi = blockIdx.x >> 4, ky = blockIdx.x & 15;   // 512 blocks
    int xm = (kxi < 16) ? kxi : kxi - 16;
    const float* wre = (kxi < 16) ? w1re : w2re;
    const float* wim = (kxi < 16) ? w1im : w2im;
    int t = threadIdx.x;                                // 128
    __shared__ float wr[1024], wi[1024];
    __shared__ float2 Xs[128];
    for (int i = t; i < 1024; i += 128) {
        int off = i * 256 + xm * 16 + ky;
        wr[i] = wre[off]; wi[i] = wim[off];
    }
    { int b = t >> 5, c = t & 31; Xs[t] = d_Xft[((b * 32 + kxi) * 16 + ky) * 32 + c]; }
    __syncthreads();
    int b = t >> 5, o = t & 31;
    float re = 0.f, im = 0.f;
#pragma unroll
    for (int i = 0; i < 32; i++) {
        float2 xv = Xs[b * 32 + i];
        float wrv = wr[i * 32 + o], wiv = wi[i * 32 + o];
        re += xv.x * wrv - xv.y * wiv;
        im += xv.x * wiv + xv.y * wrv;
    }
    d_oft[((b * 32 + kxi) * 16 + ky) * 32 + o] = make_float2(re, im);
}

// ---------------- inverse DFT over H, *1/8 ----------------
__global__ void invH_kernel() {
    int b = blockIdx.x >> 6, h = blockIdx.x & 63;   // 256 blocks
    int t = threadIdx.x;                             // 512
    __shared__ float2 tw[32];
    if (t < 32) {
        int kx = (t < 16) ? t : t + 32; float s, c;
        sincospif((float)(kx * h) * (1.0f / 32.0f), &s, &c);
        tw[t] = make_float2(c, s);
    }
    __syncthreads();
    int ky = t >> 5, o = t & 31;
    float re = 0.f, im = 0.f;
#pragma unroll 4
    for (int k = 0; k < 32; k++) {
        float2 v = d_oft[((b * 32 + k) * 16 + ky) * 32 + o];
        float2 w = tw[k];
        re += v.x * w.x - v.y * w.y;
        im += v.x * w.y + v.y * w.x;
    }
    d_V[((b * 64 + h) * 16 + ky) * 32 + o] = make_float2(re * 0.125f, im * 0.125f);
}

// ---------------- inverse C2R over W + in-block instance-norm + MLP -> d_x1b ----------------
// Block = one (b,h) row: the inorm stats for x1 are over exactly this block's 2048 values.
__global__ void __launch_bounds__(256) invWmlp_kernel(const float* __restrict__ w1,
                                                      const float* __restrict__ b1,
                                                      const float* __restrict__ w2,
                                                      const float* __restrict__ b2) {
    int bh = blockIdx.x; int t = threadIdx.x;   // 256 x 256
    __shared__ __align__(16) char ov[33664];    // overlay region
    __shared__ float x1s[64 * 33];              // [w][c], pitch 33
    __shared__ float mr[2];
    // overlay A (DFT phase)
    float2* Vs  = (float2*)ov;             // 512 f2 = 4096B
    float2* tw  = (float2*)(ov + 4096);    // 1024 f2 = 8192B
    float*  sh1 = (float*)(ov + 12288);    // 1024B
    float*  sh2 = (float*)(ov + 13312);    // 1024B
    // overlay B (MLP phase)
    float* w1s = (float*)ov;               // 8192B
    float* w2s = (float*)(ov + 8192);      // 8192B
    float* hsm = (float*)(ov + 16384);     // 64*65*4 = 16640B
    float* b1s = (float*)(ov + 33024);     // 256B
    float* b2s = (float*)(ov + 33280);     // 128B

    for (int i = t; i < 512; i += 256) Vs[i] = d_V[bh * 512 + i];
    for (int i = t; i < 1024; i += 256) {
        int ky = i >> 6, w = i & 63; float s, c;
        sincospif((float)(ky * w) * (1.0f / 32.0f), &s, &c);
        tw[i] = make_float2(c, s);
    }
    __syncthreads();
    float ss = 0.f, ss2 = 0.f;
#pragma unroll
    for (int r = 0; r < 8; r++) {
        int oi = t + r * 256; int w = oi >> 5, o = oi & 31;
        float acc = 0.f;
#pragma unroll
        for (int ky = 0; ky < 16; ky++) {
            float2 v = Vs[ky * 32 + o]; float2 tv = tw[ky * 64 + w];
            float term = v.x * tv.x - v.y * tv.y;
            acc += (ky == 0) ? term : 2.0f * term;
        }
        acc *= 0.125f;
        x1s[w * 33 + o] = acc;
        ss += acc; ss2 += acc * acc;
    }
    sh1[t] = ss; sh2[t] = ss2; __syncthreads();
    for (int o = 128; o > 0; o >>= 1) {
        if (t < o) { sh1[t] += sh1[t + o]; sh2[t] += sh2[t + o]; }
        __syncthreads();
    }
    if (t == 0) {
        float m = sh1[0] * (1.0f / 2048.0f);
        float var = sh2[0] * (1.0f / 2048.0f) - m * m;
        mr[0] = m; mr[1] = rsqrtf(var + 1e-5f);
    }
    __syncthreads();
    // switch to overlay B: load MLP weights + normalize x1s in place
    float m = mr[0], rs = mr[1];
    for (int i = t; i < 2048; i += 256) { w1s[i] = w1[i]; w2s[i] = w2[i]; }
    if (t < 64) b1s[t] = b1[t];
    if (t < 32) b2s[t] = b2[t];
    for (int i = t; i < 2048; i += 256) {
        int w = i >> 5, o = i & 31;
        x1s[w * 33 + o] = (x1s[w * 33 + o] - m) * rs;
    }
    __syncthreads();
    // stage 1: hidden (64 pixels x 64 k); thread t -> pixel t&63, k range (t>>6)*16..+16
    int pix = t & 63, kq = t >> 6;
#pragma unroll
    for (int kk = 0; kk < 16; kk++) {
        int k = kq * 16 + kk;
        float a = b1s[k];
#pragma unroll
        for (int c = 0; c < 32; c++) a += x1s[pix * 33 + c] * w1s[c * 64 + k];
        hsm[pix * 65 + k] = gelu_f(a);
    }
    __syncthreads();
    // stage 2: outputs; thread t -> pixel t&63, j range (t>>6)*8..+8
    {
        int js = kq * 8;
        float o[8];
#pragma unroll
        for (int j = 0; j < 8; j++) o[j] = b2s[js + j];
        for (int k = 0; k < 64; k++) {
            float hv = hsm[pix * 65 + k];
#pragma unroll
            for (int j = 0; j < 8; j++) o[j] += hv * w2s[k * 32 + js + j];
        }
#pragma unroll
        for (int j = 0; j < 8; j++) x1s[pix * 33 + js + j] = o[j];
    }
    __syncthreads();
    for (int i = t; i < 2048; i += 256)
        d_x1b[bh * 2048 + i] = x1s[(i >> 5) * 33 + (i & 31)];
}

// ---------------- MLP on xn -> d_x2, fused stats(slot2) ----------------
__global__ void __launch_bounds__(128) mlp1_kernel(const float* w1, const float* b1,
                                                   const float* w2, const float* b2) {
    int t = threadIdx.x;   // 128
    __shared__ float w1s[2048], w2s[2048], b1s[64], b2s[32];
    __shared__ float sh1[128], sh2[128];
    for (int i = t; i < 2048; i += 128) { w1s[i] = w1[i]; w2s[i] = w2[i]; }
    if (t < 64) b1s[t] = b1[t];
    if (t < 32) b2s[t] = b2[t];
    __syncthreads();
    int p = blockIdx.x * 128 + t;   // grid 128
    float x[32];
#pragma unroll
    for (int c = 0; c < 32; c++) x[c] = d_xn[p * 32 + c];
    float o[32];
#pragma unroll
    for (int j = 0; j < 32; j++) o[j] = b2s[j];
    for (int k = 0; k < 64; k++) {
        float a = b1s[k];
#pragma unroll
        for (int c = 0; c < 32; c++) a += x[c] * w1s[c * 64 + k];
        a = gelu_f(a);
#pragma unroll
        for (int j = 0; j < 32; j++) o[j] += a * w2s[k * 32 + j];
    }
    float ss = 0.f, ss2 = 0.f;
#pragma unroll
    for (int j = 0; j < 32; j++) {
        d_x2[p * 32 + j] = o[j];
        ss += o[j]; ss2 += o[j] * o[j];
    }
    sh1[t] = ss; sh2[t] = ss2; __syncthreads();
    int half = t & 64;
    int l = t & 63;
    for (int off = 32; off > 0; off >>= 1) {
        if (l < off) { sh1[half + l] += sh1[half + l + off]; sh2[half + l] += sh2[half + l + off]; }
        __syncthreads();
    }
    if (l == 0) {
        int row = blockIdx.x * 2 + (half >> 6);
        float m = sh1[half] * (1.0f / 2048.0f);
        float var = sh2[half] * (1.0f / 2048.0f) - m * m;
        d_stats[1024 + row] = m;
        d_stats[1024 + 256 + row] = rsqrtf(var + 1e-5f);
    }
}

// ---------------- edge hidden h = gelu(attr @ kw1 + kb1), fp16 out ----------------
__global__ void edgehid_kernel(const float* attr, const float* w1, const float* b1) {
    int e0 = blockIdx.x * 64;   // 2048 blocks
    int t = threadIdx.x;        // 256
    __shared__ float at[384], w1s[384], b1s[64];
    for (int i = t; i < 384; i += 256) { at[i] = attr[e0 * 6 + i]; w1s[i] = w1[i]; }
    if (t < 64) b1s[t] = b1[t];
    __syncthreads();
#pragma unroll
    for (int r = 0; r < 16; r++) {
        int i = t + r * 256; int el = i >> 6, k = i & 63;
        float a = b1s[k];
#pragma unroll
        for (int d = 0; d < 6; d++) a += at[el * 6 + d] * w1s[d * 64 + k];
        d_hh[(long long)(e0 + el) * 64 + k] = __float2half_rn(gelu_f(a));
    }
}

// ---------------- tensor-core g GEMM: d_gh = xnh[16384,32] @ w2h[32,2048] ----------------
__global__ void __launch_bounds__(256) gemm_gh_kernel() {
    int bm = blockIdx.x;    // 128 row blocks
    int bn = blockIdx.y;    // 16 col blocks
    int t = threadIdx.x;    // 256 = 8 warps
    int w = t >> 5, lane = t & 31;
    __shared__ __align__(16) char smemraw[32768];
    __half* Ah = (__half*)smemraw;              // [128][40] pitch 80B
    __half* Bh = (__half*)(smemraw + 10240);    // [32][136] pitch 272B
    __half* Cs = (__half*)smemraw;              // [128][128] (after barrier)

    {
        const int4* ap = (const int4*)(d_xnh + (long long)bm * 128 * 32);
        for (int i = t; i < 512; i += 256) {
            int4 v = ap[i];
            int r = i >> 2, c4 = i & 3;
            *(int4*)&Ah[r * 40 + c4 * 8] = v;
        }
    }
    {
        for (int i = t; i < 512; i += 256) {
            int r = i >> 4, c8 = i & 15;
            int4 v = *(const int4*)(d_w2h + r * 2048 + bn * 128 + c8 * 8);
            *(int4*)&Bh[r * 136 + c8 * 8] = v;
        }
    }
    __syncthreads();

    float acc[16][4];
#pragma unroll
    for (int nt = 0; nt < 16; nt++) {
        acc[nt][0] = 0.f; acc[nt][1] = 0.f; acc[nt][2] = 0.f; acc[nt][3] = 0.f;
    }
    unsigned abase = smem_u32(Ah) + w * 16 * 80;
    unsigned bbase = smem_u32(Bh);
    int grp = lane >> 3, rowi = lane & 7;
#pragma unroll
    for (int ks = 0; ks < 2; ks++) {
        unsigned a0, a1, a2, a3;
        unsigned aaddr = abase + (lane & 15) * 80 + ks * 32 + (lane >> 4) * 16;
        asm volatile("ldmatrix.sync.aligned.m8n8.x4.shared.b16 {%0,%1,%2,%3}, [%4];"
                     : "=r"(a0), "=r"(a1), "=r"(a2), "=r"(a3) : "r"(aaddr));
#pragma unroll
        for (int np = 0; np < 8; np++) {
            unsigned baddr = bbase + (unsigned)((ks * 16 + (grp & 1) * 8 + rowi) * 272
                                                + (np * 2 + (grp >> 1)) * 16);
            unsigned r0, r1, r2, r3;
            asm volatile("ldmatrix.sync.aligned.m8n8.x4.trans.shared.b16 {%0,%1,%2,%3}, [%4];"
                         : "=r"(r0), "=r"(r1), "=r"(r2), "=r"(r3) : "r"(baddr));
            asm volatile(
                "mma.sync.aligned.m16n8k16.row.col.f32.f16.f16.f32 "
                "{%0,%1,%2,%3}, {%4,%5,%6,%7}, {%8,%9}, {%0,%1,%2,%3};"
                : "+f"(acc[np * 2][0]), "+f"(acc[np * 2][1]),
                  "+f"(acc[np * 2][2]), "+f"(acc[np * 2][3])
                : "r"(a0), "r"(a1), "r"(a2), "r"(a3), "r"(r0), "r"(r1));
            asm volatile(
                "mma.sync.aligned.m16n8k16.row.col.f32.f16.f16.f32 "
                "{%0,%1,%2,%3}, {%4,%5,%6,%7}, {%8,%9}, {%0,%1,%2,%3};"
                : "+f"(acc[np * 2 + 1][0]), "+f"(acc[np * 2 + 1][1]),
                  "+f"(acc[np * 2 + 1][2]), "+f"(acc[np * 2 + 1][3])
                : "r"(a0), "r"(a1), "r"(a2), "r"(a3), "r"(r2), "r"(r3));
        }
    }
    __syncthreads();
    {
        int r0 = lane >> 2;
#pragma unroll
        for (int nt = 0; nt < 16; nt++) {
            int col = nt * 8 + (lane & 3) * 2;
            *(__half2*)&Cs[(w * 16 + r0) * 128 + col] =
                __floats2half2_rn(acc[nt][0], acc[nt][1]);
            *(__half2*)&Cs[(w * 16 + r0 + 8) * 128 + col] =
                __floats2half2_rn(acc[nt][2], acc[nt][3]);
        }
    }
    __syncthreads();
    {
        __half* gp = d_gh + (long long)bm * 128 * 2048 + bn * 128;
        for (int i = t; i < 2048; i += 256) {
            int r = i >> 4, c8 = i & 15;
            *(int4*)(gp + (long long)r * 2048 + c8 * 8) = *(int4*)&Cs[r * 128 + c8 * 8];
        }
    }
}

// ---------------- per-src msg via mma.m16n8k16; B-frags via ldmatrix.trans ----------------
__global__ void __launch_bounds__(128) edgemsg_kernel(const float* __restrict__ kb2) {
    int node = blockIdx.x;   // 4096
    int t = threadIdx.x;
    int wid = t >> 5, lane = t & 31;   // wid == b
    int s0 = d_offA[node], s1 = d_offA[node + 1];
    if (s0 == s1) return;
    __shared__ __align__(16) __half gsm[4][64 * 40];   // [b][k row][o], pitch 80B
    __shared__ __align__(16) __half hsm[16 * 72];      // [edge][k], pitch 144B
    __shared__ float xsrc[128];
    __shared__ float xbs[128];
    __shared__ int   es[16];
    __shared__ int   dp[16];

    {
        const int4* gp = (const int4*)(d_gh + (long long)(wid * NND + node) * 2048);
#pragma unroll
        for (int i = 0; i < 8; i++) {
            int idx = i * 32 + lane;
            int4 v = gp[idx];
            int r = idx >> 2, c4 = idx & 3;
            *(int4*)&gsm[wid][r * 40 + c4 * 8] = v;
        }
    }
    xsrc[t] = d_xn[(wid * NND + node) * 32 + lane];
    __syncwarp();

    uint2 bf[16];
    {
        unsigned gb = smem_u32(&gsm[wid][0]);
        int grp = lane >> 3, rowi = lane & 7;
#pragma unroll
        for (int ks = 0; ks < 4; ks++) {
#pragma unroll
            for (int np = 0; np < 2; np++) {
                unsigned addr = gb + (unsigned)((ks * 16 + (grp & 1) * 8 + rowi) * 80
                                                + (np * 2 + (grp >> 1)) * 16);
                unsigned r0, r1, r2, r3;
                asm volatile("ldmatrix.sync.aligned.m8n8.x4.trans.shared.b16 {%0,%1,%2,%3}, [%4];"
                             : "=r"(r0), "=r"(r1), "=r"(r2), "=r"(r3) : "r"(addr));
                bf[ks * 4 + np * 2 + 0] = make_uint2(r0, r1);
                bf[ks * 4 + np * 2 + 1] = make_uint2(r2, r3);
            }
        }
    }
    float xb = 0.f;
#pragma unroll
    for (int c = 0; c < 32; c++) xb += xsrc[wid * 32 + c] * kb2[c * 32 + lane];
    xbs[t] = xb;
    __syncwarp();
    float xb0[4], xb1[4];
#pragma unroll
    for (int nt = 0; nt < 4; nt++) {
        int col = nt * 8 + (lane & 3) * 2;
        xb0[nt] = xbs[wid * 32 + col];
        xb1[nt] = xbs[wid * 32 + col + 1];
    }
    int r0 = lane >> 2, r1 = r0 + 8;
    unsigned hbase = smem_u32(hsm);
    __half2* msg2 = (__half2*)d_msg;

    for (int ec = s0; ec < s1; ec += 16) {
        int nch = min(16, s1 - ec);
        __syncthreads();
        if (t < nch) { int e = d_eid[ec + t]; es[t] = e; dp[t] = d_eid[EED + e]; }
        __syncthreads();
        {
            int r = t >> 3, c8 = t & 7;
            int4 hv = make_int4(0, 0, 0, 0);
            if (r < nch) hv = *(const int4*)(d_hh + (long long)es[r] * 64 + c8 * 8);
            *(int4*)(hsm + r * 72 + c8 * 8) = hv;
        }
        __syncthreads();
        float acc[4][4];
#pragma unroll
        for (int nt = 0; nt < 4; nt++) {
            acc[nt][0] = xb0[nt]; acc[nt][1] = xb1[nt];
            acc[nt][2] = xb0[nt]; acc[nt][3] = xb1[nt];
        }
#pragma unroll
        for (int ks = 0; ks < 4; ks++) {
            unsigned a0, a1, a2, a3;
            unsigned addr = hbase + (lane & 15) * 144 + ks * 32 + (lane >> 4) * 16;
            asm volatile("ldmatrix.sync.aligned.m8n8.x4.shared.b16 {%0,%1,%2,%3}, [%4];"
                         : "=r"(a0), "=r"(a1), "=r"(a2), "=r"(a3) : "r"(addr));
#pragma unroll
            for (int nt = 0; nt < 4; nt++) {
                int f = ks * 4 + nt;
                asm volatile(
                    "mma.sync.aligned.m16n8k16.row.col.f32.f16.f16.f32 "
                    "{%0,%1,%2,%3}, {%4,%5,%6,%7}, {%8,%9}, {%0,%1,%2,%3};"
                    : "+f"(acc[nt][0]), "+f"(acc[nt][1]), "+f"(acc[nt][2]), "+f"(acc[nt][3])
                    : "r"(a0), "r"(a1), "r"(a2), "r"(a3), "r"(bf[f].x), "r"(bf[f].y));
            }
        }
#pragma unroll
        for (int nt = 0; nt < 4; nt++) {
            int h2idx = nt * 4 + (lane & 3);
            if (r0 < nch)
                msg2[((long long)dp[r0] * 4 + wid) * 16 + h2idx] =
                    __floats2half2_rn(acc[nt][0], acc[nt][1]);
            if (r1 < nch)
                msg2[((long long)dp[r1] * 4 + wid) * 16 + h2idx] =
                    __floats2half2_rn(acc[nt][2], acc[nt][3]);
        }
    }
}

// ---------------- dst gather + root + bias + combine + gelu; re-zero cnt/cur for next run ----------------
__global__ void __launch_bounds__(128) final_kernel(const float* __restrict__ root,
                                                    const float* __restrict__ gbias,
                                                    float* __restrict__ out) {
    int n = blockIdx.x;   // 4096
    int t = threadIdx.x; int b = t >> 5, o = t & 31;
    __shared__ float roots[1024];
    __shared__ float xs[128];
    for (int i = t; i < 1024; i += 128) roots[i] = root[i];
    xs[t] = d_xn[(b * NND + n) * 32 + o];
    __syncthreads();
    float acc = gbias[o];
#pragma unroll
    for (int c = 0; c < 32; c++) acc += xs[b * 32 + c] * roots[c * 32 + o];
    int s0 = d_offA[(NND + 1) + n], s1 = d_offA[(NND + 1) + n + 1];
    const __half* mp = d_msg;
    int i = s0;
    float a0 = 0.f, a1 = 0.f, a2 = 0.f, a3 = 0.f;
    for (; i + 4 <= s1; i += 4) {
        a0 += __half2float(mp[((long long)i * 4 + b) * 32 + o]);
        a1 += __half2float(mp[((long long)(i + 1) * 4 + b) * 32 + o]);
        a2 += __half2float(mp[((long long)(i + 2) * 4 + b) * 32 + o]);
        a3 += __half2float(mp[((long long)(i + 3) * 4 + b) * 32 + o]);
    }
    for (; i < s1; i++) a0 += __half2float(mp[((long long)i * 4 + b) * 32 + o]);
    acc += (a0 + a1) + (a2 + a3);
    int p = b * NND + n; int row = p >> 6;
    float x2v = (d_x2[(long long)p * 32 + o] - d_stats[1024 + row]) * d_stats[1024 + 256 + row];
    float s = d_x1b[(long long)p * 32 + o] + x2v + acc;
    out[(long long)p * 32 + o] = gelu_f(s);
    // re-zero CSR counters for the next graph replay (zero-init at load covers the first run)
    int gid = n * 128 + t;
    if (gid < 2 * NND) d_cnt[gid] = 0;
    else if (gid < 4 * NND) d_cur[gid - 2 * NND] = 0;
}

// ---------------- launch (fork/join stream-parallel graph) ----------------
extern "C" void kernel_launch(void* const* d_in, const int* in_sizes, int n_in,
                              void* d_out, int out_size) {
    const float* nodes  = (const float*)d_in[0];
    const void*  eidx   = d_in[1];
    const float* eattr  = (const float*)d_in[2];
    const float* w1re   = (const float*)d_in[3];
    const float* w1im   = (const float*)d_in[4];
    const float* w2re   = (const float*)d_in[5];
    const float* w2im   = (const float*)d_in[6];
    const float* mlp_w1 = (const float*)d_in[7];
    const float* mlp_b1 = (const float*)d_in[8];
    const float* mlp_w2 = (const float*)d_in[9];
    const float* mlp_b2 = (const float*)d_in[10];
    const float* wm_w1  = (const float*)d_in[11];
    const float* wm_b1  = (const float*)d_in[12];
    const float* wm_w2  = (const float*)d_in[13];
    const float* wm_b2  = (const float*)d_in[14];
    const float* kw1    = (const float*)d_in[15];
    const float* kb1    = (const float*)d_in[16];
    const float* kw2    = (const float*)d_in[17];
    const float* kb2    = (const float*)d_in[18];
    const float* root   = (const float*)d_in[19];
    const float* gbias  = (const float*)d_in[20];
    float* out = (float*)d_out;

    static cudaStream_t sA = nullptr, sB = nullptr;
    static cudaEvent_t evRoot, evN, evA, evB, evM;
    if (sA == nullptr) {
        cudaStreamCreateWithFlags(&sA, cudaStreamNonBlocking);
        cudaStreamCreateWithFlags(&sB, cudaStreamNonBlocking);
        cudaEventCreateWithFlags(&evRoot, cudaEventDisableTiming);
        cudaEventCreateWithFlags(&evN, cudaEventDisableTiming);
        cudaEventCreateWithFlags(&evA, cudaEventDisableTiming);
        cudaEventCreateWithFlags(&evB, cudaEventDisableTiming);
        cudaEventCreateWithFlags(&evM, cudaEventDisableTiming);
    }

    // fork point
    cudaEventRecord(evRoot, 0);
    cudaStreamWaitEvent(sA, evRoot, 0);
    cudaStreamWaitEvent(sB, evRoot, 0);

    // stream A: CSR build (cnt/cur pre-zeroed by previous run / module init)
    probe_kernel<<<1, 256, 0, sA>>>(eidx);
    convhist_kernel<<<512, 256, 0, sA>>>(eidx);
    scan_kernel<<<2, 1024, 0, sA>>>();
    fill_kernel<<<512, 256, 0, sA>>>();
    cudaEventRecord(evA, sA);

    // stream B: edge hidden + w2 convert (both independent of x)
    edgehid_kernel<<<2048, 256, 0, sB>>>(eattr, kw1, kb1);
    w2conv_kernel<<<256, 256, 0, sB>>>(kw2);

    // stream 0: fused normalize of input
    statsnorm_kernel<<<256, 256>>>(nodes);
    cudaEventRecord(evN, 0);

    // stream A: pointwise MLP branch
    cudaStreamWaitEvent(sA, evN, 0);
    mlp1_kernel<<<128, 128, 0, sA>>>(wm_w1, wm_b1, wm_w2, wm_b2);   // + stats slot2
    cudaEventRecord(evM, sA);

    // stream B: tensor-core g GEMM, then edge msg
    cudaStreamWaitEvent(sB, evN, 0);
    {
        dim3 g(128, 16);
        gemm_gh_kernel<<<g, 256, 0, sB>>>();
    }
    cudaStreamWaitEvent(sB, evA, 0);
    edgemsg_kernel<<<4096, 128, 0, sB>>>(kb2);
    cudaEventRecord(evB, sB);

    // stream 0: spectral branch (invW now also does inorm+MLP -> d_x1b)
    fwdW_kernel<<<256, 256>>>();
    fwdH_kernel<<<128, 512>>>();
    modemix_kernel<<<512, 128>>>(w1re, w1im, w2re, w2im);
    invH_kernel<<<256, 512>>>();
    invWmlp_kernel<<<256, 256>>>(mlp_w1, mlp_b1, mlp_w2, mlp_b2);

    // join: final combine
    cudaStreamWaitEvent(0, evB, 0);
    cudaStreamWaitEvent(0, evM, 0);
    final_kernel<<<4096, 128>>>(root, gbias, out);
}

// round 16
// speedup vs baseline: 2.2060x; 1.0342x over previous
#include <cuda_runtime.h>
#include <cuda_fp16.h>
#include <math.h>

#define BB 4
#define NND 4096
#define EED 131072

// ---------------- scratch ----------------
__device__ float  d_stats[3 * 512];          // slot2 @1024 used for x2 stats
__device__ float  d_xn  [BB * NND * 32];
__device__ __half d_xnh [BB * NND * 32];
__device__ __half d_w2h [32 * 2048];               // [c][k*32+o] fp16
__device__ float2 d_T   [BB * 64 * 16 * 32];
__device__ float2 d_Xft [BB * 32 * 16 * 32];
__device__ float2 d_oft [BB * 32 * 16 * 32];
__device__ float2 d_V   [BB * 64 * 16 * 32];
__device__ float  d_x1b [BB * NND * 32];
__device__ float  d_x2  [BB * NND * 32];
__device__ __half d_hh  [(long long)EED * 64];
__device__ __half d_gh  [(long long)BB * NND * 64 * 32];   // linear [row][k*32+o]
__device__ __half d_msg [(long long)EED * BB * 32];        // fp16, indexed by dst-CSR position
__device__ int    d_esrc[EED];
__device__ int    d_edst[EED];
__device__ int    d_cnt [2 * NND];   // zero-initialized at load; re-zeroed by final_kernel
__device__ int    d_offA[2 * (NND + 1)];
__device__ int    d_cur [2 * NND];   // ditto
__device__ int    d_eid [2 * EED];   // [0:E) src-CSR edge ids; [E:2E) dstpos per edge

__device__ __forceinline__ float gelu_f(float x) {
    return 0.5f * x * (1.0f + erff(x * 0.70710678118654752f));
}
__device__ __forceinline__ unsigned smem_u32(const void* p) {
    return (unsigned)__cvta_generic_to_shared(p);
}

// ---------------- convert + histogram, with per-block dtype probe ----------------
__global__ void convhist_kernel(const void* ei) {
    int t = threadIdx.x;   // 256
    // local dtype probe on first 1024 entries (L2-hot): odd words all zero => int64
    __shared__ int s;
    if (t == 0) s = 0;
    __syncthreads();
    {
        const int* w = (const int*)ei;
        int nz = 0;
        for (int k = t; k < 1024; k += 256) nz |= w[2 * k + 1];
        if (nz) atomicOr(&s, 1);
    }
    __syncthreads();
    int is64 = (s == 0);
    int e = blockIdx.x * 256 + t;  // 512x256
    int sv, dv;
    if (is64) {
        const long long* p = (const long long*)ei;
        sv = (int)p[e]; dv = (int)p[EED + e];
    } else {
        const int* p = (const int*)ei;
        sv = p[e]; dv = p[EED + e];
    }
    d_esrc[e] = sv; d_edst[e] = dv;
    atomicAdd(&d_cnt[sv], 1);
    atomicAdd(&d_cnt[NND + dv], 1);
}

__global__ void scan_kernel() {
    int a = blockIdx.x;   // 0=src, 1=dst
    int t = threadIdx.x;  // 1024
    const int* cnt = d_cnt + a * NND;
    int* off = d_offA + a * (NND + 1);
    int v0 = cnt[t * 4], v1 = cnt[t * 4 + 1], v2 = cnt[t * 4 + 2], v3 = cnt[t * 4 + 3];
    int s = v0 + v1 + v2 + v3;
    __shared__ int sh[1024];
    sh[t] = s; __syncthreads();
    for (int o1 = 1; o1 < 1024; o1 <<= 1) {
        int v = (t >= o1) ? sh[t - o1] : 0;
        __syncthreads();
        sh[t] += v;
        __syncthreads();
    }
    int excl = sh[t] - s;
    off[t * 4] = excl; off[t * 4 + 1] = excl + v0;
    off[t * 4 + 2] = excl + v0 + v1; off[t * 4 + 3] = excl + v0 + v1 + v2;
    if (t == 1023) off[NND] = sh[1023];
}

__global__ void fill_kernel() {
    int e = blockIdx.x * 256 + threadIdx.x;    // 512x256
    int s = d_esrc[e], d2 = d_edst[e];
    int p = atomicAdd(&d_cur[s], 1);
    d_eid[d_offA[s] + p] = e;
    int q = atomicAdd(&d_cur[NND + d2], 1);
    d_eid[EED + e] = d_offA[(NND + 1) + d2] + q;   // dstpos of edge e
}

// ---------------- fused instance-norm: stats + normalize, emits fp32 + fp16 ----------------
__global__ void statsnorm_kernel(const float* __restrict__ nodes) {
    int row = blockIdx.x;            // 256
    int t = threadIdx.x;             // 256
    __shared__ float xs[2048];
    __shared__ float sh1[256], sh2[256];
    __shared__ float mr[2];
    const float* p = nodes + row * 2048;
    float s = 0.f, s2 = 0.f;
#pragma unroll
    for (int i = 0; i < 8; i++) {
        float v = p[t + i * 256];
        xs[t + i * 256] = v;
        s += v; s2 += v * v;
    }
    sh1[t] = s; sh2[t] = s2; __syncthreads();
    for (int o = 128; o > 0; o >>= 1) {
        if (t < o) { sh1[t] += sh1[t + o]; sh2[t] += sh2[t + o]; }
        __syncthreads();
    }
    if (t == 0) {
        float m = sh1[0] * (1.0f / 2048.0f);
        float var = sh2[0] * (1.0f / 2048.0f) - m * m;
        mr[0] = m; mr[1] = rsqrtf(var + 1e-5f);
    }
    __syncthreads();
    float m = mr[0], rs = mr[1];
#pragma unroll
    for (int i = 0; i < 8; i++) {
        float v = (xs[t + i * 256] - m) * rs;
        d_xn [row * 2048 + t + i * 256] = v;
        d_xnh[row * 2048 + t + i * 256] = __float2half_rn(v);
    }
}

// ---------------- w2 transpose+convert ----------------
__global__ void w2conv_kernel(const float* __restrict__ kw2) {
    int i = blockIdx.x * 256 + threadIdx.x;   // 256x256 = 65536
    int c = i >> 11, col = i & 2047;
    d_w2h[i] = __float2half_rn(kw2[(col >> 5) * 1024 + c * 32 + (col & 31)]);
}

// ---------------- forward DFT over W (ky 0..15) ----------------
__global__ void fwdW_kernel() {
    int bh = blockIdx.x;            // 256
    int t = threadIdx.x;            // 256
    __shared__ float  xs[2048];
    __shared__ float2 tw[1024];
    for (int i = t; i < 2048; i += 256) xs[i] = d_xn[bh * 2048 + i];
    for (int i = t; i < 1024; i += 256) {
        int ky = i >> 6, w = i & 63; float s, c;
        sincospif(-(float)(ky * w) * (1.0f / 32.0f), &s, &c);
        tw[i] = make_float2(c, s);
    }
    __syncthreads();
#pragma unroll
    for (int r = 0; r < 2; r++) {
        int oi = t + r * 256; int ky = oi >> 5, c = oi & 31;
        float re = 0.f, im = 0.f;
#pragma unroll 8
        for (int w = 0; w < 64; w++) {
            float xv = xs[w * 32 + c]; float2 tv = tw[ky * 64 + w];
            re += xv * tv.x; im += xv * tv.y;
        }
        d_T[(bh * 16 + ky) * 32 + c] = make_float2(re, im);
    }
}

// ---------------- forward DFT over H (kx 0..15, 48..63), *1/64 ----------------
__global__ void fwdH_kernel() {
    int b = blockIdx.x >> 5, kxi = blockIdx.x & 31;   // 128 blocks
    int kx = (kxi < 16) ? kxi : kxi + 32;
    int t = threadIdx.x;                               // 512
    __shared__ float2 tw[64];
    if (t < 64) { float s, c; sincospif(-(float)(kx * t) * (1.0f / 32.0f), &s, &c); tw[t] = make_float2(c, s); }
    __syncthreads();
    int ky = t >> 5, c = t & 31;
    float re = 0.f, im = 0.f;
#pragma unroll 4
    for (int h = 0; h < 64; h++) {
        float2 v = d_T[((b * 64 + h) * 16 + ky) * 32 + c];
        float2 w = tw[h];
        re += v.x * w.x - v.y * w.y;
        im += v.x * w.y + v.y * w.x;
    }
    d_Xft[((b * 32 + kxi) * 16 + ky) * 32 + c] = make_float2(re * (1.0f / 64.0f), im * (1.0f / 64.0f));
}

// ---------------- complex channel mix per (kx,ky) ----------------
__global__ void modemix_kernel(const float* w1re, const float* w1im,
                               const float* w2re, const float* w2im) {
    int kxi = blockIdx.x >> 4, ky = blockIdx.x & 15;   // 512 blocks
    int xm = (kxi < 16) ? kxi : kxi - 16;
    const float* wre = (kxi < 16) ? w1re : w2re;
    const float* wim = (kxi < 16) ? w1im : w2im;
    int t = threadIdx.x;                                // 128
    __shared__ float wr[1024], wi[1024];
    __shared__ float2 Xs[128];
    for (int i = t; i < 1024; i += 128) {
        int off = i * 256 + xm * 16 + ky;
        wr[i] = wre[off]; wi[i] = wim[off];
    }
    { int b = t >> 5, c = t & 31; Xs[t] = d_Xft[((b * 32 + kxi) * 16 + ky) * 32 + c]; }
    __syncthreads();
    int b = t >> 5, o = t & 31;
    float re = 0.f, im = 0.f;
#pragma unroll
    for (int i = 0; i < 32; i++) {
        float2 xv = Xs[b * 32 + i];
        float wrv = wr[i * 32 + o], wiv = wi[i * 32 + o];
        re += xv.x * wrv - xv.y * wiv;
        im += xv.x * wiv + xv.y * wrv;
    }
    d_oft[((b * 32 + kxi) * 16 + ky) * 32 + o] = make_float2(re, im);
}

// ---------------- inverse DFT over H, *1/8 ----------------
__global__ void invH_kernel() {
    int b = blockIdx.x >> 6, h = blockIdx.x & 63;   // 256 blocks
    int t = threadIdx.x;                             // 512
    __shared__ float2 tw[32];
    if (t < 32) {
        int kx = (t < 16) ? t : t + 32; float s, c;
        sincospif((float)(kx * h) * (1.0f / 32.0f), &s, &c);
        tw[t] = make_float2(c, s);
    }
    __syncthreads();
    int ky = t >> 5, o = t & 31;
    float re = 0.f, im = 0.f;
#pragma unroll 4
    for (int k = 0; k < 32; k++) {
        float2 v = d_oft[((b * 32 + k) * 16 + ky) * 32 + o];
        float2 w = tw[k];
        re += v.x * w.x - v.y * w.y;
        im += v.x * w.y + v.y * w.x;
    }
    d_V[((b * 64 + h) * 16 + ky) * 32 + o] = make_float2(re * 0.125f, im * 0.125f);
}

// ---------------- inverse C2R over W + in-block instance-norm + MLP -> d_x1b ----------------
__global__ void __launch_bounds__(256) invWmlp_kernel(const float* __restrict__ w1,
                                                      const float* __restrict__ b1,
                                                      const float* __restrict__ w2,
                                                      const float* __restrict__ b2) {
    int bh = blockIdx.x; int t = threadIdx.x;   // 256 x 256
    __shared__ __align__(16) char ov[33664];    // overlay region
    __shared__ float x1s[64 * 33];              // [w][c], pitch 33
    __shared__ float mr[2];
    // overlay A (DFT phase)
    float2* Vs  = (float2*)ov;             // 4096B
    float2* tw  = (float2*)(ov + 4096);    // 8192B
    float*  sh1 = (float*)(ov + 12288);    // 1024B
    float*  sh2 = (float*)(ov + 13312);    // 1024B
    // overlay B (MLP phase)
    float* w1s = (float*)ov;               // 8192B
    float* w2s = (float*)(ov + 8192);      // 8192B
    float* hsm = (float*)(ov + 16384);     // 16640B
    float* b1s = (float*)(ov + 33024);     // 256B
    float* b2s = (float*)(ov + 33280);     // 128B

    for (int i = t; i < 512; i += 256) Vs[i] = d_V[bh * 512 + i];
    for (int i = t; i < 1024; i += 256) {
        int ky = i >> 6, w = i & 63; float s, c;
        sincospif((float)(ky * w) * (1.0f / 32.0f), &s, &c);
        tw[i] = make_float2(c, s);
    }
    __syncthreads();
    float ss = 0.f, ss2 = 0.f;
#pragma unroll
    for (int r = 0; r < 8; r++) {
        int oi = t + r * 256; int w = oi >> 5, o = oi & 31;
        float acc = 0.f;
#pragma unroll
        for (int ky = 0; ky < 16; ky++) {
            float2 v = Vs[ky * 32 + o]; float2 tv = tw[ky * 64 + w];
            float term = v.x * tv.x - v.y * tv.y;
            acc += (ky == 0) ? term : 2.0f * term;
        }
        acc *= 0.125f;
        x1s[w * 33 + o] = acc;
        ss += acc; ss2 += acc * acc;
    }
    sh1[t] = ss; sh2[t] = ss2; __syncthreads();
    for (int o = 128; o > 0; o >>= 1) {
        if (t < o) { sh1[t] += sh1[t + o]; sh2[t] += sh2[t + o]; }
        __syncthreads();
    }
    if (t == 0) {
        float m = sh1[0] * (1.0f / 2048.0f);
        float var = sh2[0] * (1.0f / 2048.0f) - m * m;
        mr[0] = m; mr[1] = rsqrtf(var + 1e-5f);
    }
    __syncthreads();
    float m = mr[0], rs = mr[1];
    for (int i = t; i < 2048; i += 256) { w1s[i] = w1[i]; w2s[i] = w2[i]; }
    if (t < 64) b1s[t] = b1[t];
    if (t < 32) b2s[t] = b2[t];
    for (int i = t; i < 2048; i += 256) {
        int w = i >> 5, o = i & 31;
        x1s[w * 33 + o] = (x1s[w * 33 + o] - m) * rs;
    }
    __syncthreads();
    int pix = t & 63, kq = t >> 6;
#pragma unroll
    for (int kk = 0; kk < 16; kk++) {
        int k = kq * 16 + kk;
        float a = b1s[k];
#pragma unroll
        for (int c = 0; c < 32; c++) a += x1s[pix * 33 + c] * w1s[c * 64 + k];
        hsm[pix * 65 + k] = gelu_f(a);
    }
    __syncthreads();
    {
        int js = kq * 8;
        float o[8];
#pragma unroll
        for (int j = 0; j < 8; j++) o[j] = b2s[js + j];
        for (int k = 0; k < 64; k++) {
            float hv = hsm[pix * 65 + k];
#pragma unroll
            for (int j = 0; j < 8; j++) o[j] += hv * w2s[k * 32 + js + j];
        }
#pragma unroll
        for (int j = 0; j < 8; j++) x1s[pix * 33 + js + j] = o[j];
    }
    __syncthreads();
    for (int i = t; i < 2048; i += 256)
        d_x1b[bh * 2048 + i] = x1s[(i >> 5) * 33 + (i & 31)];
}

// ---------------- MLP on xn -> d_x2, fused stats(slot2) ----------------
__global__ void __launch_bounds__(128) mlp1_kernel(const float* w1, const float* b1,
                                                   const float* w2, const float* b2) {
    int t = threadIdx.x;   // 128
    __shared__ float w1s[2048], w2s[2048], b1s[64], b2s[32];
    __shared__ float sh1[128], sh2[128];
    for (int i = t; i < 2048; i += 128) { w1s[i] = w1[i]; w2s[i] = w2[i]; }
    if (t < 64) b1s[t] = b1[t];
    if (t < 32) b2s[t] = b2[t];
    __syncthreads();
    int p = blockIdx.x * 128 + t;   // grid 128
    float x[32];
#pragma unroll
    for (int c = 0; c < 32; c++) x[c] = d_xn[p * 32 + c];
    float o[32];
#pragma unroll
    for (int j = 0; j < 32; j++) o[j] = b2s[j];
    for (int k = 0; k < 64; k++) {
        float a = b1s[k];
#pragma unroll
        for (int c = 0; c < 32; c++) a += x[c] * w1s[c * 64 + k];
        a = gelu_f(a);
#pragma unroll
        for (int j = 0; j < 32; j++) o[j] += a * w2s[k * 32 + j];
    }
    float ss = 0.f, ss2 = 0.f;
#pragma unroll
    for (int j = 0; j < 32; j++) {
        d_x2[p * 32 + j] = o[j];
        ss += o[j]; ss2 += o[j] * o[j];
    }
    sh1[t] = ss; sh2[t] = ss2; __syncthreads();
    int half = t & 64;
    int l = t & 63;
    for (int off = 32; off > 0; off >>= 1) {
        if (l < off) { sh1[half + l] += sh1[half + l + off]; sh2[half + l] += sh2[half + l + off]; }
        __syncthreads();
    }
    if (l == 0) {
        int row = blockIdx.x * 2 + (half >> 6);
        float m = sh1[half] * (1.0f / 2048.0f);
        float var = sh2[half] * (1.0f / 2048.0f) - m * m;
        d_stats[1024 + row] = m;
        d_stats[1024 + 256 + row] = rsqrtf(var + 1e-5f);
    }
}

// ---------------- edge hidden h = gelu(attr @ kw1 + kb1), fp16 out ----------------
__global__ void edgehid_kernel(const float* attr, const float* w1, const float* b1) {
    int e0 = blockIdx.x * 64;   // 2048 blocks
    int t = threadIdx.x;        // 256
    __shared__ float at[384], w1s[384], b1s[64];
    for (int i = t; i < 384; i += 256) { at[i] = attr[e0 * 6 + i]; w1s[i] = w1[i]; }
    if (t < 64) b1s[t] = b1[t];
    __syncthreads();
#pragma unroll
    for (int r = 0; r < 16; r++) {
        int i = t + r * 256; int el = i >> 6, k = i & 63;
        float a = b1s[k];
#pragma unroll
        for (int d = 0; d < 6; d++) a += at[el * 6 + d] * w1s[d * 64 + k];
        d_hh[(long long)(e0 + el) * 64 + k] = __float2half_rn(gelu_f(a));
    }
}

// ---------------- tensor-core g GEMM: d_gh = xnh[16384,32] @ w2h[32,2048] ----------------
__global__ void __launch_bounds__(256) gemm_gh_kernel() {
    int bm = blockIdx.x;    // 128 row blocks
    int bn = blockIdx.y;    // 16 col blocks
    int t = threadIdx.x;    // 256 = 8 warps
    int w = t >> 5, lane = t & 31;
    __shared__ __align__(16) char smemraw[32768];
    __half* Ah = (__half*)smemraw;              // [128][40] pitch 80B
    __half* Bh = (__half*)(smemraw + 10240);    // [32][136] pitch 272B
    __half* Cs = (__half*)smemraw;              // [128][128] (after barrier)

    {
        const int4* ap = (const int4*)(d_xnh + (long long)bm * 128 * 32);
        for (int i = t; i < 512; i += 256) {
            int4 v = ap[i];
            int r = i >> 2, c4 = i & 3;
            *(int4*)&Ah[r * 40 + c4 * 8] = v;
        }
    }
    {
        for (int i = t; i < 512; i += 256) {
            int r = i >> 4, c8 = i & 15;
            int4 v = *(const int4*)(d_w2h + r * 2048 + bn * 128 + c8 * 8);
            *(int4*)&Bh[r * 136 + c8 * 8] = v;
        }
    }
    __syncthreads();

    float acc[16][4];
#pragma unroll
    for (int nt = 0; nt < 16; nt++) {
        acc[nt][0] = 0.f; acc[nt][1] = 0.f; acc[nt][2] = 0.f; acc[nt][3] = 0.f;
    }
    unsigned abase = smem_u32(Ah) + w * 16 * 80;
    unsigned bbase = smem_u32(Bh);
    int grp = lane >> 3, rowi = lane & 7;
#pragma unroll
    for (int ks = 0; ks < 2; ks++) {
        unsigned a0, a1, a2, a3;
        unsigned aaddr = abase + (lane & 15) * 80 + ks * 32 + (lane >> 4) * 16;
        asm volatile("ldmatrix.sync.aligned.m8n8.x4.shared.b16 {%0,%1,%2,%3}, [%4];"
                     : "=r"(a0), "=r"(a1), "=r"(a2), "=r"(a3) : "r"(aaddr));
#pragma unroll
        for (int np = 0; np < 8; np++) {
            unsigned baddr = bbase + (unsigned)((ks * 16 + (grp & 1) * 8 + rowi) * 272
                                                + (np * 2 + (grp >> 1)) * 16);
            unsigned r0, r1, r2, r3;
            asm volatile("ldmatrix.sync.aligned.m8n8.x4.trans.shared.b16 {%0,%1,%2,%3}, [%4];"
                         : "=r"(r0), "=r"(r1), "=r"(r2), "=r"(r3) : "r"(baddr));
            asm volatile(
                "mma.sync.aligned.m16n8k16.row.col.f32.f16.f16.f32 "
                "{%0,%1,%2,%3}, {%4,%5,%6,%7}, {%8,%9}, {%0,%1,%2,%3};"
                : "+f"(acc[np * 2][0]), "+f"(acc[np * 2][1]),
                  "+f"(acc[np * 2][2]), "+f"(acc[np * 2][3])
                : "r"(a0), "r"(a1), "r"(a2), "r"(a3), "r"(r0), "r"(r1));
            asm volatile(
                "mma.sync.aligned.m16n8k16.row.col.f32.f16.f16.f32 "
                "{%0,%1,%2,%3}, {%4,%5,%6,%7}, {%8,%9}, {%0,%1,%2,%3};"
                : "+f"(acc[np * 2 + 1][0]), "+f"(acc[np * 2 + 1][1]),
                  "+f"(acc[np * 2 + 1][2]), "+f"(acc[np * 2 + 1][3])
                : "r"(a0), "r"(a1), "r"(a2), "r"(a3), "r"(r2), "r"(r3));
        }
    }
    __syncthreads();
    {
        int r0 = lane >> 2;
#pragma unroll
        for (int nt = 0; nt < 16; nt++) {
            int col = nt * 8 + (lane & 3) * 2;
            *(__half2*)&Cs[(w * 16 + r0) * 128 + col] =
                __floats2half2_rn(acc[nt][0], acc[nt][1]);
            *(__half2*)&Cs[(w * 16 + r0 + 8) * 128 + col] =
                __floats2half2_rn(acc[nt][2], acc[nt][3]);
        }
    }
    __syncthreads();
    {
        __half* gp = d_gh + (long long)bm * 128 * 2048 + bn * 128;
        for (int i = t; i < 2048; i += 256) {
            int r = i >> 4, c8 = i & 15;
            *(int4*)(gp + (long long)r * 2048 + c8 * 8) = *(int4*)&Cs[r * 128 + c8 * 8];
        }
    }
}

// ---------------- per-src msg via mma.m16n8k16; direct d_eid loads ----------------
__global__ void __launch_bounds__(128) edgemsg_kernel(const float* __restrict__ kb2) {
    int node = blockIdx.x;   // 4096
    int t = threadIdx.x;
    int wid = t >> 5, lane = t & 31;   // wid == b
    int s0 = d_offA[node], s1 = d_offA[node + 1];
    if (s0 == s1) return;
    __shared__ __align__(16) __half gsm[4][64 * 40];   // [b][k row][o], pitch 80B
    __shared__ __align__(16) __half hsm[16 * 72];      // [edge][k], pitch 144B
    __shared__ float xsrc[128];
    __shared__ float xbs[128];

    {
        const int4* gp = (const int4*)(d_gh + (long long)(wid * NND + node) * 2048);
#pragma unroll
        for (int i = 0; i < 8; i++) {
            int idx = i * 32 + lane;
            int4 v = gp[idx];
            int r = idx >> 2, c4 = idx & 3;
            *(int4*)&gsm[wid][r * 40 + c4 * 8] = v;
        }
    }
    xsrc[t] = d_xn[(wid * NND + node) * 32 + lane];
    __syncwarp();

    uint2 bf[16];
    {
        unsigned gb = smem_u32(&gsm[wid][0]);
        int grp = lane >> 3, rowi = lane & 7;
#pragma unroll
        for (int ks = 0; ks < 4; ks++) {
#pragma unroll
            for (int np = 0; np < 2; np++) {
                unsigned addr = gb + (unsigned)((ks * 16 + (grp & 1) * 8 + rowi) * 80
                                                + (np * 2 + (grp >> 1)) * 16);
                unsigned r0, r1, r2, r3;
                asm volatile("ldmatrix.sync.aligned.m8n8.x4.trans.shared.b16 {%0,%1,%2,%3}, [%4];"
                             : "=r"(r0), "=r"(r1), "=r"(r2), "=r"(r3) : "r"(addr));
                bf[ks * 4 + np * 2 + 0] = make_uint2(r0, r1);
                bf[ks * 4 + np * 2 + 1] = make_uint2(r2, r3);
            }
        }
    }
    float xb = 0.f;
#pragma unroll
    for (int c = 0; c < 32; c++) xb += xsrc[wid * 32 + c] * kb2[c * 32 + lane];
    xbs[t] = xb;
    __syncwarp();
    float xb0[4], xb1[4];
#pragma unroll
    for (int nt = 0; nt < 4; nt++) {
        int col = nt * 8 + (lane & 3) * 2;
        xb0[nt] = xbs[wid * 32 + col];
        xb1[nt] = xbs[wid * 32 + col + 1];
    }
    int r0 = lane >> 2, r1 = r0 + 8;
    unsigned hbase = smem_u32(hsm);
    __half2* msg2 = (__half2*)d_msg;

    for (int ec = s0; ec < s1; ec += 16) {
        int nch = min(16, s1 - ec);
        __syncthreads();   // protect hsm from previous iteration's readers
        {   // load H tile [16 x 64] halves; edge id read directly (L2-hot broadcast x8)
            int r = t >> 3, c8 = t & 7;
            int4 hv = make_int4(0, 0, 0, 0);
            if (r < nch) {
                int e = d_eid[ec + r];
                hv = *(const int4*)(d_hh + (long long)e * 64 + c8 * 8);
            }
            *(int4*)(hsm + r * 72 + c8 * 8) = hv;
        }
        // dst positions for this thread's two rows (independent of hsm; overlaps mma)
        int dpr0 = 0, dpr1 = 0;
        if (r0 < nch) dpr0 = d_eid[EED + d_eid[ec + r0]];
        if (r1 < nch) dpr1 = d_eid[EED + d_eid[ec + r1]];
        __syncthreads();
        float acc[4][4];
#pragma unroll
        for (int nt = 0; nt < 4; nt++) {
            acc[nt][0] = xb0[nt]; acc[nt][1] = xb1[nt];
            acc[nt][2] = xb0[nt]; acc[nt][3] = xb1[nt];
        }
#pragma unroll
        for (int ks = 0; ks < 4; ks++) {
            unsigned a0, a1, a2, a3;
            unsigned addr = hbase + (lane & 15) * 144 + ks * 32 + (lane >> 4) * 16;
            asm volatile("ldmatrix.sync.aligned.m8n8.x4.shared.b16 {%0,%1,%2,%3}, [%4];"
                         : "=r"(a0), "=r"(a1), "=r"(a2), "=r"(a3) : "r"(addr));
#pragma unroll
            for (int nt = 0; nt < 4; nt++) {
                int f = ks * 4 + nt;
                asm volatile(
                    "mma.sync.aligned.m16n8k16.row.col.f32.f16.f16.f32 "
                    "{%0,%1,%2,%3}, {%4,%5,%6,%7}, {%8,%9}, {%0,%1,%2,%3};"
                    : "+f"(acc[nt][0]), "+f"(acc[nt][1]), "+f"(acc[nt][2]), "+f"(acc[nt][3])
                    : "r"(a0), "r"(a1), "r"(a2), "r"(a3), "r"(bf[f].x), "r"(bf[f].y));
            }
        }
#pragma unroll
        for (int nt = 0; nt < 4; nt++) {
            int h2idx = nt * 4 + (lane & 3);
            if (r0 < nch)
                msg2[((long long)dpr0 * 4 + wid) * 16 + h2idx] =
                    __floats2half2_rn(acc[nt][0], acc[nt][1]);
            if (r1 < nch)
                msg2[((long long)dpr1 * 4 + wid) * 16 + h2idx] =
                    __floats2half2_rn(acc[nt][2], acc[nt][3]);
        }
    }
}

// ---------------- dst gather (unroll 8) + root + bias + combine + gelu; re-zero cnt/cur ----------------
__global__ void __launch_bounds__(128) final_kernel(const float* __restrict__ root,
                                                    const float* __restrict__ gbias,
                                                    float* __restrict__ out) {
    int n = blockIdx.x;   // 4096
    int t = threadIdx.x; int b = t >> 5, o = t & 31;
    __shared__ float roots[1024];
    __shared__ float xs[128];
    for (int i = t; i < 1024; i += 128) roots[i] = root[i];
    xs[t] = d_xn[(b * NND + n) * 32 + o];
    __syncthreads();
    float acc = gbias[o];
#pragma unroll
    for (int c = 0; c < 32; c++) acc += xs[b * 32 + c] * roots[c * 32 + o];
    int s0 = d_offA[(NND + 1) + n], s1 = d_offA[(NND + 1) + n + 1];
    const __half* mp = d_msg;
    int i = s0;
    float a[8] = {0.f, 0.f, 0.f, 0.f, 0.f, 0.f, 0.f, 0.f};
    for (; i + 8 <= s1; i += 8) {
#pragma unroll
        for (int u = 0; u < 8; u++)
            a[u] += __half2float(mp[((long long)(i + u) * 4 + b) * 32 + o]);
    }
    for (; i < s1; i++) a[0] += __half2float(mp[((long long)i * 4 + b) * 32 + o]);
    acc += ((a[0] + a[1]) + (a[2] + a[3])) + ((a[4] + a[5]) + (a[6] + a[7]));
    int p = b * NND + n; int row = p >> 6;
    float x2v = (d_x2[(long long)p * 32 + o] - d_stats[1024 + row]) * d_stats[1024 + 256 + row];
    float s = d_x1b[(long long)p * 32 + o] + x2v + acc;
    out[(long long)p * 32 + o] = gelu_f(s);
    // re-zero CSR counters for the next graph replay (zero-init at load covers the first run)
    int gid = n * 128 + t;
    if (gid < 2 * NND) d_cnt[gid] = 0;
    else if (gid < 4 * NND) d_cur[gid - 2 * NND] = 0;
}

// ---------------- launch (fork/join stream-parallel graph) ----------------
extern "C" void kernel_launch(void* const* d_in, const int* in_sizes, int n_in,
                              void* d_out, int out_size) {
    const float* nodes  = (const float*)d_in[0];
    const void*  eidx   = d_in[1];
    const float* eattr  = (const float*)d_in[2];
    const float* w1re   = (const float*)d_in[3];
    const float* w1im   = (const float*)d_in[4];
    const float* w2re   = (const float*)d_in[5];
    const float* w2im   = (const float*)d_in[6];
    const float* mlp_w1 = (const float*)d_in[7];
    const float* mlp_b1 = (const float*)d_in[8];
    const float* mlp_w2 = (const float*)d_in[9];
    const float* mlp_b2 = (const float*)d_in[10];
    const float* wm_w1  = (const float*)d_in[11];
    const float* wm_b1  = (const float*)d_in[12];
    const float* wm_w2  = (const float*)d_in[13];
    const float* wm_b2  = (const float*)d_in[14];
    const float* kw1    = (const float*)d_in[15];
    const float* kb1    = (const float*)d_in[16];
    const float* kw2    = (const float*)d_in[17];
    const float* kb2    = (const float*)d_in[18];
    const float* root   = (const float*)d_in[19];
    const float* gbias  = (const float*)d_in[20];
    float* out = (float*)d_out;

    static cudaStream_t sA = nullptr, sB = nullptr;
    static cudaEvent_t evRoot, evN, evA, evB, evM;
    if (sA == nullptr) {
        cudaStreamCreateWithFlags(&sA, cudaStreamNonBlocking);
        cudaStreamCreateWithFlags(&sB, cudaStreamNonBlocking);
        cudaEventCreateWithFlags(&evRoot, cudaEventDisableTiming);
        cudaEventCreateWithFlags(&evN, cudaEventDisableTiming);
        cudaEventCreateWithFlags(&evA, cudaEventDisableTiming);
        cudaEventCreateWithFlags(&evB, cudaEventDisableTiming);
        cudaEventCreateWithFlags(&evM, cudaEventDisableTiming);
    }

    // fork point
    cudaEventRecord(evRoot, 0);
    cudaStreamWaitEvent(sA, evRoot, 0);
    cudaStreamWaitEvent(sB, evRoot, 0);

    // stream A: CSR build (probe folded into convhist; cnt/cur pre-zeroed by previous run)
    convhist_kernel<<<512, 256, 0, sA>>>(eidx);
    scan_kernel<<<2, 1024, 0, sA>>>();
    fill_kernel<<<512, 256, 0, sA>>>();
    cudaEventRecord(evA, sA);

    // stream B: w2 convert first (gates gemm), then edge hidden
    w2conv_kernel<<<256, 256, 0, sB>>>(kw2);
    edgehid_kernel<<<2048, 256, 0, sB>>>(eattr, kw1, kb1);

    // stream 0: fused normalize of input
    statsnorm_kernel<<<256, 256>>>(nodes);
    cudaEventRecord(evN, 0);

    // stream A: pointwise MLP branch
    cudaStreamWaitEvent(sA, evN, 0);
    mlp1_kernel<<<128, 128, 0, sA>>>(wm_w1, wm_b1, wm_w2, wm_b2);   // + stats slot2
    cudaEventRecord(evM, sA);

    // stream B: tensor-core g GEMM, then edge msg
    cudaStreamWaitEvent(sB, evN, 0);
    {
        dim3 g(128, 16);
        gemm_gh_kernel<<<g, 256, 0, sB>>>();
    }
    cudaStreamWaitEvent(sB, evA, 0);
    edgemsg_kernel<<<4096, 128, 0, sB>>>(kb2);
    cudaEventRecord(evB, sB);

    // stream 0: spectral branch (invW fused with inorm+MLP -> d_x1b)
    fwdW_kernel<<<256, 256>>>();
    fwdH_kernel<<<128, 512>>>();
    modemix_kernel<<<512, 128>>>(w1re, w1im, w2re, w2im);
    invH_kernel<<<256, 512>>>();
    invWmlp_kernel<<<256, 256>>>(mlp_w1, mlp_b1, mlp_w2, mlp_b2);

    // join: final combine
    cudaStreamWaitEvent(0, evB, 0);
    cudaStreamWaitEvent(0, evM, 0);
    final_kernel<<<4096, 128>>>(root, gbias, out);
}

// round 17
// speedup vs baseline: 2.2903x; 1.0382x over previous
#include <cuda_runtime.h>
#include <cuda_fp16.h>
#include <math.h>

#define BB 4
#define NND 4096
#define EED 131072

// ---------------- scratch ----------------
__device__ float  d_stats[3 * 512];          // slot2 @1024 used for x2 stats
__device__ float  d_xn  [BB * NND * 32];
__device__ __half d_xnh [BB * NND * 32];
__device__ __half d_w2h [32 * 2048];               // [c][k*32+o] fp16
__device__ float2 d_T   [BB * 64 * 16 * 32];
__device__ float2 d_Xft [BB * 32 * 16 * 32];
__device__ float2 d_oft [BB * 32 * 16 * 32];
__device__ float2 d_V   [BB * 64 * 16 * 32];
__device__ float  d_x1b [BB * NND * 32];
__device__ float  d_x2  [BB * NND * 32];
__device__ __half d_hh  [(long long)EED * 64];
__device__ __half d_gh  [(long long)BB * NND * 64 * 32];   // linear [row][k*32+o]
__device__ __half d_msg [(long long)EED * BB * 32];        // fp16, indexed by dst-CSR position
__device__ int    d_esrc[EED];
__device__ int    d_edst[EED];
__device__ int    d_cnt [2 * NND];   // zero-initialized at load; re-zeroed by final_kernel
__device__ int    d_offA[2 * (NND + 1)];
__device__ int    d_cur [2 * NND];   // ditto
__device__ int    d_eid [2 * EED];   // [0:E) src-CSR edge ids; [E:2E) dstpos per edge

__device__ __forceinline__ float gelu_f(float x) {
    return 0.5f * x * (1.0f + erff(x * 0.70710678118654752f));
}
__device__ __forceinline__ unsigned smem_u32(const void* p) {
    return (unsigned)__cvta_generic_to_shared(p);
}

// ---------------- convert + histogram, with per-block dtype probe ----------------
__global__ void convhist_kernel(const void* ei) {
    int t = threadIdx.x;   // 256
    __shared__ int s;
    if (t == 0) s = 0;
    __syncthreads();
    {
        const int* w = (const int*)ei;
        int nz = 0;
        for (int k = t; k < 1024; k += 256) nz |= w[2 * k + 1];
        if (nz) atomicOr(&s, 1);
    }
    __syncthreads();
    int is64 = (s == 0);
    int e = blockIdx.x * 256 + t;  // 512x256
    int sv, dv;
    if (is64) {
        const long long* p = (const long long*)ei;
        sv = (int)p[e]; dv = (int)p[EED + e];
    } else {
        const int* p = (const int*)ei;
        sv = p[e]; dv = p[EED + e];
    }
    d_esrc[e] = sv; d_edst[e] = dv;
    atomicAdd(&d_cnt[sv], 1);
    atomicAdd(&d_cnt[NND + dv], 1);
}

__global__ void scan_kernel() {
    int a = blockIdx.x;   // 0=src, 1=dst
    int t = threadIdx.x;  // 1024
    const int* cnt = d_cnt + a * NND;
    int* off = d_offA + a * (NND + 1);
    int v0 = cnt[t * 4], v1 = cnt[t * 4 + 1], v2 = cnt[t * 4 + 2], v3 = cnt[t * 4 + 3];
    int s = v0 + v1 + v2 + v3;
    __shared__ int sh[1024];
    sh[t] = s; __syncthreads();
    for (int o1 = 1; o1 < 1024; o1 <<= 1) {
        int v = (t >= o1) ? sh[t - o1] : 0;
        __syncthreads();
        sh[t] += v;
        __syncthreads();
    }
    int excl = sh[t] - s;
    off[t * 4] = excl; off[t * 4 + 1] = excl + v0;
    off[t * 4 + 2] = excl + v0 + v1; off[t * 4 + 3] = excl + v0 + v1 + v2;
    if (t == 1023) off[NND] = sh[1023];
}

__global__ void fill_kernel() {
    int e = blockIdx.x * 256 + threadIdx.x;    // 512x256
    int s = d_esrc[e], d2 = d_edst[e];
    int p = atomicAdd(&d_cur[s], 1);
    d_eid[d_offA[s] + p] = e;
    int q = atomicAdd(&d_cur[NND + d2], 1);
    d_eid[EED + e] = d_offA[(NND + 1) + d2] + q;   // dstpos of edge e
}

// ---------------- fused instance-norm: stats + normalize, emits fp32 + fp16 ----------------
__global__ void statsnorm_kernel(const float* __restrict__ nodes) {
    int row = blockIdx.x;            // 256
    int t = threadIdx.x;             // 256
    __shared__ float xs[2048];
    __shared__ float sh1[256], sh2[256];
    __shared__ float mr[2];
    const float* p = nodes + row * 2048;
    float s = 0.f, s2 = 0.f;
#pragma unroll
    for (int i = 0; i < 8; i++) {
        float v = p[t + i * 256];
        xs[t + i * 256] = v;
        s += v; s2 += v * v;
    }
    sh1[t] = s; sh2[t] = s2; __syncthreads();
    for (int o = 128; o > 0; o >>= 1) {
        if (t < o) { sh1[t] += sh1[t + o]; sh2[t] += sh2[t + o]; }
        __syncthreads();
    }
    if (t == 0) {
        float m = sh1[0] * (1.0f / 2048.0f);
        float var = sh2[0] * (1.0f / 2048.0f) - m * m;
        mr[0] = m; mr[1] = rsqrtf(var + 1e-5f);
    }
    __syncthreads();
    float m = mr[0], rs = mr[1];
#pragma unroll
    for (int i = 0; i < 8; i++) {
        float v = (xs[t + i * 256] - m) * rs;
        d_xn [row * 2048 + t + i * 256] = v;
        d_xnh[row * 2048 + t + i * 256] = __float2half_rn(v);
    }
}

// ---------------- w2 transpose+convert ----------------
__global__ void w2conv_kernel(const float* __restrict__ kw2) {
    int i = blockIdx.x * 256 + threadIdx.x;   // 256x256 = 65536
    int c = i >> 11, col = i & 2047;
    d_w2h[i] = __float2half_rn(kw2[(col >> 5) * 1024 + c * 32 + (col & 31)]);
}

// ---------------- forward DFT over W (ky 0..15) ----------------
__global__ void fwdW_kernel() {
    int bh = blockIdx.x;            // 256
    int t = threadIdx.x;            // 256
    __shared__ float  xs[2048];
    __shared__ float2 tw[1024];
    for (int i = t; i < 2048; i += 256) xs[i] = d_xn[bh * 2048 + i];
    for (int i = t; i < 1024; i += 256) {
        int ky = i >> 6, w = i & 63; float s, c;
        sincospif(-(float)(ky * w) * (1.0f / 32.0f), &s, &c);
        tw[i] = make_float2(c, s);
    }
    __syncthreads();
#pragma unroll
    for (int r = 0; r < 2; r++) {
        int oi = t + r * 256; int ky = oi >> 5, c = oi & 31;
        float re = 0.f, im = 0.f;
#pragma unroll 8
        for (int w = 0; w < 64; w++) {
            float xv = xs[w * 32 + c]; float2 tv = tw[ky * 64 + w];
            re += xv * tv.x; im += xv * tv.y;
        }
        d_T[(bh * 16 + ky) * 32 + c] = make_float2(re, im);
    }
}

// ---------------- forward DFT over H (kx 0..15, 48..63), *1/64 ----------------
__global__ void fwdH_kernel() {
    int b = blockIdx.x >> 5, kxi = blockIdx.x & 31;   // 128 blocks
    int kx = (kxi < 16) ? kxi : kxi + 32;
    int t = threadIdx.x;                               // 512
    __shared__ float2 tw[64];
    if (t < 64) { float s, c; sincospif(-(float)(kx * t) * (1.0f / 32.0f), &s, &c); tw[t] = make_float2(c, s); }
    __syncthreads();
    int ky = t >> 5, c = t & 31;
    float re = 0.f, im = 0.f;
#pragma unroll 4
    for (int h = 0; h < 64; h++) {
        float2 v = d_T[((b * 64 + h) * 16 + ky) * 32 + c];
        float2 w = tw[h];
        re += v.x * w.x - v.y * w.y;
        im += v.x * w.y + v.y * w.x;
    }
    d_Xft[((b * 32 + kxi) * 16 + ky) * 32 + c] = make_float2(re * (1.0f / 64.0f), im * (1.0f / 64.0f));
}

// ---------------- complex channel mix per (kx,ky) ----------------
__global__ void modemix_kernel(const float* w1re, const float* w1im,
                               const float* w2re, const float* w2im) {
    int kxi = blockIdx.x >> 4, ky = blockIdx.x & 15;   // 512 blocks
    int xm = (kxi < 16) ? kxi : kxi - 16;
    const float* wre = (kxi < 16) ? w1re : w2re;
    const float* wim = (kxi < 16) ? w1im : w2im;
    int t = threadIdx.x;                                // 128
    __shared__ float wr[1024], wi[1024];
    __shared__ float2 Xs[128];
    for (int i = t; i < 1024; i += 128) {
        int off = i * 256 + xm * 16 + ky;
        wr[i] = wre[off]; wi[i] = wim[off];
    }
    { int b = t >> 5, c = t & 31; Xs[t] = d_Xft[((b * 32 + kxi) * 16 + ky) * 32 + c]; }
    __syncthreads();
    int b = t >> 5, o = t & 31;
    float re = 0.f, im = 0.f;
#pragma unroll
    for (int i = 0; i < 32; i++) {
        float2 xv = Xs[b * 32 + i];
        float wrv = wr[i * 32 + o], wiv = wi[i * 32 + o];
        re += xv.x * wrv - xv.y * wiv;
        im += xv.x * wiv + xv.y * wrv;
    }
    d_oft[((b * 32 + kxi) * 16 + ky) * 32 + o] = make_float2(re, im);
}

// ---------------- inverse DFT over H, *1/8 ----------------
__global__ void invH_kernel() {
    int b = blockIdx.x >> 6, h = blockIdx.x & 63;   // 256 blocks
    int t = threadIdx.x;                             // 512
    __shared__ float2 tw[32];
    if (t < 32) {
        int kx = (t < 16) ? t : t + 32; float s, c;
        sincospif((float)(kx * h) * (1.0f / 32.0f), &s, &c);
        tw[t] = make_float2(c, s);
    }
    __syncthreads();
    int ky = t >> 5, o = t & 31;
    float re = 0.f, im = 0.f;
#pragma unroll 4
    for (int k = 0; k < 32; k++) {
        float2 v = d_oft[((b * 32 + k) * 16 + ky) * 32 + o];
        float2 w = tw[k];
        re += v.x * w.x - v.y * w.y;
        im += v.x * w.y + v.y * w.x;
    }
    d_V[((b * 64 + h) * 16 + ky) * 32 + o] = make_float2(re * 0.125f, im * 0.125f);
}

// ---------------- inverse C2R over W + in-block instance-norm + MLP -> d_x1b ----------------
__global__ void __launch_bounds__(256) invWmlp_kernel(const float* __restrict__ w1,
                                                      const float* __restrict__ b1,
                                                      const float* __restrict__ w2,
                                                      const float* __restrict__ b2) {
    int bh = blockIdx.x; int t = threadIdx.x;   // 256 x 256
    __shared__ __align__(16) char ov[33664];    // overlay region
    __shared__ float x1s[64 * 33];              // [w][c], pitch 33
    __shared__ float mr[2];
    // overlay A (DFT phase)
    float2* Vs  = (float2*)ov;             // 4096B
    float2* tw  = (float2*)(ov + 4096);    // 8192B
    float*  sh1 = (float*)(ov + 12288);    // 1024B
    float*  sh2 = (float*)(ov + 13312);    // 1024B
    // overlay B (MLP phase)
    float* w1s = (float*)ov;               // 8192B
    float* w2s = (float*)(ov + 8192);      // 8192B
    float* hsm = (float*)(ov + 16384);     // 16640B
    float* b1s = (float*)(ov + 33024);     // 256B
    float* b2s = (float*)(ov + 33280);     // 128B

    for (int i = t; i < 512; i += 256) Vs[i] = d_V[bh * 512 + i];
    for (int i = t; i < 1024; i += 256) {
        int ky = i >> 6, w = i & 63; float s, c;
        sincospif((float)(ky * w) * (1.0f / 32.0f), &s, &c);
        tw[i] = make_float2(c, s);
    }
    __syncthreads();
    float ss = 0.f, ss2 = 0.f;
#pragma unroll
    for (int r = 0; r < 8; r++) {
        int oi = t + r * 256; int w = oi >> 5, o = oi & 31;
        float acc = 0.f;
#pragma unroll
        for (int ky = 0; ky < 16; ky++) {
            float2 v = Vs[ky * 32 + o]; float2 tv = tw[ky * 64 + w];
            float term = v.x * tv.x - v.y * tv.y;
            acc += (ky == 0) ? term : 2.0f * term;
        }
        acc *= 0.125f;
        x1s[w * 33 + o] = acc;
        ss += acc; ss2 += acc * acc;
    }
    sh1[t] = ss; sh2[t] = ss2; __syncthreads();
    for (int o = 128; o > 0; o >>= 1) {
        if (t < o) { sh1[t] += sh1[t + o]; sh2[t] += sh2[t + o]; }
        __syncthreads();
    }
    if (t == 0) {
        float m = sh1[0] * (1.0f / 2048.0f);
        float var = sh2[0] * (1.0f / 2048.0f) - m * m;
        mr[0] = m; mr[1] = rsqrtf(var + 1e-5f);
    }
    __syncthreads();
    float m = mr[0], rs = mr[1];
    for (int i = t; i < 2048; i += 256) { w1s[i] = w1[i]; w2s[i] = w2[i]; }
    if (t < 64) b1s[t] = b1[t];
    if (t < 32) b2s[t] = b2[t];
    for (int i = t; i < 2048; i += 256) {
        int w = i >> 5, o = i & 31;
        x1s[w * 33 + o] = (x1s[w * 33 + o] - m) * rs;
    }
    __syncthreads();
    int pix = t & 63, kq = t >> 6;
#pragma unroll
    for (int kk = 0; kk < 16; kk++) {
        int k = kq * 16 + kk;
        float a = b1s[k];
#pragma unroll
        for (int c = 0; c < 32; c++) a += x1s[pix * 33 + c] * w1s[c * 64 + k];
        hsm[pix * 65 + k] = gelu_f(a);
    }
    __syncthreads();
    {
        int js = kq * 8;
        float o[8];
#pragma unroll
        for (int j = 0; j < 8; j++) o[j] = b2s[js + j];
        for (int k = 0; k < 64; k++) {
            float hv = hsm[pix * 65 + k];
#pragma unroll
            for (int j = 0; j < 8; j++) o[j] += hv * w2s[k * 32 + js + j];
        }
#pragma unroll
        for (int j = 0; j < 8; j++) x1s[pix * 33 + js + j] = o[j];
    }
    __syncthreads();
    for (int i = t; i < 2048; i += 256)
        d_x1b[bh * 2048 + i] = x1s[(i >> 5) * 33 + (i & 31)];
}

// ---------------- MLP on xn -> d_x2, fused stats(slot2) ----------------
__global__ void __launch_bounds__(128) mlp1_kernel(const float* w1, const float* b1,
                                                   const float* w2, const float* b2) {
    int t = threadIdx.x;   // 128
    __shared__ float w1s[2048], w2s[2048], b1s[64], b2s[32];
    __shared__ float sh1[128], sh2[128];
    for (int i = t; i < 2048; i += 128) { w1s[i] = w1[i]; w2s[i] = w2[i]; }
    if (t < 64) b1s[t] = b1[t];
    if (t < 32) b2s[t] = b2[t];
    __syncthreads();
    int p = blockIdx.x * 128 + t;   // grid 128
    float x[32];
#pragma unroll
    for (int c = 0; c < 32; c++) x[c] = d_xn[p * 32 + c];
    float o[32];
#pragma unroll
    for (int j = 0; j < 32; j++) o[j] = b2s[j];
    for (int k = 0; k < 64; k++) {
        float a = b1s[k];
#pragma unroll
        for (int c = 0; c < 32; c++) a += x[c] * w1s[c * 64 + k];
        a = gelu_f(a);
#pragma unroll
        for (int j = 0; j < 32; j++) o[j] += a * w2s[k * 32 + j];
    }
    float ss = 0.f, ss2 = 0.f;
#pragma unroll
    for (int j = 0; j < 32; j++) {
        d_x2[p * 32 + j] = o[j];
        ss += o[j]; ss2 += o[j] * o[j];
    }
    sh1[t] = ss; sh2[t] = ss2; __syncthreads();
    int half = t & 64;
    int l = t & 63;
    for (int off = 32; off > 0; off >>= 1) {
        if (l < off) { sh1[half + l] += sh1[half + l + off]; sh2[half + l] += sh2[half + l + off]; }
        __syncthreads();
    }
    if (l == 0) {
        int row = blockIdx.x * 2 + (half >> 6);
        float m = sh1[half] * (1.0f / 2048.0f);
        float var = sh2[half] * (1.0f / 2048.0f) - m * m;
        d_stats[1024 + row] = m;
        d_stats[1024 + 256 + row] = rsqrtf(var + 1e-5f);
    }
}

// ---------------- edge hidden h = gelu(attr @ kw1 + kb1), fp16 out ----------------
__global__ void edgehid_kernel(const float* attr, const float* w1, const float* b1) {
    int e0 = blockIdx.x * 64;   // 2048 blocks
    int t = threadIdx.x;        // 256
    __shared__ float at[384], w1s[384], b1s[64];
    for (int i = t; i < 384; i += 256) { at[i] = attr[e0 * 6 + i]; w1s[i] = w1[i]; }
    if (t < 64) b1s[t] = b1[t];
    __syncthreads();
#pragma unroll
    for (int r = 0; r < 16; r++) {
        int i = t + r * 256; int el = i >> 6, k = i & 63;
        float a = b1s[k];
#pragma unroll
        for (int d = 0; d < 6; d++) a += at[el * 6 + d] * w1s[d * 64 + k];
        d_hh[(long long)(e0 + el) * 64 + k] = __float2half_rn(gelu_f(a));
    }
}

// ---------------- tensor-core g GEMM: d_gh = xnh[16384,32] @ w2h[32,2048] ----------------
__global__ void __launch_bounds__(256) gemm_gh_kernel() {
    int bm = blockIdx.x;    // 128 row blocks
    int bn = blockIdx.y;    // 16 col blocks
    int t = threadIdx.x;    // 256 = 8 warps
    int w = t >> 5, lane = t & 31;
    __shared__ __align__(16) char smemraw[32768];
    __half* Ah = (__half*)smemraw;              // [128][40] pitch 80B
    __half* Bh = (__half*)(smemraw + 10240);    // [32][136] pitch 272B
    __half* Cs = (__half*)smemraw;              // [128][128] (after barrier)

    {
        const int4* ap = (const int4*)(d_xnh + (long long)bm * 128 * 32);
        for (int i = t; i < 512; i += 256) {
            int4 v = ap[i];
            int r = i >> 2, c4 = i & 3;
            *(int4*)&Ah[r * 40 + c4 * 8] = v;
        }
    }
    {
        for (int i = t; i < 512; i += 256) {
            int r = i >> 4, c8 = i & 15;
            int4 v = *(const int4*)(d_w2h + r * 2048 + bn * 128 + c8 * 8);
            *(int4*)&Bh[r * 136 + c8 * 8] = v;
        }
    }
    __syncthreads();

    float acc[16][4];
#pragma unroll
    for (int nt = 0; nt < 16; nt++) {
        acc[nt][0] = 0.f; acc[nt][1] = 0.f; acc[nt][2] = 0.f; acc[nt][3] = 0.f;
    }
    unsigned abase = smem_u32(Ah) + w * 16 * 80;
    unsigned bbase = smem_u32(Bh);
    int grp = lane >> 3, rowi = lane & 7;
#pragma unroll
    for (int ks = 0; ks < 2; ks++) {
        unsigned a0, a1, a2, a3;
        unsigned aaddr = abase + (lane & 15) * 80 + ks * 32 + (lane >> 4) * 16;
        asm volatile("ldmatrix.sync.aligned.m8n8.x4.shared.b16 {%0,%1,%2,%3}, [%4];"
                     : "=r"(a0), "=r"(a1), "=r"(a2), "=r"(a3) : "r"(aaddr));
#pragma unroll
        for (int np = 0; np < 8; np++) {
            unsigned baddr = bbase + (unsigned)((ks * 16 + (grp & 1) * 8 + rowi) * 272
                                                + (np * 2 + (grp >> 1)) * 16);
            unsigned r0, r1, r2, r3;
            asm volatile("ldmatrix.sync.aligned.m8n8.x4.trans.shared.b16 {%0,%1,%2,%3}, [%4];"
                         : "=r"(r0), "=r"(r1), "=r"(r2), "=r"(r3) : "r"(baddr));
            asm volatile(
                "mma.sync.aligned.m16n8k16.row.col.f32.f16.f16.f32 "
                "{%0,%1,%2,%3}, {%4,%5,%6,%7}, {%8,%9}, {%0,%1,%2,%3};"
                : "+f"(acc[np * 2][0]), "+f"(acc[np * 2][1]),
                  "+f"(acc[np * 2][2]), "+f"(acc[np * 2][3])
                : "r"(a0), "r"(a1), "r"(a2), "r"(a3), "r"(r0), "r"(r1));
            asm volatile(
                "mma.sync.aligned.m16n8k16.row.col.f32.f16.f16.f32 "
                "{%0,%1,%2,%3}, {%4,%5,%6,%7}, {%8,%9}, {%0,%1,%2,%3};"
                : "+f"(acc[np * 2 + 1][0]), "+f"(acc[np * 2 + 1][1]),
                  "+f"(acc[np * 2 + 1][2]), "+f"(acc[np * 2 + 1][3])
                : "r"(a0), "r"(a1), "r"(a2), "r"(a3), "r"(r2), "r"(r3));
        }
    }
    __syncthreads();
    {
        int r0 = lane >> 2;
#pragma unroll
        for (int nt = 0; nt < 16; nt++) {
            int col = nt * 8 + (lane & 3) * 2;
            *(__half2*)&Cs[(w * 16 + r0) * 128 + col] =
                __floats2half2_rn(acc[nt][0], acc[nt][1]);
            *(__half2*)&Cs[(w * 16 + r0 + 8) * 128 + col] =
                __floats2half2_rn(acc[nt][2], acc[nt][3]);
        }
    }
    __syncthreads();
    {
        __half* gp = d_gh + (long long)bm * 128 * 2048 + bn * 128;
        for (int i = t; i < 2048; i += 256) {
            int r = i >> 4, c8 = i & 15;
            *(int4*)(gp + (long long)r * 2048 + c8 * 8) = *(int4*)&Cs[r * 128 + c8 * 8];
        }
    }
}

// ---------------- per-src msg via mma.m16n8k16; software-pipelined chunks ----------------
__global__ void __launch_bounds__(128) edgemsg_kernel(const float* __restrict__ kb2) {
    int node = blockIdx.x;   // 4096
    int t = threadIdx.x;
    int wid = t >> 5, lane = t & 31;   // wid == b
    int s0 = d_offA[node], s1 = d_offA[node + 1];
    if (s0 == s1) return;
    __shared__ __align__(16) __half gsm[4][64 * 40];   // [b][k row][o], pitch 80B
    __shared__ __align__(16) __half hsm[2][16 * 72];   // double-buffered [edge][k], pitch 144B
    __shared__ float xsrc[128];
    __shared__ float xbs[128];

    {
        const int4* gp = (const int4*)(d_gh + (long long)(wid * NND + node) * 2048);
#pragma unroll
        for (int i = 0; i < 8; i++) {
            int idx = i * 32 + lane;
            int4 v = gp[idx];
            int r = idx >> 2, c4 = idx & 3;
            *(int4*)&gsm[wid][r * 40 + c4 * 8] = v;
        }
    }
    xsrc[t] = d_xn[(wid * NND + node) * 32 + lane];
    __syncwarp();

    uint2 bf[16];
    {
        unsigned gb = smem_u32(&gsm[wid][0]);
        int grp = lane >> 3, rowi = lane & 7;
#pragma unroll
        for (int ks = 0; ks < 4; ks++) {
#pragma unroll
            for (int np = 0; np < 2; np++) {
                unsigned addr = gb + (unsigned)((ks * 16 + (grp & 1) * 8 + rowi) * 80
                                                + (np * 2 + (grp >> 1)) * 16);
                unsigned r0, r1, r2, r3;
                asm volatile("ldmatrix.sync.aligned.m8n8.x4.trans.shared.b16 {%0,%1,%2,%3}, [%4];"
                             : "=r"(r0), "=r"(r1), "=r"(r2), "=r"(r3) : "r"(addr));
                bf[ks * 4 + np * 2 + 0] = make_uint2(r0, r1);
                bf[ks * 4 + np * 2 + 1] = make_uint2(r2, r3);
            }
        }
    }
    float xb = 0.f;
#pragma unroll
    for (int c = 0; c < 32; c++) xb += xsrc[wid * 32 + c] * kb2[c * 32 + lane];
    xbs[t] = xb;
    __syncwarp();
    float xb0[4], xb1[4];
#pragma unroll
    for (int nt = 0; nt < 4; nt++) {
        int col = nt * 8 + (lane & 3) * 2;
        xb0[nt] = xbs[wid * 32 + col];
        xb1[nt] = xbs[wid * 32 + col + 1];
    }
    int r0 = lane >> 2, r1 = r0 + 8;
    int hr = t >> 3, hc8 = t & 7;          // H-tile load assignment
    __half2* msg2 = (__half2*)d_msg;

    int nchunks = (s1 - s0 + 15) >> 4;
    int cur = 0;
    int dpr0 = 0, dpr1 = 0;
    {   // prologue: stage chunk 0 into hsm[0], prefetch its dst positions
        int nch = min(16, s1 - s0);
        int4 hv = make_int4(0, 0, 0, 0);
        if (hr < nch) {
            int e = d_eid[s0 + hr];
            hv = *(const int4*)(d_hh + (long long)e * 64 + hc8 * 8);
        }
        *(int4*)(hsm[0] + hr * 72 + hc8 * 8) = hv;
        if (r0 < nch) dpr0 = d_eid[EED + d_eid[s0 + r0]];
        if (r1 < nch) dpr1 = d_eid[EED + d_eid[s0 + r1]];
    }
    for (int ci = 0; ci < nchunks; ci++) {
        int ec = s0 + ci * 16;
        int nch = min(16, s1 - ec);
        __syncthreads();   // hsm[cur] fully staged
        // prefetch next chunk (gmem loads overlap the mma below)
        int4 hvn = make_int4(0, 0, 0, 0);
        int dpr0n = 0, dpr1n = 0;
        bool more = (ci + 1 < nchunks);
        if (more) {
            int ecn = ec + 16;
            int nchn = min(16, s1 - ecn);
            if (hr < nchn)
                hvn = *(const int4*)(d_hh + (long long)d_eid[ecn + hr] * 64 + hc8 * 8);
            if (r0 < nchn) dpr0n = d_eid[EED + d_eid[ecn + r0]];
            if (r1 < nchn) dpr1n = d_eid[EED + d_eid[ecn + r1]];
        }
        float acc[4][4];
#pragma unroll
        for (int nt = 0; nt < 4; nt++) {
            acc[nt][0] = xb0[nt]; acc[nt][1] = xb1[nt];
            acc[nt][2] = xb0[nt]; acc[nt][3] = xb1[nt];
        }
        unsigned hbase = smem_u32(hsm[cur]);
#pragma unroll
        for (int ks = 0; ks < 4; ks++) {
            unsigned a0, a1, a2, a3;
            unsigned addr = hbase + (lane & 15) * 144 + ks * 32 + (lane >> 4) * 16;
            asm volatile("ldmatrix.sync.aligned.m8n8.x4.shared.b16 {%0,%1,%2,%3}, [%4];"
                         : "=r"(a0), "=r"(a1), "=r"(a2), "=r"(a3) : "r"(addr));
#pragma unroll
            for (int nt = 0; nt < 4; nt++) {
                int f = ks * 4 + nt;
                asm volatile(
                    "mma.sync.aligned.m16n8k16.row.col.f32.f16.f16.f32 "
                    "{%0,%1,%2,%3}, {%4,%5,%6,%7}, {%8,%9}, {%0,%1,%2,%3};"
                    : "+f"(acc[nt][0]), "+f"(acc[nt][1]), "+f"(acc[nt][2]), "+f"(acc[nt][3])
                    : "r"(a0), "r"(a1), "r"(a2), "r"(a3), "r"(bf[f].x), "r"(bf[f].y));
            }
        }
#pragma unroll
        for (int nt = 0; nt < 4; nt++) {
            int h2idx = nt * 4 + (lane & 3);
            if (r0 < nch)
                msg2[((long long)dpr0 * 4 + wid) * 16 + h2idx] =
                    __floats2half2_rn(acc[nt][0], acc[nt][1]);
            if (r1 < nch)
                msg2[((long long)dpr1 * 4 + wid) * 16 + h2idx] =
                    __floats2half2_rn(acc[nt][2], acc[nt][3]);
        }
        if (more)
            *(int4*)(hsm[cur ^ 1] + hr * 72 + hc8 * 8) = hvn;
        dpr0 = dpr0n; dpr1 = dpr1n;
        cur ^= 1;
    }
}

// ---------------- dst gather (unroll 8) + root + bias + combine + gelu; re-zero cnt/cur ----------------
__global__ void __launch_bounds__(128) final_kernel(const float* __restrict__ root,
                                                    const float* __restrict__ gbias,
                                                    float* __restrict__ out) {
    int n = blockIdx.x;   // 4096
    int t = threadIdx.x; int b = t >> 5, o = t & 31;
    __shared__ float roots[1024];
    __shared__ float xs[128];
    for (int i = t; i < 1024; i += 128) roots[i] = root[i];
    xs[t] = d_xn[(b * NND + n) * 32 + o];
    __syncthreads();
    float acc = gbias[o];
#pragma unroll
    for (int c = 0; c < 32; c++) acc += xs[b * 32 + c] * roots[c * 32 + o];
    int s0 = d_offA[(NND + 1) + n], s1 = d_offA[(NND + 1) + n + 1];
    const __half* mp = d_msg;
    int i = s0;
    float a[8] = {0.f, 0.f, 0.f, 0.f, 0.f, 0.f, 0.f, 0.f};
    for (; i + 8 <= s1; i += 8) {
#pragma unroll
        for (int u = 0; u < 8; u++)
            a[u] += __half2float(mp[((long long)(i + u) * 4 + b) * 32 + o]);
    }
    for (; i < s1; i++) a[0] += __half2float(mp[((long long)i * 4 + b) * 32 + o]);
    acc += ((a[0] + a[1]) + (a[2] + a[3])) + ((a[4] + a[5]) + (a[6] + a[7]));
    int p = b * NND + n; int row = p >> 6;
    float x2v = (d_x2[(long long)p * 32 + o] - d_stats[1024 + row]) * d_stats[1024 + 256 + row];
    float s = d_x1b[(long long)p * 32 + o] + x2v + acc;
    out[(long long)p * 32 + o] = gelu_f(s);
    // re-zero CSR counters for the next graph replay (zero-init at load covers the first run)
    int gid = n * 128 + t;
    if (gid < 2 * NND) d_cnt[gid] = 0;
    else if (gid < 4 * NND) d_cur[gid - 2 * NND] = 0;
}

// ---------------- launch (fork/join stream-parallel graph) ----------------
extern "C" void kernel_launch(void* const* d_in, const int* in_sizes, int n_in,
                              void* d_out, int out_size) {
    const float* nodes  = (const float*)d_in[0];
    const void*  eidx   = d_in[1];
    const float* eattr  = (const float*)d_in[2];
    const float* w1re   = (const float*)d_in[3];
    const float* w1im   = (const float*)d_in[4];
    const float* w2re   = (const float*)d_in[5];
    const float* w2im   = (const float*)d_in[6];
    const float* mlp_w1 = (const float*)d_in[7];
    const float* mlp_b1 = (const float*)d_in[8];
    const float* mlp_w2 = (const float*)d_in[9];
    const float* mlp_b2 = (const float*)d_in[10];
    const float* wm_w1  = (const float*)d_in[11];
    const float* wm_b1  = (const float*)d_in[12];
    const float* wm_w2  = (const float*)d_in[13];
    const float* wm_b2  = (const float*)d_in[14];
    const float* kw1    = (const float*)d_in[15];
    const float* kb1    = (const float*)d_in[16];
    const float* kw2    = (const float*)d_in[17];
    const float* kb2    = (const float*)d_in[18];
    const float* root   = (const float*)d_in[19];
    const float* gbias  = (const float*)d_in[20];
    float* out = (float*)d_out;

    static cudaStream_t sA = nullptr, sB = nullptr;
    static cudaEvent_t evRoot, evN, evA, evB, evM;
    if (sA == nullptr) {
        cudaStreamCreateWithFlags(&sA, cudaStreamNonBlocking);
        cudaStreamCreateWithFlags(&sB, cudaStreamNonBlocking);
        cudaEventCreateWithFlags(&evRoot, cudaEventDisableTiming);
        cudaEventCreateWithFlags(&evN, cudaEventDisableTiming);
        cudaEventCreateWithFlags(&evA, cudaEventDisableTiming);
        cudaEventCreateWithFlags(&evB, cudaEventDisableTiming);
        cudaEventCreateWithFlags(&evM, cudaEventDisableTiming);
    }

    // fork point
    cudaEventRecord(evRoot, 0);
    cudaStreamWaitEvent(sA, evRoot, 0);
    cudaStreamWaitEvent(sB, evRoot, 0);

    // stream A: CSR build
    convhist_kernel<<<512, 256, 0, sA>>>(eidx);
    scan_kernel<<<2, 1024, 0, sA>>>();
    fill_kernel<<<512, 256, 0, sA>>>();
    cudaEventRecord(evA, sA);

    // stream B: w2 convert first (gates gemm), then edge hidden
    w2conv_kernel<<<256, 256, 0, sB>>>(kw2);
    edgehid_kernel<<<2048, 256, 0, sB>>>(eattr, kw1, kb1);

    // stream 0: fused normalize of input
    statsnorm_kernel<<<256, 256>>>(nodes);
    cudaEventRecord(evN, 0);

    // stream A: pointwise MLP branch
    cudaStreamWaitEvent(sA, evN, 0);
    mlp1_kernel<<<128, 128, 0, sA>>>(wm_w1, wm_b1, wm_w2, wm_b2);   // + stats slot2
    cudaEventRecord(evM, sA);

    // stream B: tensor-core g GEMM, then edge msg
    cudaStreamWaitEvent(sB, evN, 0);
    {
        dim3 g(128, 16);
        gemm_gh_kernel<<<g, 256, 0, sB>>>();
    }
    cudaStreamWaitEvent(sB, evA, 0);
    edgemsg_kernel<<<4096, 128, 0, sB>>>(kb2);
    cudaEventRecord(evB, sB);

    // stream 0: spectral branch (invW fused with inorm+MLP -> d_x1b)
    fwdW_kernel<<<256, 256>>>();
    fwdH_kernel<<<128, 512>>>();
    modemix_kernel<<<512, 128>>>(w1re, w1im, w2re, w2im);
    invH_kernel<<<256, 512>>>();
    invWmlp_kernel<<<256, 256>>>(mlp_w1, mlp_b1, mlp_w2, mlp_b2);

    // join: final combine
    cudaStreamWaitEvent(0, evB, 0);
    cudaStreamWaitEvent(0, evM, 0);
    final_kernel<<<4096, 128>>>(root, gbias, out);
}